// round 6
// baseline (speedup 1.0000x reference)
#include <cuda_runtime.h>
#include <cuda_bf16.h>
#include <math.h>

#define BB 4
#define TT 1024
#define CC 1024
#define HH 16
#define DD 64
#define EE 8
#define HID 128
#define NTOK (BB*TT)          // 4096 global tokens
#define NUNIT (3*HH*EE)       // 384 (proj, head, expert) units
#define SPLITS 8

#define NEG_HUGE (-3.38953139e38f)

typedef unsigned long long ull;
typedef unsigned int uint;

// ---------------- tf32 mma helpers ----------------
__device__ __forceinline__ uint f2tf(float f) {
    uint r; asm("cvt.rna.tf32.f32 %0, %1;" : "=r"(r) : "f"(f)); return r;
}
__device__ __forceinline__ void mma_tf32(float c[4], const uint a[4], uint b0, uint b1) {
    asm("mma.sync.aligned.m16n8k8.row.col.f32.tf32.tf32.f32 "
        "{%0,%1,%2,%3}, {%4,%5,%6,%7}, {%8,%9}, {%0,%1,%2,%3};"
        : "+f"(c[0]), "+f"(c[1]), "+f"(c[2]), "+f"(c[3])
        : "r"(a[0]), "r"(a[1]), "r"(a[2]), "r"(a[3]), "r"(b0), "r"(b1));
}
__device__ __forceinline__ void cpa16(uint dst, const void* src) {
    asm volatile("cp.async.cg.shared.global [%0], [%1], 16;" :: "r"(dst), "l"(src));
}

// ---------------- device scratch (allocation-free rule) ----------------
__device__ float g_q[BB*HH*TT*DD];   // [B,H,T,D], post-RoPE, tf32 bits, pre-scaled
__device__ float g_k[BB*HH*TT*DD];   // tf32 bits
__device__ float g_v[BB*HH*TT*DD];   // tf32 bits
__device__ float g_ao[BB*TT*CC];     // attention output, tf32 bits
__device__ float g_owt[CC*CC];       // o_w pre-converted to tf32 bits
__device__ unsigned int g_cnt[NUNIT];
__device__ unsigned int g_ent_id[NUNIT*NTOK];
__device__ float        g_ent_wt[NUNIT*NTOK];
__device__ float g_part[2ll*3*HH*NTOK*DD];   // [slot][proj][h][tk][d]

__device__ __forceinline__ float gelu_tanh(float t) {
    float t3 = t * t * t;
    return t / (1.0f + __expf(-1.5957691216057308f * (t + 0.044715f * t3)));
}

// ---------------------------------------------------------------------------
// Kernel 0: zero the routing counters
// ---------------------------------------------------------------------------
__global__ void zero_cnt_kernel() {
    if (threadIdx.x < NUNIT) g_cnt[threadIdx.x] = 0u;
}

// ---------------------------------------------------------------------------
// Kernel 1: routing + ow tf32 pre-conversion (folded in for free).
// One block per token, 96 threads (warp = proj).
// ---------------------------------------------------------------------------
__global__ void __launch_bounds__(96) route_kernel(
    const float* __restrict__ x,
    const float* __restrict__ rq, const float* __restrict__ rk,
    const float* __restrict__ rv, const float* __restrict__ ow)
{
    const int tk   = blockIdx.x;
    const int tid  = threadIdx.x;
    const int w    = tid >> 5;
    const int lane = tid & 31;
    const int e    = lane & 7;
    const int hq   = lane >> 3;     // 0..3

    __shared__ float xs[CC];
    __shared__ float rs[3][DD*EE];

    // fold: convert this block's 256-element slice of ow to tf32 bits
    for (int i = tid; i < 256; i += 96) {
        int idx = tk * 256 + i;
        g_owt[idx] = __uint_as_float(f2tf(ow[idx]));
    }

    for (int i = tid; i < CC/4; i += 96)
        ((float4*)xs)[i] = ((const float4*)(x + (size_t)tk * CC))[i];
    for (int i = tid; i < DD*EE; i += 96) {
        rs[0][i] = rq[i]; rs[1][i] = rk[i]; rs[2][i] = rv[i];
    }
    __syncthreads();

    const float* rw = rs[w];
    for (int hb = 0; hb < 4; hb++) {
        int h = hb * 4 + hq;
        float acc = 0.0f;
        #pragma unroll 16
        for (int d = 0; d < DD; d++) acc += xs[h*DD + d] * rw[d*EE + e];

        float m1 = NEG_HUGE, m2 = NEG_HUGE;
        int   i1 = 0, i2 = 0;
        #pragma unroll
        for (int ee = 0; ee < EE; ee++) {
            float v = __shfl_sync(0xffffffffu, acc, hq*8 + ee);
            if (v > m1)      { m2 = m1; i2 = i1; m1 = v; i1 = ee; }
            else if (v > m2) { m2 = v;  i2 = ee; }
        }
        if (e == 0) {
            float dex = expf(m2 - m1);
            float wt1 = 1.0f / (1.0f + dex);
            float wt2 = dex * wt1;
            int base = (w * HH + h) * EE;
            unsigned int p1 = atomicAdd(&g_cnt[base + i1], 1u);
            g_ent_id[(size_t)(base + i1) * NTOK + p1] = (unsigned int)tk;
            g_ent_wt[(size_t)(base + i1) * NTOK + p1] = wt1;
            unsigned int p2 = atomicAdd(&g_cnt[base + i2], 1u);
            g_ent_id[(size_t)(base + i2) * NTOK + p2] = (unsigned int)tk | 0x80000000u;
            g_ent_wt[(size_t)(base + i2) * NTOK + p2] = wt2;
        }
    }
}

// ---------------------------------------------------------------------------
// Kernel 2: expert-grouped MoE GEMM on tf32 mma.sync (unchanged, known-good).
// ---------------------------------------------------------------------------
#define MOE_SMEM ((128*68 + 64*132 + 64*132 + 64*68) * 4)   // 119808 B

__global__ void __launch_bounds__(256) moe_gemm_kernel(
    const float* __restrict__ x,
    const float* __restrict__ qw1, const float* __restrict__ qw2,
    const float* __restrict__ kw1, const float* __restrict__ kw2,
    const float* __restrict__ vw1, const float* __restrict__ vw2)
{
    const int gid  = blockIdx.x;
    const int unit = gid / SPLITS;
    const int s    = gid % SPLITS;
    const int proj = unit >> 7;
    const int h    = (unit >> 3) & 15;
    const int e    = unit & 7;

    const float* w1 = ((proj == 0) ? qw1 : (proj == 1) ? kw1 : vw1) + (size_t)e * DD * HID;
    const float* w2 = ((proj == 0) ? qw2 : (proj == 1) ? kw2 : vw2) + (size_t)e * HID * DD;

    extern __shared__ uint smu[];
    uint* w1t = smu;                    // [128][68]
    uint* w2t = smu + 128*68;           // [64][132]
    uint* hsm = w2t + 64*132;           // [64][132]
    uint* xsm = hsm + 64*132;           // [64][68]
    __shared__ unsigned int stk[64];
    __shared__ float        swt[64];

    const int tid  = threadIdx.x;
    const int w    = tid >> 5;
    const int lane = tid & 31;
    const int g    = lane >> 2;
    const int tg   = lane & 3;
    const int wm   = w & 3;
    const int wn   = w >> 2;

    for (int i = tid; i < DD*HID; i += 256) {
        int d = i >> 7, f = i & 127;
        w1t[f*68 + d] = f2tf(w1[i]);
    }
    for (int i = tid; i < HID*DD; i += 256) {
        int j = i >> 6, d = i & 63;
        w2t[d*132 + j] = f2tf(w2[i]);
    }

    const int nt = (int)g_cnt[unit];
    const size_t ent_base = (size_t)unit * NTOK;

    for (int tile = s; tile * 64 < nt; tile += SPLITS) {
        const int base = tile * 64;
        __syncthreads();
        if (tid < 64) {
            int idx = base + tid;
            if (idx < nt) {
                stk[tid] = g_ent_id[ent_base + idx];
                swt[tid] = g_ent_wt[ent_base + idx];
            } else {
                stk[tid] = 0xFFFFFFFFu;
                swt[tid] = 0.0f;
            }
        }
        __syncthreads();
        {
            int tok = tid >> 2, part = tid & 3;
            unsigned int id = stk[tok];
            if (id != 0xFFFFFFFFu) {
                unsigned int tkk = id & 0x7FFFFFFFu;
                const float* src = x + (size_t)tkk * CC + h * DD + part * 16;
                uint* dst = xsm + tok * 68 + part * 16;
                #pragma unroll
                for (int q = 0; q < 16; q++) dst[q] = f2tf(src[q]);
            }
        }
        __syncthreads();

        // ---- stage 1: H = gelu(X @ W1) ----
        float c1[8][4];
        #pragma unroll
        for (int j = 0; j < 8; j++)
            #pragma unroll
            for (int r = 0; r < 4; r++) c1[j][r] = 0.0f;

        #pragma unroll
        for (int c = 0; c < 8; c++) {
            uint a[4];
            a[0] = xsm[(16*wm + g)    *68 + 8*c + tg];
            a[1] = xsm[(16*wm + g + 8)*68 + 8*c + tg];
            a[2] = xsm[(16*wm + g)    *68 + 8*c + tg + 4];
            a[3] = xsm[(16*wm + g + 8)*68 + 8*c + tg + 4];
            #pragma unroll
            for (int j = 0; j < 8; j++) {
                uint b0 = w1t[(64*wn + 8*j + g)*68 + 8*c + tg];
                uint b1 = w1t[(64*wn + 8*j + g)*68 + 8*c + tg + 4];
                mma_tf32(c1[j], a, b0, b1);
            }
        }
        #pragma unroll
        for (int j = 0; j < 8; j++) {
            int col = 64*wn + 8*j + 2*tg;
            hsm[(16*wm + g)    *132 + col]     = f2tf(gelu_tanh(c1[j][0]));
            hsm[(16*wm + g)    *132 + col + 1] = f2tf(gelu_tanh(c1[j][1]));
            hsm[(16*wm + g + 8)*132 + col]     = f2tf(gelu_tanh(c1[j][2]));
            hsm[(16*wm + g + 8)*132 + col + 1] = f2tf(gelu_tanh(c1[j][3]));
        }
        __syncthreads();

        // ---- stage 2: O = H @ W2 ----
        float c2[4][4];
        #pragma unroll
        for (int j = 0; j < 4; j++)
            #pragma unroll
            for (int r = 0; r < 4; r++) c2[j][r] = 0.0f;

        #pragma unroll
        for (int c = 0; c < 16; c++) {
            uint a[4];
            a[0] = hsm[(16*wm + g)    *132 + 8*c + tg];
            a[1] = hsm[(16*wm + g + 8)*132 + 8*c + tg];
            a[2] = hsm[(16*wm + g)    *132 + 8*c + tg + 4];
            a[3] = hsm[(16*wm + g + 8)*132 + 8*c + tg + 4];
            #pragma unroll
            for (int j = 0; j < 4; j++) {
                uint b0 = w2t[(32*wn + 8*j + g)*132 + 8*c + tg];
                uint b1 = w2t[(32*wn + 8*j + g)*132 + 8*c + tg + 4];
                mma_tf32(c2[j], a, b0, b1);
            }
        }

        int tokA = 16*wm + g, tokB = tokA + 8;
        unsigned int idA = stk[tokA], idB = stk[tokB];
        if (idA != 0xFFFFFFFFu) {
            float wt = swt[tokA];
            unsigned int slot = idA >> 31, tkk = idA & 0x7FFFFFFFu;
            float* dst = g_part + ((((size_t)slot*3 + proj)*HH + h)*NTOK + tkk)*DD;
            #pragma unroll
            for (int j = 0; j < 4; j++)
                *(float2*)&dst[32*wn + 8*j + 2*tg] =
                    make_float2(wt*c2[j][0], wt*c2[j][1]);
        }
        if (idB != 0xFFFFFFFFu) {
            float wt = swt[tokB];
            unsigned int slot = idB >> 31, tkk = idB & 0x7FFFFFFFu;
            float* dst = g_part + ((((size_t)slot*3 + proj)*HH + h)*NTOK + tkk)*DD;
            #pragma unroll
            for (int j = 0; j < 4; j++)
                *(float2*)&dst[32*wn + 8*j + 2*tg] =
                    make_float2(wt*c2[j][2], wt*c2[j][3]);
        }
    }
}

// ---------------------------------------------------------------------------
// Kernel 3: combine slots + RoPE; emits tf32-rounded values (Q pre-scaled).
// ---------------------------------------------------------------------------
__global__ void __launch_bounds__(256) combine_rope_kernel(
    const int* __restrict__ pos_ids,
    const float* __restrict__ cosT, const float* __restrict__ sinT)
{
    const int gw   = blockIdx.x * 8 + (threadIdx.x >> 5);
    const int lane = threadIdx.x & 31;
    const int proj = gw / (HH * NTOK);
    const int rest = gw % (HH * NTOK);
    const int h  = rest / NTOK;
    const int tk = rest % NTOK;

    const size_t SLOT = (size_t)3 * HH * NTOK * DD;
    const size_t pbase = (((size_t)proj * HH + h) * NTOK + tk) * DD;
    float a0 = g_part[pbase + lane]      + g_part[pbase + SLOT + lane];
    float a1 = g_part[pbase + lane + 32] + g_part[pbase + SLOT + lane + 32];

    if (proj < 2) {
        int p = pos_ids[tk];
        float c0 = cosT[p*DD + lane],  c1 = cosT[p*DD + lane + 32];
        float s0 = sinT[p*DD + lane],  s1 = sinT[p*DD + lane + 32];
        float r0 = a0 * c0 - a1 * s0;
        float r1 = a1 * c1 + a0 * s1;
        a0 = r0; a1 = r1;
    }
    if (proj == 0) { a0 *= 0.125f; a1 *= 0.125f; }

    int b = tk >> 10, t = tk & 1023;
    float* outg = (proj == 0) ? g_q : (proj == 1) ? g_k : g_v;
    size_t obase = (((size_t)b * HH + h) * TT + t) * DD;
    outg[obase + lane]      = __uint_as_float(f2tf(a0));
    outg[obase + lane + 32] = __uint_as_float(f2tf(a1));
}

// ---------------------------------------------------------------------------
// Kernel 4: causal flash attention, tf32 mma, BQ=128, BK=64, 256 threads.
// Low-register variant: QK in two 4-tile halves, raw scores staged in pw.
// smem words: K 2x4352, V 2x4608, psm/Qstage 8704 -> 26624 w = 106496 B
// ---------------------------------------------------------------------------
#define ATTN_SMEM (26624 * 4)

__global__ void __launch_bounds__(256, 2) attn_kernel()
{
    extern __shared__ uint smu[];
    uint* psm = smu + 17920;          // [8 warps][16 rows][68]

    const int qtb = 7 - blockIdx.x;   // heavy blocks first
    const int bh  = blockIdx.y;
    const int tid  = threadIdx.x;
    const int w    = tid >> 5;
    const int lane = tid & 31;
    const int g    = lane >> 2;
    const int tg   = lane & 3;
    uint* pw = psm + w * 1088;

    const float* qg = g_q + (size_t)bh * TT * DD;
    const float* kg = g_k + (size_t)bh * TT * DD;
    const float* vg = g_v + (size_t)bh * TT * DD;
    const int q0 = qtb * 128;
    const uint sbase = (uint)__cvta_generic_to_shared(smu);

    // stage Q (raw tf32 bits, pre-scaled) into psm, rows 0..127
    #pragma unroll
    for (int it = 0; it < 8; it++) {
        int idx = tid + it * 256;
        int row = idx >> 4, dc = (idx & 15) * 4;
        *(uint4*)&psm[row*68 + dc] = *(const uint4*)&qg[(size_t)(q0 + row)*DD + dc];
    }
    __syncthreads();
    uint qa[8][4];
    {
        int rA = 16*w + g;
        #pragma unroll
        for (int c = 0; c < 8; c++) {
            qa[c][0] = psm[rA*68     + 8*c + tg];
            qa[c][1] = psm[(rA+8)*68 + 8*c + tg];
            qa[c][2] = psm[rA*68     + 8*c + tg + 4];
            qa[c][3] = psm[(rA+8)*68 + 8*c + tg + 4];
        }
    }

    float oa[8][4];
    #pragma unroll
    for (int j = 0; j < 8; j++)
        #pragma unroll
        for (int r = 0; r < 4; r++) oa[j][r] = 0.0f;
    float mA = -1e30f, mB = -1e30f, lA = 0.0f, lB = 0.0f;

    const int ktmax = 2*qtb + 1;

    #define ISSUE_TILE(kt_) do {                                              \
        int k0_ = (kt_) * 64;                                                 \
        uint kb_ = sbase + (((kt_) & 1) * 4352) * 4;                          \
        uint vb_ = sbase + (8704 + ((kt_) & 1) * 4608) * 4;                   \
        _Pragma("unroll")                                                     \
        for (int it_ = 0; it_ < 4; it_++) {                                   \
            int idx_ = tid + it_ * 256;                                       \
            int row_ = idx_ >> 4, dc_ = (idx_ & 15) * 4;                      \
            cpa16(kb_ + (row_*68 + dc_)*4, &kg[(size_t)(k0_ + row_)*DD + dc_]);\
            cpa16(vb_ + (row_*72 + dc_)*4, &vg[(size_t)(k0_ + row_)*DD + dc_]);\
        }                                                                     \
        asm volatile("cp.async.commit_group;");                               \
    } while (0)

    ISSUE_TILE(0);

    for (int kt = 0; kt <= ktmax; kt++) {
        if (kt < ktmax) {
            ISSUE_TILE(kt + 1);
            asm volatile("cp.async.wait_group 1;");
        } else {
            asm volatile("cp.async.wait_group 0;");
        }
        __syncthreads();
        const uint* ksm = smu + (kt & 1) * 4352;
        const uint* vsm = smu + 8704 + (kt & 1) * 4608;
        const int k0 = kt * 64;

        // ---- QK in two halves; raw scores -> pw; track running tile max ----
        float mtA = -1e30f, mtB = -1e30f;
        #pragma unroll
        for (int jh = 0; jh < 2; jh++) {
            float sc[4][4];
            #pragma unroll
            for (int j = 0; j < 4; j++)
                #pragma unroll
                for (int r = 0; r < 4; r++) sc[j][r] = 0.0f;

            #pragma unroll
            for (int c = 0; c < 8; c++) {
                #pragma unroll
                for (int j = 0; j < 4; j++) {
                    int jj = 4*jh + j;
                    uint b0 = ksm[(8*jj + g)*68 + 8*c + tg];
                    uint b1 = ksm[(8*jj + g)*68 + 8*c + tg + 4];
                    mma_tf32(sc[j], qa[c], b0, b1);
                }
            }

            if (kt >= ktmax - 1) {
                const int rA = q0 + 16*w + g, rB = rA + 8;
                #pragma unroll
                for (int j = 0; j < 4; j++) {
                    int col = k0 + 8*(4*jh + j) + 2*tg;
                    if (col     > rA) sc[j][0] = -1e30f;
                    if (col + 1 > rA) sc[j][1] = -1e30f;
                    if (col     > rB) sc[j][2] = -1e30f;
                    if (col + 1 > rB) sc[j][3] = -1e30f;
                }
            }

            #pragma unroll
            for (int j = 0; j < 4; j++) {
                int jj = 4*jh + j;
                mtA = fmaxf(mtA, fmaxf(sc[j][0], sc[j][1]));
                mtB = fmaxf(mtB, fmaxf(sc[j][2], sc[j][3]));
                *(uint2*)&pw[g*68     + 8*jj + 2*tg] =
                    make_uint2(__float_as_uint(sc[j][0]), __float_as_uint(sc[j][1]));
                *(uint2*)&pw[(g+8)*68 + 8*jj + 2*tg] =
                    make_uint2(__float_as_uint(sc[j][2]), __float_as_uint(sc[j][3]));
            }
        }

        // ---- online softmax ----
        mtA = fmaxf(mtA, __shfl_xor_sync(0xffffffffu, mtA, 1));
        mtA = fmaxf(mtA, __shfl_xor_sync(0xffffffffu, mtA, 2));
        mtB = fmaxf(mtB, __shfl_xor_sync(0xffffffffu, mtB, 1));
        mtB = fmaxf(mtB, __shfl_xor_sync(0xffffffffu, mtB, 2));

        float mnA = fmaxf(mA, mtA), mnB = fmaxf(mB, mtB);
        float aA = __expf(mA - mnA), aB = __expf(mB - mnB);
        mA = mnA; mB = mnB;

        __syncwarp();
        float psA = 0.0f, psB = 0.0f;
        #pragma unroll
        for (int jj = 0; jj < 8; jj++) {
            uint2 uA = *(uint2*)&pw[g*68     + 8*jj + 2*tg];
            uint2 uB = *(uint2*)&pw[(g+8)*68 + 8*jj + 2*tg];
            float p0 = __expf(__uint_as_float(uA.x) - mnA);
            float p1 = __expf(__uint_as_float(uA.y) - mnA);
            float p2 = __expf(__uint_as_float(uB.x) - mnB);
            float p3 = __expf(__uint_as_float(uB.y) - mnB);
            psA += p0 + p1;
            psB += p2 + p3;
            *(uint2*)&pw[g*68     + 8*jj + 2*tg] = make_uint2(f2tf(p0), f2tf(p1));
            *(uint2*)&pw[(g+8)*68 + 8*jj + 2*tg] = make_uint2(f2tf(p2), f2tf(p3));
        }
        psA += __shfl_xor_sync(0xffffffffu, psA, 1);
        psA += __shfl_xor_sync(0xffffffffu, psA, 2);
        psB += __shfl_xor_sync(0xffffffffu, psB, 1);
        psB += __shfl_xor_sync(0xffffffffu, psB, 2);
        lA = lA * aA + psA;
        lB = lB * aB + psB;

        #pragma unroll
        for (int j = 0; j < 8; j++) {
            oa[j][0] *= aA; oa[j][1] *= aA;
            oa[j][2] *= aB; oa[j][3] *= aB;
        }
        __syncwarp();

        // ---- PV ----
        #pragma unroll
        for (int c = 0; c < 8; c++) {
            uint pa[4];
            pa[0] = pw[g*68     + 8*c + tg];
            pa[1] = pw[(g+8)*68 + 8*c + tg];
            pa[2] = pw[g*68     + 8*c + tg + 4];
            pa[3] = pw[(g+8)*68 + 8*c + tg + 4];
            #pragma unroll
            for (int jd = 0; jd < 8; jd++) {
                uint b0 = vsm[(8*c + tg)*72     + 8*jd + g];
                uint b1 = vsm[(8*c + tg + 4)*72 + 8*jd + g];
                mma_tf32(oa[jd], pa, b0, b1);
            }
        }
        __syncthreads();
    }
    #undef ISSUE_TILE

    // epilogue: store tf32-rounded bits (outproj consumes them raw)
    const int b = bh / HH, h = bh % HH;
    float invA = 1.0f / lA, invB = 1.0f / lB;
    const int rA = q0 + 16*w + g, rB = rA + 8;
    #pragma unroll
    for (int jd = 0; jd < 8; jd++) {
        uint2 vA = make_uint2(f2tf(oa[jd][0] * invA), f2tf(oa[jd][1] * invA));
        uint2 vB = make_uint2(f2tf(oa[jd][2] * invB), f2tf(oa[jd][3] * invB));
        *(uint2*)&g_ao[((size_t)(b * TT) + rA) * CC + h * DD + 8*jd + 2*tg] = vA;
        *(uint2*)&g_ao[((size_t)(b * TT) + rB) * CC + h * DD + 8*jd + 2*tg] = vB;
    }
}

// ---------------------------------------------------------------------------
// Kernel 5: y = ao @ ow^T, tf32 mma, BM=128, BN=64, BK=32.
// Inputs pre-converted to tf32 bits -> pure cp.async double-buffered mainloop.
// smem: 2 x (128*36 + 64*36) uint = 55296 B (dynamic)
// ---------------------------------------------------------------------------
#define OUT_SMEM (2 * 6912 * 4)

__global__ void __launch_bounds__(256) outproj_kernel(float* __restrict__ y)
{
    extern __shared__ uint osm[];

    const int tid  = threadIdx.x;
    const int w    = tid >> 5;
    const int lane = tid & 31;
    const int g    = lane >> 2;
    const int tg   = lane & 3;
    const int n0 = blockIdx.x * 64;
    const int m0 = blockIdx.y * 128;
    const uint sbase = (uint)__cvta_generic_to_shared(osm);

    float acc[8][4];
    #pragma unroll
    for (int j = 0; j < 8; j++)
        #pragma unroll
        for (int r = 0; r < 4; r++) acc[j][r] = 0.0f;

    #define OP_ISSUE(k0_, buf_) do {                                          \
        uint ab_ = sbase + (buf_) * 6912 * 4;                                 \
        uint bb_ = ab_ + 4608 * 4;                                            \
        _Pragma("unroll")                                                     \
        for (int it_ = 0; it_ < 4; it_++) {                                   \
            int idx_ = tid + it_ * 256;                                       \
            int row_ = idx_ >> 3, c4_ = (idx_ & 7) * 4;                       \
            cpa16(ab_ + (row_*36 + c4_)*4,                                    \
                  &g_ao[(size_t)(m0 + row_) * 1024 + (k0_) + c4_]);           \
        }                                                                     \
        _Pragma("unroll")                                                     \
        for (int it_ = 0; it_ < 2; it_++) {                                   \
            int idx_ = tid + it_ * 256;                                       \
            int row_ = idx_ >> 3, c4_ = (idx_ & 7) * 4;                       \
            cpa16(bb_ + (row_*36 + c4_)*4,                                    \
                  &g_owt[(size_t)(n0 + row_) * 1024 + (k0_) + c4_]);          \
        }                                                                     \
        asm volatile("cp.async.commit_group;");                               \
    } while (0)

    OP_ISSUE(0, 0);

    for (int kc = 0; kc < 32; kc++) {
        if (kc < 31) {
            OP_ISSUE((kc + 1) * 32, (kc + 1) & 1);
            asm volatile("cp.async.wait_group 1;");
        } else {
            asm volatile("cp.async.wait_group 0;");
        }
        __syncthreads();
        const uint* as = osm + (kc & 1) * 6912;
        const uint* bs = as + 4608;

        #pragma unroll
        for (int c = 0; c < 4; c++) {
            uint a[4];
            a[0] = as[(16*w + g)    *36 + 8*c + tg];
            a[1] = as[(16*w + g + 8)*36 + 8*c + tg];
            a[2] = as[(16*w + g)    *36 + 8*c + tg + 4];
            a[3] = as[(16*w + g + 8)*36 + 8*c + tg + 4];
            #pragma unroll
            for (int j = 0; j < 8; j++) {
                uint b0 = bs[(8*j + g)*36 + 8*c + tg];
                uint b1 = bs[(8*j + g)*36 + 8*c + tg + 4];
                mma_tf32(acc[j], a, b0, b1);
            }
        }
        __syncthreads();
    }
    #undef OP_ISSUE

    const int rA = m0 + 16*w + g, rB = rA + 8;
    #pragma unroll
    for (int j = 0; j < 8; j++) {
        *(float2*)&y[(size_t)rA * 1024 + n0 + 8*j + 2*tg] =
            make_float2(acc[j][0], acc[j][1]);
        *(float2*)&y[(size_t)rB * 1024 + n0 + 8*j + 2*tg] =
            make_float2(acc[j][2], acc[j][3]);
    }
}

// ---------------------------------------------------------------------------
extern "C" void kernel_launch(void* const* d_in, const int* in_sizes, int n_in,
                              void* d_out, int out_size)
{
    const float* x    = (const float*)d_in[0];
    const int*   pid  = (const int*)  d_in[1];
    const float* cosT = (const float*)d_in[2];
    const float* sinT = (const float*)d_in[3];
    const float* rq   = (const float*)d_in[4];
    const float* rk   = (const float*)d_in[5];
    const float* rv   = (const float*)d_in[6];
    const float* qw1  = (const float*)d_in[7];
    const float* qw2  = (const float*)d_in[8];
    const float* kw1  = (const float*)d_in[9];
    const float* kw2  = (const float*)d_in[10];
    const float* vw1  = (const float*)d_in[11];
    const float* vw2  = (const float*)d_in[12];
    const float* ow   = (const float*)d_in[13];
    float* y = (float*)d_out;

    cudaFuncSetAttribute(moe_gemm_kernel,
                         cudaFuncAttributeMaxDynamicSharedMemorySize, MOE_SMEM);
    cudaFuncSetAttribute(attn_kernel,
                         cudaFuncAttributeMaxDynamicSharedMemorySize, ATTN_SMEM);
    cudaFuncSetAttribute(outproj_kernel,
                         cudaFuncAttributeMaxDynamicSharedMemorySize, OUT_SMEM);

    zero_cnt_kernel<<<1, 512>>>();
    route_kernel<<<NTOK, 96>>>(x, rq, rk, rv, ow);
    moe_gemm_kernel<<<NUNIT * SPLITS, 256, MOE_SMEM>>>(x, qw1, qw2, kw1, kw2, vw1, vw2);
    combine_rope_kernel<<<(3 * HH * NTOK) / 8, 256>>>(pid, cosT, sinT);

    dim3 g2(8, BB * HH);
    attn_kernel<<<g2, 256, ATTN_SMEM>>>();

    dim3 g3(CC / 64, (BB * TT) / 128);
    outproj_kernel<<<g3, 256, OUT_SMEM>>>(y);
}

// round 7
// speedup vs baseline: 1.0980x; 1.0980x over previous
#include <cuda_runtime.h>
#include <cuda_bf16.h>
#include <math.h>

#define BB 4
#define TT 1024
#define CC 1024
#define HH 16
#define DD 64
#define EE 8
#define HID 128
#define NTOK (BB*TT)          // 4096 global tokens
#define NUNIT (3*HH*EE)       // 384 (proj, head, expert) units
#define SPLITS 2

#define NEG_HUGE (-3.38953139e38f)

typedef unsigned long long ull;
typedef unsigned int uint;

// ---------------- tf32 mma helpers ----------------
__device__ __forceinline__ uint f2tf(float f) {
    uint r; asm("cvt.rna.tf32.f32 %0, %1;" : "=r"(r) : "f"(f)); return r;
}
__device__ __forceinline__ void mma_tf32(float c[4], const uint a[4], uint b0, uint b1) {
    asm("mma.sync.aligned.m16n8k8.row.col.f32.tf32.tf32.f32 "
        "{%0,%1,%2,%3}, {%4,%5,%6,%7}, {%8,%9}, {%0,%1,%2,%3};"
        : "+f"(c[0]), "+f"(c[1]), "+f"(c[2]), "+f"(c[3])
        : "r"(a[0]), "r"(a[1]), "r"(a[2]), "r"(a[3]), "r"(b0), "r"(b1));
}
__device__ __forceinline__ void cpa16(uint dst, const void* src) {
    asm volatile("cp.async.cg.shared.global [%0], [%1], 16;" :: "r"(dst), "l"(src));
}

// ---------------- device scratch (allocation-free rule) ----------------
__device__ float g_q[BB*HH*TT*DD];   // [B,H,T,D], post-RoPE, tf32 bits, pre-scaled
__device__ float g_k[BB*HH*TT*DD];   // tf32 bits
__device__ float g_v[BB*HH*TT*DD];   // tf32 bits
__device__ float g_ao[BB*TT*CC];     // attention output, tf32 bits
__device__ float g_owt[CC*CC];       // o_w pre-converted to tf32 bits
__device__ unsigned int g_cnt[NUNIT];
__device__ unsigned int g_ent_id[NUNIT*NTOK];
__device__ float        g_ent_wt[NUNIT*NTOK];
__device__ float g_part[2ll*3*HH*NTOK*DD];   // [slot][proj][h][tk][d]

__device__ __forceinline__ float gelu_tanh(float t) {
    float t3 = t * t * t;
    return t / (1.0f + __expf(-1.5957691216057308f * (t + 0.044715f * t3)));
}

// ---------------------------------------------------------------------------
// Kernel 0: zero the routing counters
// ---------------------------------------------------------------------------
__global__ void zero_cnt_kernel() {
    if (threadIdx.x < NUNIT) g_cnt[threadIdx.x] = 0u;
}

// ---------------------------------------------------------------------------
// Kernel 1: routing + ow tf32 pre-conversion (folded in for free).
// ---------------------------------------------------------------------------
__global__ void __launch_bounds__(96) route_kernel(
    const float* __restrict__ x,
    const float* __restrict__ rq, const float* __restrict__ rk,
    const float* __restrict__ rv, const float* __restrict__ ow)
{
    const int tk   = blockIdx.x;
    const int tid  = threadIdx.x;
    const int w    = tid >> 5;
    const int lane = tid & 31;
    const int e    = lane & 7;
    const int hq   = lane >> 3;     // 0..3

    __shared__ float xs[CC];
    __shared__ float rs[3][DD*EE];

    for (int i = tid; i < 256; i += 96) {
        int idx = tk * 256 + i;
        g_owt[idx] = __uint_as_float(f2tf(ow[idx]));
    }

    for (int i = tid; i < CC/4; i += 96)
        ((float4*)xs)[i] = ((const float4*)(x + (size_t)tk * CC))[i];
    for (int i = tid; i < DD*EE; i += 96) {
        rs[0][i] = rq[i]; rs[1][i] = rk[i]; rs[2][i] = rv[i];
    }
    __syncthreads();

    const float* rw = rs[w];
    for (int hb = 0; hb < 4; hb++) {
        int h = hb * 4 + hq;
        float acc = 0.0f;
        #pragma unroll 16
        for (int d = 0; d < DD; d++) acc += xs[h*DD + d] * rw[d*EE + e];

        float m1 = NEG_HUGE, m2 = NEG_HUGE;
        int   i1 = 0, i2 = 0;
        #pragma unroll
        for (int ee = 0; ee < EE; ee++) {
            float v = __shfl_sync(0xffffffffu, acc, hq*8 + ee);
            if (v > m1)      { m2 = m1; i2 = i1; m1 = v; i1 = ee; }
            else if (v > m2) { m2 = v;  i2 = ee; }
        }
        if (e == 0) {
            float dex = expf(m2 - m1);
            float wt1 = 1.0f / (1.0f + dex);
            float wt2 = dex * wt1;
            int base = (w * HH + h) * EE;
            unsigned int p1 = atomicAdd(&g_cnt[base + i1], 1u);
            g_ent_id[(size_t)(base + i1) * NTOK + p1] = (unsigned int)tk;
            g_ent_wt[(size_t)(base + i1) * NTOK + p1] = wt1;
            unsigned int p2 = atomicAdd(&g_cnt[base + i2], 1u);
            g_ent_id[(size_t)(base + i2) * NTOK + p2] = (unsigned int)tk | 0x80000000u;
            g_ent_wt[(size_t)(base + i2) * NTOK + p2] = wt2;
        }
    }
}

// ---------------------------------------------------------------------------
// Kernel 2: expert-grouped MoE GEMM, tf32 mma, software-pipelined gather.
// SPLITS=2 -> ~8 tiles/block, weight prologue amortized.
// 2 __syncthreads per tile; next tile's ids+x prefetched during compute.
// ---------------------------------------------------------------------------
#define MOE_SMEM ((128*68 + 64*132 + 64*132 + 64*68) * 4)   // 119808 B

__global__ void __launch_bounds__(256) moe_gemm_kernel(
    const float* __restrict__ x,
    const float* __restrict__ qw1, const float* __restrict__ qw2,
    const float* __restrict__ kw1, const float* __restrict__ kw2,
    const float* __restrict__ vw1, const float* __restrict__ vw2)
{
    const int gid  = blockIdx.x;
    const int unit = gid / SPLITS;
    const int s    = gid % SPLITS;
    const int proj = unit >> 7;
    const int h    = (unit >> 3) & 15;
    const int e    = unit & 7;

    const float* w1 = ((proj == 0) ? qw1 : (proj == 1) ? kw1 : vw1) + (size_t)e * DD * HID;
    const float* w2 = ((proj == 0) ? qw2 : (proj == 1) ? kw2 : vw2) + (size_t)e * HID * DD;

    extern __shared__ uint smu[];
    uint* w1t = smu;                    // [128][68]
    uint* w2t = smu + 128*68;           // [64][132]
    uint* hsm = w2t + 64*132;           // [64][132]
    uint* xsm = hsm + 64*132;           // [64][68]

    const int tid  = threadIdx.x;
    const int w    = tid >> 5;
    const int lane = tid & 31;
    const int g    = lane >> 2;
    const int tg   = lane & 3;
    const int wm   = w & 3;
    const int wn   = w >> 2;
    const int myTok = tid >> 2;     // 0..63 (4 threads per token for gather)
    const int part  = tid & 3;

    const int nt = (int)g_cnt[unit];
    const size_t ent_base = (size_t)unit * NTOK;

    int base = s * 64;
    if (base >= nt) return;         // uniform across block; no syncs before this

    // one-time transposed weight load (tf32)
    for (int i = tid; i < DD*HID; i += 256) {
        int d = i >> 7, f = i & 127;
        w1t[f*68 + d] = f2tf(w1[i]);
    }
    for (int i = tid; i < HID*DD; i += 256) {
        int j = i >> 6, d = i & 63;
        w2t[d*132 + j] = f2tf(w2[i]);
    }

    // prologue: gather x rows for first tile into registers
    float xg[16];
    {
        uint idg = 0xFFFFFFFFu;
        int idx = base + myTok;
        if (idx < nt) idg = g_ent_id[ent_base + idx];
        #pragma unroll
        for (int q = 0; q < 16; q++) xg[q] = 0.0f;
        if (idg != 0xFFFFFFFFu) {
            const float* src = x + (size_t)(idg & 0x7FFFFFFFu) * CC + h * DD + part * 16;
            #pragma unroll
            for (int q = 0; q < 16; q++) xg[q] = src[q];
        }
    }

    const int tokA = 16*wm + g, tokB = tokA + 8;

    for (int b2 = base; ; b2 += SPLITS * 64) {
        // store current tile's x into xsm (tf32)
        {
            uint* dst = xsm + myTok * 68 + part * 16;
            #pragma unroll
            for (int q = 0; q < 16; q++) dst[q] = f2tf(xg[q]);
        }

        // epilogue ids for this tile (direct LDG; latency hidden by stage 1)
        uint idA = 0xFFFFFFFFu, idB = 0xFFFFFFFFu;
        float wtA = 0.0f, wtB = 0.0f;
        if (b2 + tokA < nt) {
            idA = g_ent_id[ent_base + b2 + tokA];
            wtA = g_ent_wt[ent_base + b2 + tokA];
        }
        if (b2 + tokB < nt) {
            idB = g_ent_id[ent_base + b2 + tokB];
            wtB = g_ent_wt[ent_base + b2 + tokB];
        }

        // prefetch next tile's token id
        const int bn = b2 + SPLITS * 64;
        const bool has_next = bn < nt;
        uint idgn = 0xFFFFFFFFu;
        if (has_next && bn + myTok < nt) idgn = g_ent_id[ent_base + bn + myTok];

        __syncthreads();   // xsm (and, first iter, weights) visible

        // ---- stage 1: H = gelu(X @ W1) ----
        float c1[8][4];
        #pragma unroll
        for (int j = 0; j < 8; j++)
            #pragma unroll
            for (int r = 0; r < 4; r++) c1[j][r] = 0.0f;

        #pragma unroll
        for (int c = 0; c < 8; c++) {
            uint a[4];
            a[0] = xsm[(16*wm + g)    *68 + 8*c + tg];
            a[1] = xsm[(16*wm + g + 8)*68 + 8*c + tg];
            a[2] = xsm[(16*wm + g)    *68 + 8*c + tg + 4];
            a[3] = xsm[(16*wm + g + 8)*68 + 8*c + tg + 4];
            #pragma unroll
            for (int j = 0; j < 8; j++) {
                uint b0 = w1t[(64*wn + 8*j + g)*68 + 8*c + tg];
                uint b1 = w1t[(64*wn + 8*j + g)*68 + 8*c + tg + 4];
                mma_tf32(c1[j], a, b0, b1);
            }
        }
        #pragma unroll
        for (int j = 0; j < 8; j++) {
            int col = 64*wn + 8*j + 2*tg;
            hsm[(16*wm + g)    *132 + col]     = f2tf(gelu_tanh(c1[j][0]));
            hsm[(16*wm + g)    *132 + col + 1] = f2tf(gelu_tanh(c1[j][1]));
            hsm[(16*wm + g + 8)*132 + col]     = f2tf(gelu_tanh(c1[j][2]));
            hsm[(16*wm + g + 8)*132 + col + 1] = f2tf(gelu_tanh(c1[j][3]));
        }

        // gather next tile's x rows (overlaps with stage-2 compute)
        #pragma unroll
        for (int q = 0; q < 16; q++) xg[q] = 0.0f;
        if (idgn != 0xFFFFFFFFu) {
            const float* src = x + (size_t)(idgn & 0x7FFFFFFFu) * CC + h * DD + part * 16;
            #pragma unroll
            for (int q = 0; q < 16; q++) xg[q] = src[q];
        }

        __syncthreads();   // hsm visible (also: all stage-1 xsm reads done)

        // ---- stage 2: O = H @ W2 ----
        float c2[4][4];
        #pragma unroll
        for (int j = 0; j < 4; j++)
            #pragma unroll
            for (int r = 0; r < 4; r++) c2[j][r] = 0.0f;

        #pragma unroll
        for (int c = 0; c < 16; c++) {
            uint a[4];
            a[0] = hsm[(16*wm + g)    *132 + 8*c + tg];
            a[1] = hsm[(16*wm + g + 8)*132 + 8*c + tg];
            a[2] = hsm[(16*wm + g)    *132 + 8*c + tg + 4];
            a[3] = hsm[(16*wm + g + 8)*132 + 8*c + tg + 4];
            #pragma unroll
            for (int j = 0; j < 4; j++) {
                uint b0 = w2t[(32*wn + 8*j + g)*132 + 8*c + tg];
                uint b1 = w2t[(32*wn + 8*j + g)*132 + 8*c + tg + 4];
                mma_tf32(c2[j], a, b0, b1);
            }
        }

        if (idA != 0xFFFFFFFFu) {
            unsigned int slot = idA >> 31, tkk = idA & 0x7FFFFFFFu;
            float* dst = g_part + ((((size_t)slot*3 + proj)*HH + h)*NTOK + tkk)*DD;
            #pragma unroll
            for (int j = 0; j < 4; j++)
                *(float2*)&dst[32*wn + 8*j + 2*tg] =
                    make_float2(wtA*c2[j][0], wtA*c2[j][1]);
        }
        if (idB != 0xFFFFFFFFu) {
            unsigned int slot = idB >> 31, tkk = idB & 0x7FFFFFFFu;
            float* dst = g_part + ((((size_t)slot*3 + proj)*HH + h)*NTOK + tkk)*DD;
            #pragma unroll
            for (int j = 0; j < 4; j++)
                *(float2*)&dst[32*wn + 8*j + 2*tg] =
                    make_float2(wtB*c2[j][2], wtB*c2[j][3]);
        }

        if (!has_next) break;
    }
}

// ---------------------------------------------------------------------------
// Kernel 3: combine slots + RoPE; emits tf32-rounded values (Q pre-scaled).
// ---------------------------------------------------------------------------
__global__ void __launch_bounds__(256) combine_rope_kernel(
    const int* __restrict__ pos_ids,
    const float* __restrict__ cosT, const float* __restrict__ sinT)
{
    const int gw   = blockIdx.x * 8 + (threadIdx.x >> 5);
    const int lane = threadIdx.x & 31;
    const int proj = gw / (HH * NTOK);
    const int rest = gw % (HH * NTOK);
    const int h  = rest / NTOK;
    const int tk = rest % NTOK;

    const size_t SLOT = (size_t)3 * HH * NTOK * DD;
    const size_t pbase = (((size_t)proj * HH + h) * NTOK + tk) * DD;
    float a0 = g_part[pbase + lane]      + g_part[pbase + SLOT + lane];
    float a1 = g_part[pbase + lane + 32] + g_part[pbase + SLOT + lane + 32];

    if (proj < 2) {
        int p = pos_ids[tk];
        float c0 = cosT[p*DD + lane],  c1 = cosT[p*DD + lane + 32];
        float s0 = sinT[p*DD + lane],  s1 = sinT[p*DD + lane + 32];
        float r0 = a0 * c0 - a1 * s0;
        float r1 = a1 * c1 + a0 * s1;
        a0 = r0; a1 = r1;
    }
    if (proj == 0) { a0 *= 0.125f; a1 *= 0.125f; }

    int b = tk >> 10, t = tk & 1023;
    float* outg = (proj == 0) ? g_q : (proj == 1) ? g_k : g_v;
    size_t obase = (((size_t)b * HH + h) * TT + t) * DD;
    outg[obase + lane]      = __uint_as_float(f2tf(a0));
    outg[obase + lane + 32] = __uint_as_float(f2tf(a1));
}

// ---------------------------------------------------------------------------
// Kernel 4: causal flash attention, tf32 mma, BQ=128, BK=64, 256 threads.
// (R5 version: full sc[8][4] in registers, cp.async double-buffered K/V.)
// ---------------------------------------------------------------------------
#define ATTN_SMEM (26624 * 4)

__global__ void __launch_bounds__(256, 2) attn_kernel()
{
    extern __shared__ uint smu[];
    uint* psm = smu + 17920;          // [8 warps][16 rows][68]

    const int qtb = 7 - blockIdx.x;   // heavy blocks first
    const int bh  = blockIdx.y;
    const int tid  = threadIdx.x;
    const int w    = tid >> 5;
    const int lane = tid & 31;
    const int g    = lane >> 2;
    const int tg   = lane & 3;
    uint* pw = psm + w * 1088;

    const float* qg = g_q + (size_t)bh * TT * DD;
    const float* kg = g_k + (size_t)bh * TT * DD;
    const float* vg = g_v + (size_t)bh * TT * DD;
    const int q0 = qtb * 128;
    const uint sbase = (uint)__cvta_generic_to_shared(smu);

    #pragma unroll
    for (int it = 0; it < 8; it++) {
        int idx = tid + it * 256;
        int row = idx >> 4, dc = (idx & 15) * 4;
        *(uint4*)&psm[row*68 + dc] = *(const uint4*)&qg[(size_t)(q0 + row)*DD + dc];
    }
    __syncthreads();
    uint qa[8][4];
    {
        int rA = 16*w + g;
        #pragma unroll
        for (int c = 0; c < 8; c++) {
            qa[c][0] = psm[rA*68     + 8*c + tg];
            qa[c][1] = psm[(rA+8)*68 + 8*c + tg];
            qa[c][2] = psm[rA*68     + 8*c + tg + 4];
            qa[c][3] = psm[(rA+8)*68 + 8*c + tg + 4];
        }
    }

    float oa[8][4];
    #pragma unroll
    for (int j = 0; j < 8; j++)
        #pragma unroll
        for (int r = 0; r < 4; r++) oa[j][r] = 0.0f;
    float mA = -1e30f, mB = -1e30f, lA = 0.0f, lB = 0.0f;

    const int ktmax = 2*qtb + 1;

    #define ISSUE_TILE(kt_) do {                                              \
        int k0_ = (kt_) * 64;                                                 \
        uint kb_ = sbase + (((kt_) & 1) * 4352) * 4;                          \
        uint vb_ = sbase + (8704 + ((kt_) & 1) * 4608) * 4;                   \
        _Pragma("unroll")                                                     \
        for (int it_ = 0; it_ < 4; it_++) {                                   \
            int idx_ = tid + it_ * 256;                                       \
            int row_ = idx_ >> 4, dc_ = (idx_ & 15) * 4;                      \
            cpa16(kb_ + (row_*68 + dc_)*4, &kg[(size_t)(k0_ + row_)*DD + dc_]);\
            cpa16(vb_ + (row_*72 + dc_)*4, &vg[(size_t)(k0_ + row_)*DD + dc_]);\
        }                                                                     \
        asm volatile("cp.async.commit_group;");                               \
    } while (0)

    ISSUE_TILE(0);

    for (int kt = 0; kt <= ktmax; kt++) {
        if (kt < ktmax) {
            ISSUE_TILE(kt + 1);
            asm volatile("cp.async.wait_group 1;");
        } else {
            asm volatile("cp.async.wait_group 0;");
        }
        __syncthreads();
        const uint* ksm = smu + (kt & 1) * 4352;
        const uint* vsm = smu + 8704 + (kt & 1) * 4608;
        const int k0 = kt * 64;

        float sc[8][4];
        #pragma unroll
        for (int j = 0; j < 8; j++)
            #pragma unroll
            for (int r = 0; r < 4; r++) sc[j][r] = 0.0f;

        #pragma unroll
        for (int c = 0; c < 8; c++) {
            #pragma unroll
            for (int j = 0; j < 8; j++) {
                uint b0 = ksm[(8*j + g)*68 + 8*c + tg];
                uint b1 = ksm[(8*j + g)*68 + 8*c + tg + 4];
                mma_tf32(sc[j], qa[c], b0, b1);
            }
        }

        if (kt >= ktmax - 1) {
            const int rA = q0 + 16*w + g, rB = rA + 8;
            #pragma unroll
            for (int j = 0; j < 8; j++) {
                int col = k0 + 8*j + 2*tg;
                if (col     > rA) sc[j][0] = -1e30f;
                if (col + 1 > rA) sc[j][1] = -1e30f;
                if (col     > rB) sc[j][2] = -1e30f;
                if (col + 1 > rB) sc[j][3] = -1e30f;
            }
        }

        float mtA = -1e30f, mtB = -1e30f;
        #pragma unroll
        for (int j = 0; j < 8; j++) {
            mtA = fmaxf(mtA, fmaxf(sc[j][0], sc[j][1]));
            mtB = fmaxf(mtB, fmaxf(sc[j][2], sc[j][3]));
        }
        mtA = fmaxf(mtA, __shfl_xor_sync(0xffffffffu, mtA, 1));
        mtA = fmaxf(mtA, __shfl_xor_sync(0xffffffffu, mtA, 2));
        mtB = fmaxf(mtB, __shfl_xor_sync(0xffffffffu, mtB, 1));
        mtB = fmaxf(mtB, __shfl_xor_sync(0xffffffffu, mtB, 2));

        float mnA = fmaxf(mA, mtA), mnB = fmaxf(mB, mtB);
        float aA = __expf(mA - mnA), aB = __expf(mB - mnB);
        mA = mnA; mB = mnB;

        float psA = 0.0f, psB = 0.0f;
        #pragma unroll
        for (int j = 0; j < 8; j++) {
            sc[j][0] = __expf(sc[j][0] - mnA);
            sc[j][1] = __expf(sc[j][1] - mnA);
            sc[j][2] = __expf(sc[j][2] - mnB);
            sc[j][3] = __expf(sc[j][3] - mnB);
            psA += sc[j][0] + sc[j][1];
            psB += sc[j][2] + sc[j][3];
        }
        psA += __shfl_xor_sync(0xffffffffu, psA, 1);
        psA += __shfl_xor_sync(0xffffffffu, psA, 2);
        psB += __shfl_xor_sync(0xffffffffu, psB, 1);
        psB += __shfl_xor_sync(0xffffffffu, psB, 2);
        lA = lA * aA + psA;
        lB = lB * aB + psB;

        #pragma unroll
        for (int j = 0; j < 8; j++) {
            oa[j][0] *= aA; oa[j][1] *= aA;
            oa[j][2] *= aB; oa[j][3] *= aB;
        }

        #pragma unroll
        for (int j = 0; j < 8; j++) {
            pw[g*68     + 8*j + 2*tg]     = f2tf(sc[j][0]);
            pw[g*68     + 8*j + 2*tg + 1] = f2tf(sc[j][1]);
            pw[(g+8)*68 + 8*j + 2*tg]     = f2tf(sc[j][2]);
            pw[(g+8)*68 + 8*j + 2*tg + 1] = f2tf(sc[j][3]);
        }
        __syncwarp();

        #pragma unroll
        for (int c = 0; c < 8; c++) {
            uint pa[4];
            pa[0] = pw[g*68     + 8*c + tg];
            pa[1] = pw[(g+8)*68 + 8*c + tg];
            pa[2] = pw[g*68     + 8*c + tg + 4];
            pa[3] = pw[(g+8)*68 + 8*c + tg + 4];
            #pragma unroll
            for (int jd = 0; jd < 8; jd++) {
                uint b0 = vsm[(8*c + tg)*72     + 8*jd + g];
                uint b1 = vsm[(8*c + tg + 4)*72 + 8*jd + g];
                mma_tf32(oa[jd], pa, b0, b1);
            }
        }
        __syncthreads();
    }
    #undef ISSUE_TILE

    // epilogue: store tf32-rounded bits (outproj consumes them raw)
    const int b = bh / HH, h = bh % HH;
    float invA = 1.0f / lA, invB = 1.0f / lB;
    const int rA = q0 + 16*w + g, rB = rA + 8;
    #pragma unroll
    for (int jd = 0; jd < 8; jd++) {
        uint2 vA = make_uint2(f2tf(oa[jd][0] * invA), f2tf(oa[jd][1] * invA));
        uint2 vB = make_uint2(f2tf(oa[jd][2] * invB), f2tf(oa[jd][3] * invB));
        *(uint2*)&g_ao[((size_t)(b * TT) + rA) * CC + h * DD + 8*jd + 2*tg] = vA;
        *(uint2*)&g_ao[((size_t)(b * TT) + rB) * CC + h * DD + 8*jd + 2*tg] = vB;
    }
}

// ---------------------------------------------------------------------------
// Kernel 5: y = ao @ ow^T, tf32 mma, BM=128, BN=64, BK=32, cp.async pipelined.
// ---------------------------------------------------------------------------
#define OUT_SMEM (2 * 6912 * 4)

__global__ void __launch_bounds__(256) outproj_kernel(float* __restrict__ y)
{
    extern __shared__ uint osm[];

    const int tid  = threadIdx.x;
    const int w    = tid >> 5;
    const int lane = tid & 31;
    const int g    = lane >> 2;
    const int tg   = lane & 3;
    const int n0 = blockIdx.x * 64;
    const int m0 = blockIdx.y * 128;
    const uint sbase = (uint)__cvta_generic_to_shared(osm);

    float acc[8][4];
    #pragma unroll
    for (int j = 0; j < 8; j++)
        #pragma unroll
        for (int r = 0; r < 4; r++) acc[j][r] = 0.0f;

    #define OP_ISSUE(k0_, buf_) do {                                          \
        uint ab_ = sbase + (buf_) * 6912 * 4;                                 \
        uint bb_ = ab_ + 4608 * 4;                                            \
        _Pragma("unroll")                                                     \
        for (int it_ = 0; it_ < 4; it_++) {                                   \
            int idx_ = tid + it_ * 256;                                       \
            int row_ = idx_ >> 3, c4_ = (idx_ & 7) * 4;                       \
            cpa16(ab_ + (row_*36 + c4_)*4,                                    \
                  &g_ao[(size_t)(m0 + row_) * 1024 + (k0_) + c4_]);           \
        }                                                                     \
        _Pragma("unroll")                                                     \
        for (int it_ = 0; it_ < 2; it_++) {                                   \
            int idx_ = tid + it_ * 256;                                       \
            int row_ = idx_ >> 3, c4_ = (idx_ & 7) * 4;                       \
            cpa16(bb_ + (row_*36 + c4_)*4,                                    \
                  &g_owt[(size_t)(n0 + row_) * 1024 + (k0_) + c4_]);          \
        }                                                                     \
        asm volatile("cp.async.commit_group;");                               \
    } while (0)

    OP_ISSUE(0, 0);

    for (int kc = 0; kc < 32; kc++) {
        if (kc < 31) {
            OP_ISSUE((kc + 1) * 32, (kc + 1) & 1);
            asm volatile("cp.async.wait_group 1;");
        } else {
            asm volatile("cp.async.wait_group 0;");
        }
        __syncthreads();
        const uint* as = osm + (kc & 1) * 6912;
        const uint* bs = as + 4608;

        #pragma unroll
        for (int c = 0; c < 4; c++) {
            uint a[4];
            a[0] = as[(16*w + g)    *36 + 8*c + tg];
            a[1] = as[(16*w + g + 8)*36 + 8*c + tg];
            a[2] = as[(16*w + g)    *36 + 8*c + tg + 4];
            a[3] = as[(16*w + g + 8)*36 + 8*c + tg + 4];
            #pragma unroll
            for (int j = 0; j < 8; j++) {
                uint b0 = bs[(8*j + g)*36 + 8*c + tg];
                uint b1 = bs[(8*j + g)*36 + 8*c + tg + 4];
                mma_tf32(acc[j], a, b0, b1);
            }
        }
        __syncthreads();
    }
    #undef OP_ISSUE

    const int rA = m0 + 16*w + g, rB = rA + 8;
    #pragma unroll
    for (int j = 0; j < 8; j++) {
        *(float2*)&y[(size_t)rA * 1024 + n0 + 8*j + 2*tg] =
            make_float2(acc[j][0], acc[j][1]);
        *(float2*)&y[(size_t)rB * 1024 + n0 + 8*j + 2*tg] =
            make_float2(acc[j][2], acc[j][3]);
    }
}

// ---------------------------------------------------------------------------
extern "C" void kernel_launch(void* const* d_in, const int* in_sizes, int n_in,
                              void* d_out, int out_size)
{
    const float* x    = (const float*)d_in[0];
    const int*   pid  = (const int*)  d_in[1];
    const float* cosT = (const float*)d_in[2];
    const float* sinT = (const float*)d_in[3];
    const float* rq   = (const float*)d_in[4];
    const float* rk   = (const float*)d_in[5];
    const float* rv   = (const float*)d_in[6];
    const float* qw1  = (const float*)d_in[7];
    const float* qw2  = (const float*)d_in[8];
    const float* kw1  = (const float*)d_in[9];
    const float* kw2  = (const float*)d_in[10];
    const float* vw1  = (const float*)d_in[11];
    const float* vw2  = (const float*)d_in[12];
    const float* ow   = (const float*)d_in[13];
    float* y = (float*)d_out;

    cudaFuncSetAttribute(moe_gemm_kernel,
                         cudaFuncAttributeMaxDynamicSharedMemorySize, MOE_SMEM);
    cudaFuncSetAttribute(attn_kernel,
                         cudaFuncAttributeMaxDynamicSharedMemorySize, ATTN_SMEM);
    cudaFuncSetAttribute(outproj_kernel,
                         cudaFuncAttributeMaxDynamicSharedMemorySize, OUT_SMEM);

    zero_cnt_kernel<<<1, 512>>>();
    route_kernel<<<NTOK, 96>>>(x, rq, rk, rv, ow);
    moe_gemm_kernel<<<NUNIT * SPLITS, 256, MOE_SMEM>>>(x, qw1, qw2, kw1, kw2, vw1, vw2);
    combine_rope_kernel<<<(3 * HH * NTOK) / 8, 256>>>(pid, cosT, sinT);

    dim3 g2(8, BB * HH);
    attn_kernel<<<g2, 256, ATTN_SMEM>>>();

    dim3 g3(CC / 64, (BB * TT) / 128);
    outproj_kernel<<<g3, 256, OUT_SMEM>>>(y);
}

// round 8
// speedup vs baseline: 1.1650x; 1.0610x over previous
#include <cuda_runtime.h>
#include <cuda_bf16.h>
#include <math.h>

#define BB 4
#define TT 1024
#define CC 1024
#define HH 16
#define DD 64
#define EE 8
#define HID 128
#define NTOK (BB*TT)          // 4096 global tokens
#define NUNIT (3*HH*EE)       // 384 (proj, head, expert) units
#define SPLITS 2

#define NEG_HUGE (-3.38953139e38f)

typedef unsigned long long ull;
typedef unsigned int uint;

// ---------------- tf32 mma helpers ----------------
__device__ __forceinline__ uint f2tf(float f) {
    uint r; asm("cvt.rna.tf32.f32 %0, %1;" : "=r"(r) : "f"(f)); return r;
}
__device__ __forceinline__ void mma_tf32(float c[4], const uint a[4], uint b0, uint b1) {
    asm("mma.sync.aligned.m16n8k8.row.col.f32.tf32.tf32.f32 "
        "{%0,%1,%2,%3}, {%4,%5,%6,%7}, {%8,%9}, {%0,%1,%2,%3};"
        : "+f"(c[0]), "+f"(c[1]), "+f"(c[2]), "+f"(c[3])
        : "r"(a[0]), "r"(a[1]), "r"(a[2]), "r"(a[3]), "r"(b0), "r"(b1));
}
__device__ __forceinline__ void cpa16(uint dst, const void* src) {
    asm volatile("cp.async.cg.shared.global [%0], [%1], 16;" :: "r"(dst), "l"(src));
}

// ---------------- device scratch (allocation-free rule) ----------------
__device__ float g_q[BB*HH*TT*DD];   // [B,H,T,D], post-RoPE, tf32 bits, pre-scaled
__device__ float g_k[BB*HH*TT*DD];   // tf32 bits
__device__ float g_v[BB*HH*TT*DD];   // tf32 bits
__device__ float g_ao[BB*TT*CC];     // attention output, tf32 bits
__device__ float g_owt[CC*CC];       // o_w pre-converted to tf32 bits
__device__ unsigned int g_cnt[NUNIT];
__device__ unsigned int g_ent_id[NUNIT*NTOK];
__device__ float        g_ent_wt[NUNIT*NTOK];
__device__ float g_part[2ll*3*HH*NTOK*DD];   // [slot][proj][h][tk][d]

__device__ __forceinline__ float gelu_tanh(float t) {
    float t3 = t * t * t;
    return t / (1.0f + __expf(-1.5957691216057308f * (t + 0.044715f * t3)));
}

// ---------------------------------------------------------------------------
// Kernel 0: zero the routing counters
// ---------------------------------------------------------------------------
__global__ void zero_cnt_kernel() {
    if (threadIdx.x < NUNIT) g_cnt[threadIdx.x] = 0u;
}

// ---------------------------------------------------------------------------
// Kernel 1: routing + ow tf32 pre-conversion (folded in for free).
// ---------------------------------------------------------------------------
__global__ void __launch_bounds__(96) route_kernel(
    const float* __restrict__ x,
    const float* __restrict__ rq, const float* __restrict__ rk,
    const float* __restrict__ rv, const float* __restrict__ ow)
{
    const int tk   = blockIdx.x;
    const int tid  = threadIdx.x;
    const int w    = tid >> 5;
    const int lane = tid & 31;
    const int e    = lane & 7;
    const int hq   = lane >> 3;     // 0..3

    __shared__ float xs[CC];
    __shared__ float rs[3][DD*EE];

    for (int i = tid; i < 256; i += 96) {
        int idx = tk * 256 + i;
        g_owt[idx] = __uint_as_float(f2tf(ow[idx]));
    }

    for (int i = tid; i < CC/4; i += 96)
        ((float4*)xs)[i] = ((const float4*)(x + (size_t)tk * CC))[i];
    for (int i = tid; i < DD*EE; i += 96) {
        rs[0][i] = rq[i]; rs[1][i] = rk[i]; rs[2][i] = rv[i];
    }
    __syncthreads();

    const float* rw = rs[w];
    for (int hb = 0; hb < 4; hb++) {
        int h = hb * 4 + hq;
        float acc = 0.0f;
        #pragma unroll 16
        for (int d = 0; d < DD; d++) acc += xs[h*DD + d] * rw[d*EE + e];

        float m1 = NEG_HUGE, m2 = NEG_HUGE;
        int   i1 = 0, i2 = 0;
        #pragma unroll
        for (int ee = 0; ee < EE; ee++) {
            float v = __shfl_sync(0xffffffffu, acc, hq*8 + ee);
            if (v > m1)      { m2 = m1; i2 = i1; m1 = v; i1 = ee; }
            else if (v > m2) { m2 = v;  i2 = ee; }
        }
        if (e == 0) {
            float dex = expf(m2 - m1);
            float wt1 = 1.0f / (1.0f + dex);
            float wt2 = dex * wt1;
            int base = (w * HH + h) * EE;
            unsigned int p1 = atomicAdd(&g_cnt[base + i1], 1u);
            g_ent_id[(size_t)(base + i1) * NTOK + p1] = (unsigned int)tk;
            g_ent_wt[(size_t)(base + i1) * NTOK + p1] = wt1;
            unsigned int p2 = atomicAdd(&g_cnt[base + i2], 1u);
            g_ent_id[(size_t)(base + i2) * NTOK + p2] = (unsigned int)tk | 0x80000000u;
            g_ent_wt[(size_t)(base + i2) * NTOK + p2] = wt2;
        }
    }
}

// ---------------------------------------------------------------------------
// Kernel 2: expert-grouped MoE GEMM, tf32 mma, 512 threads, 128-token tiles.
// 16 warps/SM (vs 8 before) for mma latency hiding; weights stay in smem.
// smem: w1t[128*68] + w2t[64*132] + hsm[128*132] + xsm[128*68] = 171008 B
// ---------------------------------------------------------------------------
#define MOE_SMEM ((128*68 + 64*132 + 128*132 + 128*68) * 4)   // 171008 B

__global__ void __launch_bounds__(512) moe_gemm_kernel(
    const float* __restrict__ x,
    const float* __restrict__ qw1, const float* __restrict__ qw2,
    const float* __restrict__ kw1, const float* __restrict__ kw2,
    const float* __restrict__ vw1, const float* __restrict__ vw2)
{
    const int gid  = blockIdx.x;
    const int unit = gid / SPLITS;
    const int s    = gid % SPLITS;
    const int proj = unit >> 7;
    const int h    = (unit >> 3) & 15;
    const int e    = unit & 7;

    const float* w1 = ((proj == 0) ? qw1 : (proj == 1) ? kw1 : vw1) + (size_t)e * DD * HID;
    const float* w2 = ((proj == 0) ? qw2 : (proj == 1) ? kw2 : vw2) + (size_t)e * HID * DD;

    extern __shared__ uint smu[];
    uint* w1t = smu;                    // [128][68]
    uint* w2t = smu + 128*68;           // [64][132]
    uint* hsm = w2t + 64*132;           // [128][132]
    uint* xsm = hsm + 128*132;          // [128][68]

    const int tid  = threadIdx.x;
    const int w    = tid >> 5;          // 0..15
    const int lane = tid & 31;
    const int g    = lane >> 2;
    const int tg   = lane & 3;
    const int wm   = w & 7;             // token group of 16 (128 tokens)
    const int wn   = w >> 3;            // column half
    const int myTok = tid >> 2;         // 0..127 (4 threads per token)
    const int part  = tid & 3;

    const int nt = (int)g_cnt[unit];
    const size_t ent_base = (size_t)unit * NTOK;

    int base = s * 128;
    if (base >= nt) return;             // uniform across block

    // one-time transposed weight load (tf32)
    for (int i = tid; i < DD*HID; i += 512) {
        int d = i >> 7, f = i & 127;
        w1t[f*68 + d] = f2tf(w1[i]);
    }
    for (int i = tid; i < HID*DD; i += 512) {
        int j = i >> 6, d = i & 63;
        w2t[d*132 + j] = f2tf(w2[i]);
    }

    // prologue: gather x rows for first tile into registers
    float xg[16];
    {
        uint idg = 0xFFFFFFFFu;
        int idx = base + myTok;
        if (idx < nt) idg = g_ent_id[ent_base + idx];
        #pragma unroll
        for (int q = 0; q < 16; q++) xg[q] = 0.0f;
        if (idg != 0xFFFFFFFFu) {
            const float* src = x + (size_t)(idg & 0x7FFFFFFFu) * CC + h * DD + part * 16;
            #pragma unroll
            for (int q = 0; q < 16; q++) xg[q] = src[q];
        }
    }

    const int tokA = 16*wm + g, tokB = tokA + 8;

    for (int b2 = base; ; b2 += SPLITS * 128) {
        // store current tile's x into xsm (tf32)
        {
            uint* dst = xsm + myTok * 68 + part * 16;
            #pragma unroll
            for (int q = 0; q < 16; q++) dst[q] = f2tf(xg[q]);
        }

        // epilogue ids for this tile
        uint idA = 0xFFFFFFFFu, idB = 0xFFFFFFFFu;
        float wtA = 0.0f, wtB = 0.0f;
        if (b2 + tokA < nt) {
            idA = g_ent_id[ent_base + b2 + tokA];
            wtA = g_ent_wt[ent_base + b2 + tokA];
        }
        if (b2 + tokB < nt) {
            idB = g_ent_id[ent_base + b2 + tokB];
            wtB = g_ent_wt[ent_base + b2 + tokB];
        }

        // prefetch next tile's token id
        const int bn = b2 + SPLITS * 128;
        const bool has_next = bn < nt;
        uint idgn = 0xFFFFFFFFu;
        if (has_next && bn + myTok < nt) idgn = g_ent_id[ent_base + bn + myTok];

        __syncthreads();   // xsm (and, first iter, weights) visible

        // ---- stage 1: H = gelu(X @ W1) ----
        float c1[8][4];
        #pragma unroll
        for (int j = 0; j < 8; j++)
            #pragma unroll
            for (int r = 0; r < 4; r++) c1[j][r] = 0.0f;

        #pragma unroll
        for (int c = 0; c < 8; c++) {
            uint a[4];
            a[0] = xsm[(16*wm + g)    *68 + 8*c + tg];
            a[1] = xsm[(16*wm + g + 8)*68 + 8*c + tg];
            a[2] = xsm[(16*wm + g)    *68 + 8*c + tg + 4];
            a[3] = xsm[(16*wm + g + 8)*68 + 8*c + tg + 4];
            #pragma unroll
            for (int j = 0; j < 8; j++) {
                uint b0 = w1t[(64*wn + 8*j + g)*68 + 8*c + tg];
                uint b1 = w1t[(64*wn + 8*j + g)*68 + 8*c + tg + 4];
                mma_tf32(c1[j], a, b0, b1);
            }
        }
        #pragma unroll
        for (int j = 0; j < 8; j++) {
            int col = 64*wn + 8*j + 2*tg;
            hsm[(16*wm + g)    *132 + col]     = f2tf(gelu_tanh(c1[j][0]));
            hsm[(16*wm + g)    *132 + col + 1] = f2tf(gelu_tanh(c1[j][1]));
            hsm[(16*wm + g + 8)*132 + col]     = f2tf(gelu_tanh(c1[j][2]));
            hsm[(16*wm + g + 8)*132 + col + 1] = f2tf(gelu_tanh(c1[j][3]));
        }

        // gather next tile's x rows (overlaps with stage-2 compute)
        #pragma unroll
        for (int q = 0; q < 16; q++) xg[q] = 0.0f;
        if (idgn != 0xFFFFFFFFu) {
            const float* src = x + (size_t)(idgn & 0x7FFFFFFFu) * CC + h * DD + part * 16;
            #pragma unroll
            for (int q = 0; q < 16; q++) xg[q] = src[q];
        }

        __syncthreads();   // hsm visible; stage-1 xsm reads done

        // ---- stage 2: O = H @ W2 ----
        float c2[4][4];
        #pragma unroll
        for (int j = 0; j < 4; j++)
            #pragma unroll
            for (int r = 0; r < 4; r++) c2[j][r] = 0.0f;

        #pragma unroll
        for (int c = 0; c < 16; c++) {
            uint a[4];
            a[0] = hsm[(16*wm + g)    *132 + 8*c + tg];
            a[1] = hsm[(16*wm + g + 8)*132 + 8*c + tg];
            a[2] = hsm[(16*wm + g)    *132 + 8*c + tg + 4];
            a[3] = hsm[(16*wm + g + 8)*132 + 8*c + tg + 4];
            #pragma unroll
            for (int j = 0; j < 4; j++) {
                uint b0 = w2t[(32*wn + 8*j + g)*132 + 8*c + tg];
                uint b1 = w2t[(32*wn + 8*j + g)*132 + 8*c + tg + 4];
                mma_tf32(c2[j], a, b0, b1);
            }
        }

        if (idA != 0xFFFFFFFFu) {
            unsigned int slot = idA >> 31, tkk = idA & 0x7FFFFFFFu;
            float* dst = g_part + ((((size_t)slot*3 + proj)*HH + h)*NTOK + tkk)*DD;
            #pragma unroll
            for (int j = 0; j < 4; j++)
                *(float2*)&dst[32*wn + 8*j + 2*tg] =
                    make_float2(wtA*c2[j][0], wtA*c2[j][1]);
        }
        if (idB != 0xFFFFFFFFu) {
            unsigned int slot = idB >> 31, tkk = idB & 0x7FFFFFFFu;
            float* dst = g_part + ((((size_t)slot*3 + proj)*HH + h)*NTOK + tkk)*DD;
            #pragma unroll
            for (int j = 0; j < 4; j++)
                *(float2*)&dst[32*wn + 8*j + 2*tg] =
                    make_float2(wtB*c2[j][2], wtB*c2[j][3]);
        }

        if (!has_next) break;
    }
}

// ---------------------------------------------------------------------------
// Kernel 3: combine slots + RoPE; emits tf32-rounded values (Q pre-scaled).
// ---------------------------------------------------------------------------
__global__ void __launch_bounds__(256) combine_rope_kernel(
    const int* __restrict__ pos_ids,
    const float* __restrict__ cosT, const float* __restrict__ sinT)
{
    const int gw   = blockIdx.x * 8 + (threadIdx.x >> 5);
    const int lane = threadIdx.x & 31;
    const int proj = gw / (HH * NTOK);
    const int rest = gw % (HH * NTOK);
    const int h  = rest / NTOK;
    const int tk = rest % NTOK;

    const size_t SLOT = (size_t)3 * HH * NTOK * DD;
    const size_t pbase = (((size_t)proj * HH + h) * NTOK + tk) * DD;
    float a0 = g_part[pbase + lane]      + g_part[pbase + SLOT + lane];
    float a1 = g_part[pbase + lane + 32] + g_part[pbase + SLOT + lane + 32];

    if (proj < 2) {
        int p = pos_ids[tk];
        float c0 = cosT[p*DD + lane],  c1 = cosT[p*DD + lane + 32];
        float s0 = sinT[p*DD + lane],  s1 = sinT[p*DD + lane + 32];
        float r0 = a0 * c0 - a1 * s0;
        float r1 = a1 * c1 + a0 * s1;
        a0 = r0; a1 = r1;
    }
    if (proj == 0) { a0 *= 0.125f; a1 *= 0.125f; }

    int b = tk >> 10, t = tk & 1023;
    float* outg = (proj == 0) ? g_q : (proj == 1) ? g_k : g_v;
    size_t obase = (((size_t)b * HH + h) * TT + t) * DD;
    outg[obase + lane]      = __uint_as_float(f2tf(a0));
    outg[obase + lane + 32] = __uint_as_float(f2tf(a1));
}

// ---------------------------------------------------------------------------
// Kernel 4: causal flash attention, tf32 mma, BQ=128, BK=64, 256 threads.
// (R5/R7 version: sc[8][4] in registers, cp.async double-buffered K/V.)
// ---------------------------------------------------------------------------
#define ATTN_SMEM (26624 * 4)

__global__ void __launch_bounds__(256, 2) attn_kernel()
{
    extern __shared__ uint smu[];
    uint* psm = smu + 17920;          // [8 warps][16 rows][68]

    const int qtb = 7 - blockIdx.x;   // heavy blocks first
    const int bh  = blockIdx.y;
    const int tid  = threadIdx.x;
    const int w    = tid >> 5;
    const int lane = tid & 31;
    const int g    = lane >> 2;
    const int tg   = lane & 3;
    uint* pw = psm + w * 1088;

    const float* qg = g_q + (size_t)bh * TT * DD;
    const float* kg = g_k + (size_t)bh * TT * DD;
    const float* vg = g_v + (size_t)bh * TT * DD;
    const int q0 = qtb * 128;
    const uint sbase = (uint)__cvta_generic_to_shared(smu);

    #pragma unroll
    for (int it = 0; it < 8; it++) {
        int idx = tid + it * 256;
        int row = idx >> 4, dc = (idx & 15) * 4;
        *(uint4*)&psm[row*68 + dc] = *(const uint4*)&qg[(size_t)(q0 + row)*DD + dc];
    }
    __syncthreads();
    uint qa[8][4];
    {
        int rA = 16*w + g;
        #pragma unroll
        for (int c = 0; c < 8; c++) {
            qa[c][0] = psm[rA*68     + 8*c + tg];
            qa[c][1] = psm[(rA+8)*68 + 8*c + tg];
            qa[c][2] = psm[rA*68     + 8*c + tg + 4];
            qa[c][3] = psm[(rA+8)*68 + 8*c + tg + 4];
        }
    }

    float oa[8][4];
    #pragma unroll
    for (int j = 0; j < 8; j++)
        #pragma unroll
        for (int r = 0; r < 4; r++) oa[j][r] = 0.0f;
    float mA = -1e30f, mB = -1e30f, lA = 0.0f, lB = 0.0f;

    const int ktmax = 2*qtb + 1;

    #define ISSUE_TILE(kt_) do {                                              \
        int k0_ = (kt_) * 64;                                                 \
        uint kb_ = sbase + (((kt_) & 1) * 4352) * 4;                          \
        uint vb_ = sbase + (8704 + ((kt_) & 1) * 4608) * 4;                   \
        _Pragma("unroll")                                                     \
        for (int it_ = 0; it_ < 4; it_++) {                                   \
            int idx_ = tid + it_ * 256;                                       \
            int row_ = idx_ >> 4, dc_ = (idx_ & 15) * 4;                      \
            cpa16(kb_ + (row_*68 + dc_)*4, &kg[(size_t)(k0_ + row_)*DD + dc_]);\
            cpa16(vb_ + (row_*72 + dc_)*4, &vg[(size_t)(k0_ + row_)*DD + dc_]);\
        }                                                                     \
        asm volatile("cp.async.commit_group;");                               \
    } while (0)

    ISSUE_TILE(0);

    for (int kt = 0; kt <= ktmax; kt++) {
        if (kt < ktmax) {
            ISSUE_TILE(kt + 1);
            asm volatile("cp.async.wait_group 1;");
        } else {
            asm volatile("cp.async.wait_group 0;");
        }
        __syncthreads();
        const uint* ksm = smu + (kt & 1) * 4352;
        const uint* vsm = smu + 8704 + (kt & 1) * 4608;
        const int k0 = kt * 64;

        float sc[8][4];
        #pragma unroll
        for (int j = 0; j < 8; j++)
            #pragma unroll
            for (int r = 0; r < 4; r++) sc[j][r] = 0.0f;

        #pragma unroll
        for (int c = 0; c < 8; c++) {
            #pragma unroll
            for (int j = 0; j < 8; j++) {
                uint b0 = ksm[(8*j + g)*68 + 8*c + tg];
                uint b1 = ksm[(8*j + g)*68 + 8*c + tg + 4];
                mma_tf32(sc[j], qa[c], b0, b1);
            }
        }

        if (kt >= ktmax - 1) {
            const int rA = q0 + 16*w + g, rB = rA + 8;
            #pragma unroll
            for (int j = 0; j < 8; j++) {
                int col = k0 + 8*j + 2*tg;
                if (col     > rA) sc[j][0] = -1e30f;
                if (col + 1 > rA) sc[j][1] = -1e30f;
                if (col     > rB) sc[j][2] = -1e30f;
                if (col + 1 > rB) sc[j][3] = -1e30f;
            }
        }

        float mtA = -1e30f, mtB = -1e30f;
        #pragma unroll
        for (int j = 0; j < 8; j++) {
            mtA = fmaxf(mtA, fmaxf(sc[j][0], sc[j][1]));
            mtB = fmaxf(mtB, fmaxf(sc[j][2], sc[j][3]));
        }
        mtA = fmaxf(mtA, __shfl_xor_sync(0xffffffffu, mtA, 1));
        mtA = fmaxf(mtA, __shfl_xor_sync(0xffffffffu, mtA, 2));
        mtB = fmaxf(mtB, __shfl_xor_sync(0xffffffffu, mtB, 1));
        mtB = fmaxf(mtB, __shfl_xor_sync(0xffffffffu, mtB, 2));

        float mnA = fmaxf(mA, mtA), mnB = fmaxf(mB, mtB);
        float aA = __expf(mA - mnA), aB = __expf(mB - mnB);
        mA = mnA; mB = mnB;

        float psA = 0.0f, psB = 0.0f;
        #pragma unroll
        for (int j = 0; j < 8; j++) {
            sc[j][0] = __expf(sc[j][0] - mnA);
            sc[j][1] = __expf(sc[j][1] - mnA);
            sc[j][2] = __expf(sc[j][2] - mnB);
            sc[j][3] = __expf(sc[j][3] - mnB);
            psA += sc[j][0] + sc[j][1];
            psB += sc[j][2] + sc[j][3];
        }
        psA += __shfl_xor_sync(0xffffffffu, psA, 1);
        psA += __shfl_xor_sync(0xffffffffu, psA, 2);
        psB += __shfl_xor_sync(0xffffffffu, psB, 1);
        psB += __shfl_xor_sync(0xffffffffu, psB, 2);
        lA = lA * aA + psA;
        lB = lB * aB + psB;

        #pragma unroll
        for (int j = 0; j < 8; j++) {
            oa[j][0] *= aA; oa[j][1] *= aA;
            oa[j][2] *= aB; oa[j][3] *= aB;
        }

        #pragma unroll
        for (int j = 0; j < 8; j++) {
            pw[g*68     + 8*j + 2*tg]     = f2tf(sc[j][0]);
            pw[g*68     + 8*j + 2*tg + 1] = f2tf(sc[j][1]);
            pw[(g+8)*68 + 8*j + 2*tg]     = f2tf(sc[j][2]);
            pw[(g+8)*68 + 8*j + 2*tg + 1] = f2tf(sc[j][3]);
        }
        __syncwarp();

        #pragma unroll
        for (int c = 0; c < 8; c++) {
            uint pa[4];
            pa[0] = pw[g*68     + 8*c + tg];
            pa[1] = pw[(g+8)*68 + 8*c + tg];
            pa[2] = pw[g*68     + 8*c + tg + 4];
            pa[3] = pw[(g+8)*68 + 8*c + tg + 4];
            #pragma unroll
            for (int jd = 0; jd < 8; jd++) {
                uint b0 = vsm[(8*c + tg)*72     + 8*jd + g];
                uint b1 = vsm[(8*c + tg + 4)*72 + 8*jd + g];
                mma_tf32(oa[jd], pa, b0, b1);
            }
        }
        __syncthreads();
    }
    #undef ISSUE_TILE

    // epilogue: store tf32-rounded bits (outproj consumes them raw)
    const int b = bh / HH, h = bh % HH;
    float invA = 1.0f / lA, invB = 1.0f / lB;
    const int rA = q0 + 16*w + g, rB = rA + 8;
    #pragma unroll
    for (int jd = 0; jd < 8; jd++) {
        uint2 vA = make_uint2(f2tf(oa[jd][0] * invA), f2tf(oa[jd][1] * invA));
        uint2 vB = make_uint2(f2tf(oa[jd][2] * invB), f2tf(oa[jd][3] * invB));
        *(uint2*)&g_ao[((size_t)(b * TT) + rA) * CC + h * DD + 8*jd + 2*tg] = vA;
        *(uint2*)&g_ao[((size_t)(b * TT) + rB) * CC + h * DD + 8*jd + 2*tg] = vB;
    }
}

// ---------------------------------------------------------------------------
// Kernel 5: y = ao @ ow^T, tf32 mma, BM=128, BN=128, BK=32, cp.async pipelined.
// 256 blocks -> single wave at 2 CTA/SM. smem 2 x 9216 words = 73728 B.
// ---------------------------------------------------------------------------
#define OUT_SMEM (2 * 9216 * 4)

__global__ void __launch_bounds__(256, 2) outproj_kernel(float* __restrict__ y)
{
    extern __shared__ uint osm[];

    const int tid  = threadIdx.x;
    const int w    = tid >> 5;
    const int lane = tid & 31;
    const int g    = lane >> 2;
    const int tg   = lane & 3;
    const int n0 = blockIdx.x * 128;
    const int m0 = blockIdx.y * 128;
    const uint sbase = (uint)__cvta_generic_to_shared(osm);

    float acc[16][4];
    #pragma unroll
    for (int j = 0; j < 16; j++)
        #pragma unroll
        for (int r = 0; r < 4; r++) acc[j][r] = 0.0f;

    #define OP_ISSUE(k0_, buf_) do {                                          \
        uint ab_ = sbase + (buf_) * 9216 * 4;                                 \
        uint bb_ = ab_ + 4608 * 4;                                            \
        _Pragma("unroll")                                                     \
        for (int it_ = 0; it_ < 4; it_++) {                                   \
            int idx_ = tid + it_ * 256;                                       \
            int row_ = idx_ >> 3, c4_ = (idx_ & 7) * 4;                       \
            cpa16(ab_ + (row_*36 + c4_)*4,                                    \
                  &g_ao[(size_t)(m0 + row_) * 1024 + (k0_) + c4_]);           \
            cpa16(bb_ + (row_*36 + c4_)*4,                                    \
                  &g_owt[(size_t)(n0 + row_) * 1024 + (k0_) + c4_]);          \
        }                                                                     \
        asm volatile("cp.async.commit_group;");                               \
    } while (0)

    OP_ISSUE(0, 0);

    for (int kc = 0; kc < 32; kc++) {
        if (kc < 31) {
            OP_ISSUE((kc + 1) * 32, (kc + 1) & 1);
            asm volatile("cp.async.wait_group 1;");
        } else {
            asm volatile("cp.async.wait_group 0;");
        }
        __syncthreads();
        const uint* as = osm + (kc & 1) * 9216;
        const uint* bs = as + 4608;

        #pragma unroll
        for (int c = 0; c < 4; c++) {
            uint a[4];
            a[0] = as[(16*w + g)    *36 + 8*c + tg];
            a[1] = as[(16*w + g + 8)*36 + 8*c + tg];
            a[2] = as[(16*w + g)    *36 + 8*c + tg + 4];
            a[3] = as[(16*w + g + 8)*36 + 8*c + tg + 4];
            #pragma unroll
            for (int j = 0; j < 16; j++) {
                uint b0 = bs[(8*j + g)*36 + 8*c + tg];
                uint b1 = bs[(8*j + g)*36 + 8*c + tg + 4];
                mma_tf32(acc[j], a, b0, b1);
            }
        }
        __syncthreads();
    }
    #undef OP_ISSUE

    const int rA = m0 + 16*w + g, rB = rA + 8;
    #pragma unroll
    for (int j = 0; j < 16; j++) {
        *(float2*)&y[(size_t)rA * 1024 + n0 + 8*j + 2*tg] =
            make_float2(acc[j][0], acc[j][1]);
        *(float2*)&y[(size_t)rB * 1024 + n0 + 8*j + 2*tg] =
            make_float2(acc[j][2], acc[j][3]);
    }
}

// ---------------------------------------------------------------------------
extern "C" void kernel_launch(void* const* d_in, const int* in_sizes, int n_in,
                              void* d_out, int out_size)
{
    const float* x    = (const float*)d_in[0];
    const int*   pid  = (const int*)  d_in[1];
    const float* cosT = (const float*)d_in[2];
    const float* sinT = (const float*)d_in[3];
    const float* rq   = (const float*)d_in[4];
    const float* rk   = (const float*)d_in[5];
    const float* rv   = (const float*)d_in[6];
    const float* qw1  = (const float*)d_in[7];
    const float* qw2  = (const float*)d_in[8];
    const float* kw1  = (const float*)d_in[9];
    const float* kw2  = (const float*)d_in[10];
    const float* vw1  = (const float*)d_in[11];
    const float* vw2  = (const float*)d_in[12];
    const float* ow   = (const float*)d_in[13];
    float* y = (float*)d_out;

    cudaFuncSetAttribute(moe_gemm_kernel,
                         cudaFuncAttributeMaxDynamicSharedMemorySize, MOE_SMEM);
    cudaFuncSetAttribute(attn_kernel,
                         cudaFuncAttributeMaxDynamicSharedMemorySize, ATTN_SMEM);
    cudaFuncSetAttribute(outproj_kernel,
                         cudaFuncAttributeMaxDynamicSharedMemorySize, OUT_SMEM);

    zero_cnt_kernel<<<1, 512>>>();
    route_kernel<<<NTOK, 96>>>(x, rq, rk, rv, ow);
    moe_gemm_kernel<<<NUNIT * SPLITS, 512, MOE_SMEM>>>(x, qw1, qw2, kw1, kw2, vw1, vw2);
    combine_rope_kernel<<<(3 * HH * NTOK) / 8, 256>>>(pid, cosT, sinT);

    dim3 g2(8, BB * HH);
    attn_kernel<<<g2, 256, ATTN_SMEM>>>();

    dim3 g3(CC / 128, (BB * TT) / 128);
    outproj_kernel<<<g3, 256, OUT_SMEM>>>(y);
}

// round 9
// speedup vs baseline: 1.1956x; 1.0263x over previous
#include <cuda_runtime.h>
#include <cuda_bf16.h>
#include <math.h>

#define BB 4
#define TT 1024
#define CC 1024
#define HH 16
#define DD 64
#define EE 8
#define HID 128
#define NTOK (BB*TT)          // 4096 global tokens
#define NUNIT (3*HH*EE)       // 384 (proj, head, expert) units
#define SPLITS 3

#define NEG_HUGE (-3.38953139e38f)

typedef unsigned long long ull;
typedef unsigned int uint;

// ---------------- tf32 mma helpers ----------------
__device__ __forceinline__ uint f2tf(float f) {
    uint r; asm("cvt.rna.tf32.f32 %0, %1;" : "=r"(r) : "f"(f)); return r;
}
__device__ __forceinline__ void mma_tf32(float c[4], const uint a[4], uint b0, uint b1) {
    asm("mma.sync.aligned.m16n8k8.row.col.f32.tf32.tf32.f32 "
        "{%0,%1,%2,%3}, {%4,%5,%6,%7}, {%8,%9}, {%0,%1,%2,%3};"
        : "+f"(c[0]), "+f"(c[1]), "+f"(c[2]), "+f"(c[3])
        : "r"(a[0]), "r"(a[1]), "r"(a[2]), "r"(a[3]), "r"(b0), "r"(b1));
}
__device__ __forceinline__ void cpa16(uint dst, const void* src) {
    asm volatile("cp.async.cg.shared.global [%0], [%1], 16;" :: "r"(dst), "l"(src));
}

// ---------------- device scratch (allocation-free rule) ----------------
__device__ float g_q[BB*HH*TT*DD];   // [B,H,T,D], post-RoPE, tf32 bits, pre-scaled
__device__ float g_k[BB*HH*TT*DD];   // tf32 bits
__device__ float g_v[BB*HH*TT*DD];   // tf32 bits
__device__ float g_ao[BB*TT*CC];     // attention output, tf32 bits
__device__ float g_owt[CC*CC];       // o_w pre-converted to tf32 bits
__device__ unsigned int g_cnt[NUNIT];
__device__ unsigned int g_ent_id[NUNIT*NTOK];
__device__ float        g_ent_wt[NUNIT*NTOK];
__device__ float g_part[2ll*3*HH*NTOK*DD];   // [slot][proj][h][tk][d]

__device__ __forceinline__ float gelu_tanh(float t) {
    float t3 = t * t * t;
    return t / (1.0f + __expf(-1.5957691216057308f * (t + 0.044715f * t3)));
}

// ---------------------------------------------------------------------------
// Kernel 0: zero the routing counters
// ---------------------------------------------------------------------------
__global__ void zero_cnt_kernel() {
    if (threadIdx.x < NUNIT) g_cnt[threadIdx.x] = 0u;
}

// ---------------------------------------------------------------------------
// Kernel 1: routing + ow tf32 pre-conversion (folded in for free).
// ---------------------------------------------------------------------------
__global__ void __launch_bounds__(96) route_kernel(
    const float* __restrict__ x,
    const float* __restrict__ rq, const float* __restrict__ rk,
    const float* __restrict__ rv, const float* __restrict__ ow)
{
    const int tk   = blockIdx.x;
    const int tid  = threadIdx.x;
    const int w    = tid >> 5;
    const int lane = tid & 31;
    const int e    = lane & 7;
    const int hq   = lane >> 3;     // 0..3

    __shared__ float xs[CC];
    __shared__ float rs[3][DD*EE];

    for (int i = tid; i < 256; i += 96) {
        int idx = tk * 256 + i;
        g_owt[idx] = __uint_as_float(f2tf(ow[idx]));
    }

    for (int i = tid; i < CC/4; i += 96)
        ((float4*)xs)[i] = ((const float4*)(x + (size_t)tk * CC))[i];
    for (int i = tid; i < DD*EE; i += 96) {
        rs[0][i] = rq[i]; rs[1][i] = rk[i]; rs[2][i] = rv[i];
    }
    __syncthreads();

    const float* rw = rs[w];
    for (int hb = 0; hb < 4; hb++) {
        int h = hb * 4 + hq;
        float acc = 0.0f;
        #pragma unroll 16
        for (int d = 0; d < DD; d++) acc += xs[h*DD + d] * rw[d*EE + e];

        float m1 = NEG_HUGE, m2 = NEG_HUGE;
        int   i1 = 0, i2 = 0;
        #pragma unroll
        for (int ee = 0; ee < EE; ee++) {
            float v = __shfl_sync(0xffffffffu, acc, hq*8 + ee);
            if (v > m1)      { m2 = m1; i2 = i1; m1 = v; i1 = ee; }
            else if (v > m2) { m2 = v;  i2 = ee; }
        }
        if (e == 0) {
            float dex = expf(m2 - m1);
            float wt1 = 1.0f / (1.0f + dex);
            float wt2 = dex * wt1;
            int base = (w * HH + h) * EE;
            unsigned int p1 = atomicAdd(&g_cnt[base + i1], 1u);
            g_ent_id[(size_t)(base + i1) * NTOK + p1] = (unsigned int)tk;
            g_ent_wt[(size_t)(base + i1) * NTOK + p1] = wt1;
            unsigned int p2 = atomicAdd(&g_cnt[base + i2], 1u);
            g_ent_id[(size_t)(base + i2) * NTOK + p2] = (unsigned int)tk | 0x80000000u;
            g_ent_wt[(size_t)(base + i2) * NTOK + p2] = wt2;
        }
    }
}

// ---------------------------------------------------------------------------
// Kernel 2: expert-grouped MoE GEMM, tf32 mma, 512 threads, 128-token tiles.
// SPLITS=3 -> 1152 blocks = 7.78 waves (2.7% tail) at 1 CTA/SM.
// ---------------------------------------------------------------------------
#define MOE_SMEM ((128*68 + 64*132 + 128*132 + 128*68) * 4)   // 171008 B

__global__ void __launch_bounds__(512) moe_gemm_kernel(
    const float* __restrict__ x,
    const float* __restrict__ qw1, const float* __restrict__ qw2,
    const float* __restrict__ kw1, const float* __restrict__ kw2,
    const float* __restrict__ vw1, const float* __restrict__ vw2)
{
    const int gid  = blockIdx.x;
    const int unit = gid / SPLITS;
    const int s    = gid % SPLITS;
    const int proj = unit >> 7;
    const int h    = (unit >> 3) & 15;
    const int e    = unit & 7;

    const float* w1 = ((proj == 0) ? qw1 : (proj == 1) ? kw1 : vw1) + (size_t)e * DD * HID;
    const float* w2 = ((proj == 0) ? qw2 : (proj == 1) ? kw2 : vw2) + (size_t)e * HID * DD;

    extern __shared__ uint smu[];
    uint* w1t = smu;                    // [128][68]
    uint* w2t = smu + 128*68;           // [64][132]
    uint* hsm = w2t + 64*132;           // [128][132]
    uint* xsm = hsm + 128*132;          // [128][68]

    const int tid  = threadIdx.x;
    const int w    = tid >> 5;          // 0..15
    const int lane = tid & 31;
    const int g    = lane >> 2;
    const int tg   = lane & 3;
    const int wm   = w & 7;             // token group of 16 (128 tokens)
    const int wn   = w >> 3;            // column half
    const int myTok = tid >> 2;         // 0..127 (4 threads per token)
    const int part  = tid & 3;

    const int nt = (int)g_cnt[unit];
    const size_t ent_base = (size_t)unit * NTOK;

    int base = s * 128;
    if (base >= nt) return;             // uniform across block

    // one-time transposed weight load (tf32)
    for (int i = tid; i < DD*HID; i += 512) {
        int d = i >> 7, f = i & 127;
        w1t[f*68 + d] = f2tf(w1[i]);
    }
    for (int i = tid; i < HID*DD; i += 512) {
        int j = i >> 6, d = i & 63;
        w2t[d*132 + j] = f2tf(w2[i]);
    }

    // prologue: gather x rows for first tile into registers
    float xg[16];
    {
        uint idg = 0xFFFFFFFFu;
        int idx = base + myTok;
        if (idx < nt) idg = g_ent_id[ent_base + idx];
        #pragma unroll
        for (int q = 0; q < 16; q++) xg[q] = 0.0f;
        if (idg != 0xFFFFFFFFu) {
            const float* src = x + (size_t)(idg & 0x7FFFFFFFu) * CC + h * DD + part * 16;
            #pragma unroll
            for (int q = 0; q < 16; q++) xg[q] = src[q];
        }
    }

    const int tokA = 16*wm + g, tokB = tokA + 8;

    for (int b2 = base; ; b2 += SPLITS * 128) {
        // store current tile's x into xsm (tf32)
        {
            uint* dst = xsm + myTok * 68 + part * 16;
            #pragma unroll
            for (int q = 0; q < 16; q++) dst[q] = f2tf(xg[q]);
        }

        // epilogue ids for this tile
        uint idA = 0xFFFFFFFFu, idB = 0xFFFFFFFFu;
        float wtA = 0.0f, wtB = 0.0f;
        if (b2 + tokA < nt) {
            idA = g_ent_id[ent_base + b2 + tokA];
            wtA = g_ent_wt[ent_base + b2 + tokA];
        }
        if (b2 + tokB < nt) {
            idB = g_ent_id[ent_base + b2 + tokB];
            wtB = g_ent_wt[ent_base + b2 + tokB];
        }

        // prefetch next tile's token id
        const int bn = b2 + SPLITS * 128;
        const bool has_next = bn < nt;
        uint idgn = 0xFFFFFFFFu;
        if (has_next && bn + myTok < nt) idgn = g_ent_id[ent_base + bn + myTok];

        __syncthreads();   // xsm (and, first iter, weights) visible

        // ---- stage 1: H = gelu(X @ W1) ----
        float c1[8][4];
        #pragma unroll
        for (int j = 0; j < 8; j++)
            #pragma unroll
            for (int r = 0; r < 4; r++) c1[j][r] = 0.0f;

        #pragma unroll
        for (int c = 0; c < 8; c++) {
            uint a[4];
            a[0] = xsm[(16*wm + g)    *68 + 8*c + tg];
            a[1] = xsm[(16*wm + g + 8)*68 + 8*c + tg];
            a[2] = xsm[(16*wm + g)    *68 + 8*c + tg + 4];
            a[3] = xsm[(16*wm + g + 8)*68 + 8*c + tg + 4];
            #pragma unroll
            for (int j = 0; j < 8; j++) {
                uint b0 = w1t[(64*wn + 8*j + g)*68 + 8*c + tg];
                uint b1 = w1t[(64*wn + 8*j + g)*68 + 8*c + tg + 4];
                mma_tf32(c1[j], a, b0, b1);
            }
        }
        #pragma unroll
        for (int j = 0; j < 8; j++) {
            int col = 64*wn + 8*j + 2*tg;
            hsm[(16*wm + g)    *132 + col]     = f2tf(gelu_tanh(c1[j][0]));
            hsm[(16*wm + g)    *132 + col + 1] = f2tf(gelu_tanh(c1[j][1]));
            hsm[(16*wm + g + 8)*132 + col]     = f2tf(gelu_tanh(c1[j][2]));
            hsm[(16*wm + g + 8)*132 + col + 1] = f2tf(gelu_tanh(c1[j][3]));
        }

        // gather next tile's x rows (overlaps with stage-2 compute)
        #pragma unroll
        for (int q = 0; q < 16; q++) xg[q] = 0.0f;
        if (idgn != 0xFFFFFFFFu) {
            const float* src = x + (size_t)(idgn & 0x7FFFFFFFu) * CC + h * DD + part * 16;
            #pragma unroll
            for (int q = 0; q < 16; q++) xg[q] = src[q];
        }

        __syncthreads();   // hsm visible; stage-1 xsm reads done

        // ---- stage 2: O = H @ W2 ----
        float c2[4][4];
        #pragma unroll
        for (int j = 0; j < 4; j++)
            #pragma unroll
            for (int r = 0; r < 4; r++) c2[j][r] = 0.0f;

        #pragma unroll
        for (int c = 0; c < 16; c++) {
            uint a[4];
            a[0] = hsm[(16*wm + g)    *132 + 8*c + tg];
            a[1] = hsm[(16*wm + g + 8)*132 + 8*c + tg];
            a[2] = hsm[(16*wm + g)    *132 + 8*c + tg + 4];
            a[3] = hsm[(16*wm + g + 8)*132 + 8*c + tg + 4];
            #pragma unroll
            for (int j = 0; j < 4; j++) {
                uint b0 = w2t[(32*wn + 8*j + g)*132 + 8*c + tg];
                uint b1 = w2t[(32*wn + 8*j + g)*132 + 8*c + tg + 4];
                mma_tf32(c2[j], a, b0, b1);
            }
        }

        if (idA != 0xFFFFFFFFu) {
            unsigned int slot = idA >> 31, tkk = idA & 0x7FFFFFFFu;
            float* dst = g_part + ((((size_t)slot*3 + proj)*HH + h)*NTOK + tkk)*DD;
            #pragma unroll
            for (int j = 0; j < 4; j++)
                *(float2*)&dst[32*wn + 8*j + 2*tg] =
                    make_float2(wtA*c2[j][0], wtA*c2[j][1]);
        }
        if (idB != 0xFFFFFFFFu) {
            unsigned int slot = idB >> 31, tkk = idB & 0x7FFFFFFFu;
            float* dst = g_part + ((((size_t)slot*3 + proj)*HH + h)*NTOK + tkk)*DD;
            #pragma unroll
            for (int j = 0; j < 4; j++)
                *(float2*)&dst[32*wn + 8*j + 2*tg] =
                    make_float2(wtB*c2[j][2], wtB*c2[j][3]);
        }

        if (!has_next) break;
    }
}

// ---------------------------------------------------------------------------
// Kernel 3: combine slots + RoPE; emits tf32-rounded values (Q pre-scaled).
// ---------------------------------------------------------------------------
__global__ void __launch_bounds__(256) combine_rope_kernel(
    const int* __restrict__ pos_ids,
    const float* __restrict__ cosT, const float* __restrict__ sinT)
{
    const int gw   = blockIdx.x * 8 + (threadIdx.x >> 5);
    const int lane = threadIdx.x & 31;
    const int proj = gw / (HH * NTOK);
    const int rest = gw % (HH * NTOK);
    const int h  = rest / NTOK;
    const int tk = rest % NTOK;

    const size_t SLOT = (size_t)3 * HH * NTOK * DD;
    const size_t pbase = (((size_t)proj * HH + h) * NTOK + tk) * DD;
    float a0 = g_part[pbase + lane]      + g_part[pbase + SLOT + lane];
    float a1 = g_part[pbase + lane + 32] + g_part[pbase + SLOT + lane + 32];

    if (proj < 2) {
        int p = pos_ids[tk];
        float c0 = cosT[p*DD + lane],  c1 = cosT[p*DD + lane + 32];
        float s0 = sinT[p*DD + lane],  s1 = sinT[p*DD + lane + 32];
        float r0 = a0 * c0 - a1 * s0;
        float r1 = a1 * c1 + a0 * s1;
        a0 = r0; a1 = r1;
    }
    if (proj == 0) { a0 *= 0.125f; a1 *= 0.125f; }

    int b = tk >> 10, t = tk & 1023;
    float* outg = (proj == 0) ? g_q : (proj == 1) ? g_k : g_v;
    size_t obase = (((size_t)b * HH + h) * TT + t) * DD;
    outg[obase + lane]      = __uint_as_float(f2tf(a0));
    outg[obase + lane + 32] = __uint_as_float(f2tf(a1));
}

// ---------------------------------------------------------------------------
// Kernel 4: causal flash attention, tf32 mma, BQ=128, BK=64, 256 threads.
// 1-D grid ordered globally heavy-first for LPT scheduling across 2 CTA/SM.
// ---------------------------------------------------------------------------
#define ATTN_SMEM (26624 * 4)

__global__ void __launch_bounds__(256, 2) attn_kernel()
{
    extern __shared__ uint smu[];
    uint* psm = smu + 17920;          // [8 warps][16 rows][68]

    const int wid = blockIdx.x;       // 0..511, heavy-major
    const int qtb = 7 - (wid >> 6);   // first 64 blocks = qtb 7 (heaviest)
    const int bh  = wid & 63;
    const int tid  = threadIdx.x;
    const int w    = tid >> 5;
    const int lane = tid & 31;
    const int g    = lane >> 2;
    const int tg   = lane & 3;
    uint* pw = psm + w * 1088;

    const float* qg = g_q + (size_t)bh * TT * DD;
    const float* kg = g_k + (size_t)bh * TT * DD;
    const float* vg = g_v + (size_t)bh * TT * DD;
    const int q0 = qtb * 128;
    const uint sbase = (uint)__cvta_generic_to_shared(smu);

    #pragma unroll
    for (int it = 0; it < 8; it++) {
        int idx = tid + it * 256;
        int row = idx >> 4, dc = (idx & 15) * 4;
        *(uint4*)&psm[row*68 + dc] = *(const uint4*)&qg[(size_t)(q0 + row)*DD + dc];
    }
    __syncthreads();
    uint qa[8][4];
    {
        int rA = 16*w + g;
        #pragma unroll
        for (int c = 0; c < 8; c++) {
            qa[c][0] = psm[rA*68     + 8*c + tg];
            qa[c][1] = psm[(rA+8)*68 + 8*c + tg];
            qa[c][2] = psm[rA*68     + 8*c + tg + 4];
            qa[c][3] = psm[(rA+8)*68 + 8*c + tg + 4];
        }
    }

    float oa[8][4];
    #pragma unroll
    for (int j = 0; j < 8; j++)
        #pragma unroll
        for (int r = 0; r < 4; r++) oa[j][r] = 0.0f;
    float mA = -1e30f, mB = -1e30f, lA = 0.0f, lB = 0.0f;

    const int ktmax = 2*qtb + 1;

    #define ISSUE_TILE(kt_) do {                                              \
        int k0_ = (kt_) * 64;                                                 \
        uint kb_ = sbase + (((kt_) & 1) * 4352) * 4;                          \
        uint vb_ = sbase + (8704 + ((kt_) & 1) * 4608) * 4;                   \
        _Pragma("unroll")                                                     \
        for (int it_ = 0; it_ < 4; it_++) {                                   \
            int idx_ = tid + it_ * 256;                                       \
            int row_ = idx_ >> 4, dc_ = (idx_ & 15) * 4;                      \
            cpa16(kb_ + (row_*68 + dc_)*4, &kg[(size_t)(k0_ + row_)*DD + dc_]);\
            cpa16(vb_ + (row_*72 + dc_)*4, &vg[(size_t)(k0_ + row_)*DD + dc_]);\
        }                                                                     \
        asm volatile("cp.async.commit_group;");                               \
    } while (0)

    ISSUE_TILE(0);

    for (int kt = 0; kt <= ktmax; kt++) {
        if (kt < ktmax) {
            ISSUE_TILE(kt + 1);
            asm volatile("cp.async.wait_group 1;");
        } else {
            asm volatile("cp.async.wait_group 0;");
        }
        __syncthreads();
        const uint* ksm = smu + (kt & 1) * 4352;
        const uint* vsm = smu + 8704 + (kt & 1) * 4608;
        const int k0 = kt * 64;

        float sc[8][4];
        #pragma unroll
        for (int j = 0; j < 8; j++)
            #pragma unroll
            for (int r = 0; r < 4; r++) sc[j][r] = 0.0f;

        #pragma unroll
        for (int c = 0; c < 8; c++) {
            #pragma unroll
            for (int j = 0; j < 8; j++) {
                uint b0 = ksm[(8*j + g)*68 + 8*c + tg];
                uint b1 = ksm[(8*j + g)*68 + 8*c + tg + 4];
                mma_tf32(sc[j], qa[c], b0, b1);
            }
        }

        if (kt >= ktmax - 1) {
            const int rA = q0 + 16*w + g, rB = rA + 8;
            #pragma unroll
            for (int j = 0; j < 8; j++) {
                int col = k0 + 8*j + 2*tg;
                if (col     > rA) sc[j][0] = -1e30f;
                if (col + 1 > rA) sc[j][1] = -1e30f;
                if (col     > rB) sc[j][2] = -1e30f;
                if (col + 1 > rB) sc[j][3] = -1e30f;
            }
        }

        float mtA = -1e30f, mtB = -1e30f;
        #pragma unroll
        for (int j = 0; j < 8; j++) {
            mtA = fmaxf(mtA, fmaxf(sc[j][0], sc[j][1]));
            mtB = fmaxf(mtB, fmaxf(sc[j][2], sc[j][3]));
        }
        mtA = fmaxf(mtA, __shfl_xor_sync(0xffffffffu, mtA, 1));
        mtA = fmaxf(mtA, __shfl_xor_sync(0xffffffffu, mtA, 2));
        mtB = fmaxf(mtB, __shfl_xor_sync(0xffffffffu, mtB, 1));
        mtB = fmaxf(mtB, __shfl_xor_sync(0xffffffffu, mtB, 2));

        float mnA = fmaxf(mA, mtA), mnB = fmaxf(mB, mtB);
        float aA = __expf(mA - mnA), aB = __expf(mB - mnB);
        mA = mnA; mB = mnB;

        float psA = 0.0f, psB = 0.0f;
        #pragma unroll
        for (int j = 0; j < 8; j++) {
            sc[j][0] = __expf(sc[j][0] - mnA);
            sc[j][1] = __expf(sc[j][1] - mnA);
            sc[j][2] = __expf(sc[j][2] - mnB);
            sc[j][3] = __expf(sc[j][3] - mnB);
            psA += sc[j][0] + sc[j][1];
            psB += sc[j][2] + sc[j][3];
        }
        psA += __shfl_xor_sync(0xffffffffu, psA, 1);
        psA += __shfl_xor_sync(0xffffffffu, psA, 2);
        psB += __shfl_xor_sync(0xffffffffu, psB, 1);
        psB += __shfl_xor_sync(0xffffffffu, psB, 2);
        lA = lA * aA + psA;
        lB = lB * aB + psB;

        #pragma unroll
        for (int j = 0; j < 8; j++) {
            oa[j][0] *= aA; oa[j][1] *= aA;
            oa[j][2] *= aB; oa[j][3] *= aB;
        }

        #pragma unroll
        for (int j = 0; j < 8; j++) {
            pw[g*68     + 8*j + 2*tg]     = f2tf(sc[j][0]);
            pw[g*68     + 8*j + 2*tg + 1] = f2tf(sc[j][1]);
            pw[(g+8)*68 + 8*j + 2*tg]     = f2tf(sc[j][2]);
            pw[(g+8)*68 + 8*j + 2*tg + 1] = f2tf(sc[j][3]);
        }
        __syncwarp();

        #pragma unroll
        for (int c = 0; c < 8; c++) {
            uint pa[4];
            pa[0] = pw[g*68     + 8*c + tg];
            pa[1] = pw[(g+8)*68 + 8*c + tg];
            pa[2] = pw[g*68     + 8*c + tg + 4];
            pa[3] = pw[(g+8)*68 + 8*c + tg + 4];
            #pragma unroll
            for (int jd = 0; jd < 8; jd++) {
                uint b0 = vsm[(8*c + tg)*72     + 8*jd + g];
                uint b1 = vsm[(8*c + tg + 4)*72 + 8*jd + g];
                mma_tf32(oa[jd], pa, b0, b1);
            }
        }
        __syncthreads();
    }
    #undef ISSUE_TILE

    // epilogue: store tf32-rounded bits (outproj consumes them raw)
    const int b = bh / HH, h = bh % HH;
    float invA = 1.0f / lA, invB = 1.0f / lB;
    const int rA = q0 + 16*w + g, rB = rA + 8;
    #pragma unroll
    for (int jd = 0; jd < 8; jd++) {
        uint2 vA = make_uint2(f2tf(oa[jd][0] * invA), f2tf(oa[jd][1] * invA));
        uint2 vB = make_uint2(f2tf(oa[jd][2] * invB), f2tf(oa[jd][3] * invB));
        *(uint2*)&g_ao[((size_t)(b * TT) + rA) * CC + h * DD + 8*jd + 2*tg] = vA;
        *(uint2*)&g_ao[((size_t)(b * TT) + rB) * CC + h * DD + 8*jd + 2*tg] = vB;
    }
}

// ---------------------------------------------------------------------------
// Kernel 5: y = ao @ ow^T, tf32 mma, BM=128, BN=128, BK=32, cp.async pipelined.
// 256 blocks -> single wave at 2 CTA/SM.
// ---------------------------------------------------------------------------
#define OUT_SMEM (2 * 9216 * 4)

__global__ void __launch_bounds__(256, 2) outproj_kernel(float* __restrict__ y)
{
    extern __shared__ uint osm[];

    const int tid  = threadIdx.x;
    const int w    = tid >> 5;
    const int lane = tid & 31;
    const int g    = lane >> 2;
    const int tg   = lane & 3;
    const int n0 = blockIdx.x * 128;
    const int m0 = blockIdx.y * 128;
    const uint sbase = (uint)__cvta_generic_to_shared(osm);

    float acc[16][4];
    #pragma unroll
    for (int j = 0; j < 16; j++)
        #pragma unroll
        for (int r = 0; r < 4; r++) acc[j][r] = 0.0f;

    #define OP_ISSUE(k0_, buf_) do {                                          \
        uint ab_ = sbase + (buf_) * 9216 * 4;                                 \
        uint bb_ = ab_ + 4608 * 4;                                            \
        _Pragma("unroll")                                                     \
        for (int it_ = 0; it_ < 4; it_++) {                                   \
            int idx_ = tid + it_ * 256;                                       \
            int row_ = idx_ >> 3, c4_ = (idx_ & 7) * 4;                       \
            cpa16(ab_ + (row_*36 + c4_)*4,                                    \
                  &g_ao[(size_t)(m0 + row_) * 1024 + (k0_) + c4_]);           \
            cpa16(bb_ + (row_*36 + c4_)*4,                                    \
                  &g_owt[(size_t)(n0 + row_) * 1024 + (k0_) + c4_]);          \
        }                                                                     \
        asm volatile("cp.async.commit_group;");                               \
    } while (0)

    OP_ISSUE(0, 0);

    for (int kc = 0; kc < 32; kc++) {
        if (kc < 31) {
            OP_ISSUE((kc + 1) * 32, (kc + 1) & 1);
            asm volatile("cp.async.wait_group 1;");
        } else {
            asm volatile("cp.async.wait_group 0;");
        }
        __syncthreads();
        const uint* as = osm + (kc & 1) * 9216;
        const uint* bs = as + 4608;

        #pragma unroll
        for (int c = 0; c < 4; c++) {
            uint a[4];
            a[0] = as[(16*w + g)    *36 + 8*c + tg];
            a[1] = as[(16*w + g + 8)*36 + 8*c + tg];
            a[2] = as[(16*w + g)    *36 + 8*c + tg + 4];
            a[3] = as[(16*w + g + 8)*36 + 8*c + tg + 4];
            #pragma unroll
            for (int j = 0; j < 16; j++) {
                uint b0 = bs[(8*j + g)*36 + 8*c + tg];
                uint b1 = bs[(8*j + g)*36 + 8*c + tg + 4];
                mma_tf32(acc[j], a, b0, b1);
            }
        }
        __syncthreads();
    }
    #undef OP_ISSUE

    const int rA = m0 + 16*w + g, rB = rA + 8;
    #pragma unroll
    for (int j = 0; j < 16; j++) {
        *(float2*)&y[(size_t)rA * 1024 + n0 + 8*j + 2*tg] =
            make_float2(acc[j][0], acc[j][1]);
        *(float2*)&y[(size_t)rB * 1024 + n0 + 8*j + 2*tg] =
            make_float2(acc[j][2], acc[j][3]);
    }
}

// ---------------------------------------------------------------------------
extern "C" void kernel_launch(void* const* d_in, const int* in_sizes, int n_in,
                              void* d_out, int out_size)
{
    const float* x    = (const float*)d_in[0];
    const int*   pid  = (const int*)  d_in[1];
    const float* cosT = (const float*)d_in[2];
    const float* sinT = (const float*)d_in[3];
    const float* rq   = (const float*)d_in[4];
    const float* rk   = (const float*)d_in[5];
    const float* rv   = (const float*)d_in[6];
    const float* qw1  = (const float*)d_in[7];
    const float* qw2  = (const float*)d_in[8];
    const float* kw1  = (const float*)d_in[9];
    const float* kw2  = (const float*)d_in[10];
    const float* vw1  = (const float*)d_in[11];
    const float* vw2  = (const float*)d_in[12];
    const float* ow   = (const float*)d_in[13];
    float* y = (float*)d_out;

    cudaFuncSetAttribute(moe_gemm_kernel,
                         cudaFuncAttributeMaxDynamicSharedMemorySize, MOE_SMEM);
    cudaFuncSetAttribute(attn_kernel,
                         cudaFuncAttributeMaxDynamicSharedMemorySize, ATTN_SMEM);
    cudaFuncSetAttribute(outproj_kernel,
                         cudaFuncAttributeMaxDynamicSharedMemorySize, OUT_SMEM);

    zero_cnt_kernel<<<1, 512>>>();
    route_kernel<<<NTOK, 96>>>(x, rq, rk, rv, ow);
    moe_gemm_kernel<<<NUNIT * SPLITS, 512, MOE_SMEM>>>(x, qw1, qw2, kw1, kw2, vw1, vw2);
    combine_rope_kernel<<<(3 * HH * NTOK) / 8, 256>>>(pid, cosT, sinT);

    attn_kernel<<<512, 256, ATTN_SMEM>>>();

    dim3 g3(CC / 128, (BB * TT) / 128);
    outproj_kernel<<<g3, 256, OUT_SMEM>>>(y);
}

// round 10
// speedup vs baseline: 1.7350x; 1.4511x over previous
#include <cuda_runtime.h>
#include <cuda_fp16.h>
#include <math.h>

#define BB 4
#define TT 1024
#define CC 1024
#define HH 16
#define DD 64
#define EE 8
#define HID 128
#define NTOK (BB*TT)
#define NUNIT (3*HH*EE)
#define SPLITS 3

#define NEG_HUGE (-3.38953139e38f)

typedef unsigned int uint;

// ---------------- fp16 mma helpers (m16n8k16, fp32 accumulate) ----------------
__device__ __forceinline__ uint f2h2(float lo, float hi) {
    __half2 h = __floats2half2_rn(lo, hi);
    return *(uint*)&h;
}
__device__ __forceinline__ void mma_f16(float c[4], const uint a[4], uint b0, uint b1) {
    asm("mma.sync.aligned.m16n8k16.row.col.f32.f16.f16.f32 "
        "{%0,%1,%2,%3}, {%4,%5,%6,%7}, {%8,%9}, {%0,%1,%2,%3};"
        : "+f"(c[0]), "+f"(c[1]), "+f"(c[2]), "+f"(c[3])
        : "r"(a[0]), "r"(a[1]), "r"(a[2]), "r"(a[3]), "r"(b0), "r"(b1));
}
__device__ __forceinline__ void cpa16(uint dst, const void* src) {
    asm volatile("cp.async.cg.shared.global [%0], [%1], 16;" :: "r"(dst), "l"(src));
}

// ---------------- device scratch ----------------
__device__ uint g_qh[BB*HH*TT*32];     // [bh][t][d/2] half2 along d, pre-scaled
__device__ uint g_kh[BB*HH*TT*32];     // [bh][t][d/2] half2 along d
__device__ uint g_vh[BB*HH*512*64];    // [bh][t/2][d]  half2 along t (pair layout)
__device__ uint g_aoh[(size_t)BB*TT*512];      // [tok][c/2] half2 along c
__device__ uint g_owth[(size_t)CC*512];        // [n][k/2] half2 along k
__device__ unsigned int g_cnt[NUNIT];
__device__ unsigned int g_ent_id[NUNIT*NTOK];
__device__ float        g_ent_wt[NUNIT*NTOK];
__device__ float g_part[2ll*3*HH*NTOK*DD];     // [slot][proj][h][tk][d] fp32

__device__ __forceinline__ float gelu_tanh(float t) {
    float t3 = t * t * t;
    return t / (1.0f + __expf(-1.5957691216057308f * (t + 0.044715f * t3)));
}

// ---------------------------------------------------------------------------
// Kernel 0: zero routing counters
// ---------------------------------------------------------------------------
__global__ void zero_cnt_kernel() {
    if (threadIdx.x < NUNIT) g_cnt[threadIdx.x] = 0u;
}

// ---------------------------------------------------------------------------
// Kernel 1: routing + ow fp16 pre-conversion.
// ---------------------------------------------------------------------------
__global__ void __launch_bounds__(96) route_kernel(
    const float* __restrict__ x,
    const float* __restrict__ rq, const float* __restrict__ rk,
    const float* __restrict__ rv, const float* __restrict__ ow)
{
    const int tk   = blockIdx.x;
    const int tid  = threadIdx.x;
    const int w    = tid >> 5;
    const int lane = tid & 31;
    const int e    = lane & 7;
    const int hq   = lane >> 3;

    __shared__ float xs[CC];
    __shared__ float rs[3][DD*EE];

    // convert this block's 256-element slice of ow to half
    for (int i = tid; i < 128; i += 96) {
        int idx = tk * 128 + i;   // in half2 units: 128 per block covers 256 halves
        float2 v = ((const float2*)ow)[idx];
        g_owth[idx] = f2h2(v.x, v.y);
    }

    for (int i = tid; i < CC/4; i += 96)
        ((float4*)xs)[i] = ((const float4*)(x + (size_t)tk * CC))[i];
    for (int i = tid; i < DD*EE; i += 96) {
        rs[0][i] = rq[i]; rs[1][i] = rk[i]; rs[2][i] = rv[i];
    }
    __syncthreads();

    const float* rw = rs[w];
    for (int hb = 0; hb < 4; hb++) {
        int h = hb * 4 + hq;
        float acc = 0.0f;
        #pragma unroll 16
        for (int d = 0; d < DD; d++) acc += xs[h*DD + d] * rw[d*EE + e];

        float m1 = NEG_HUGE, m2 = NEG_HUGE;
        int   i1 = 0, i2 = 0;
        #pragma unroll
        for (int ee = 0; ee < EE; ee++) {
            float v = __shfl_sync(0xffffffffu, acc, hq*8 + ee);
            if (v > m1)      { m2 = m1; i2 = i1; m1 = v; i1 = ee; }
            else if (v > m2) { m2 = v;  i2 = ee; }
        }
        if (e == 0) {
            float dex = expf(m2 - m1);
            float wt1 = 1.0f / (1.0f + dex);
            float wt2 = dex * wt1;
            int base = (w * HH + h) * EE;
            unsigned int p1 = atomicAdd(&g_cnt[base + i1], 1u);
            g_ent_id[(size_t)(base + i1) * NTOK + p1] = (unsigned int)tk;
            g_ent_wt[(size_t)(base + i1) * NTOK + p1] = wt1;
            unsigned int p2 = atomicAdd(&g_cnt[base + i2], 1u);
            g_ent_id[(size_t)(base + i2) * NTOK + p2] = (unsigned int)tk | 0x80000000u;
            g_ent_wt[(size_t)(base + i2) * NTOK + p2] = wt2;
        }
    }
}

// ---------------------------------------------------------------------------
// Kernel 2: expert-grouped MoE GEMM, fp16 mma, 512 threads, 128-token tiles.
// smem(uints): w1t[128][36] + w2t[64][68] + hsm[128][68] + xsm[128][36] = 22272
// ---------------------------------------------------------------------------
#define MOE_SMEM (22272 * 4)

__global__ void __launch_bounds__(512) moe_gemm_kernel(
    const float* __restrict__ x,
    const float* __restrict__ qw1, const float* __restrict__ qw2,
    const float* __restrict__ kw1, const float* __restrict__ kw2,
    const float* __restrict__ vw1, const float* __restrict__ vw2)
{
    const int gid  = blockIdx.x;
    const int unit = gid / SPLITS;
    const int s    = gid % SPLITS;
    const int proj = unit >> 7;
    const int h    = (unit >> 3) & 15;
    const int e    = unit & 7;

    const float* w1 = ((proj == 0) ? qw1 : (proj == 1) ? kw1 : vw1) + (size_t)e * DD * HID;
    const float* w2 = ((proj == 0) ? qw2 : (proj == 1) ? kw2 : vw2) + (size_t)e * HID * DD;

    extern __shared__ uint smu[];
    uint* w1t = smu;                    // [128 f][36]  half2 along d
    uint* w2t = smu + 128*36;           // [64 d][68]   half2 along j
    uint* hsm = w2t + 64*68;            // [128 tok][68] half2 along j
    uint* xsm = hsm + 128*68;           // [128 tok][36] half2 along d

    const int tid  = threadIdx.x;
    const int w    = tid >> 5;
    const int lane = tid & 31;
    const int g    = lane >> 2;
    const int tg   = lane & 3;
    const int wm   = w & 7;
    const int wn   = w >> 3;
    const int myTok = tid >> 2;
    const int part  = tid & 3;

    const int nt = (int)g_cnt[unit];
    const size_t ent_base = (size_t)unit * NTOK;

    int base = s * 128;
    if (base >= nt) return;

    // one-time transposed weight load (half)
    for (int i = tid; i < DD*HID; i += 512) {
        int d = i >> 7, f = i & 127;
        ((half*)w1t)[f*72 + d] = __float2half(w1[i]);      // w1t row = 36 uints = 72 halves
    }
    for (int i = tid; i < HID*DD; i += 512) {
        int j = i >> 6, d = i & 63;
        ((half*)w2t)[d*136 + j] = __float2half(w2[i]);     // w2t row = 68 uints = 136 halves
    }

    // prologue gather: first tile x rows (8 half2 per thread-quarter)
    uint xg[8];
    {
        uint idg = 0xFFFFFFFFu;
        int idx = base + myTok;
        if (idx < nt) idg = g_ent_id[ent_base + idx];
        #pragma unroll
        for (int q = 0; q < 8; q++) xg[q] = 0u;
        if (idg != 0xFFFFFFFFu) {
            const float2* src = (const float2*)(x + (size_t)(idg & 0x7FFFFFFFu) * CC + h * DD + part * 16);
            #pragma unroll
            for (int q = 0; q < 8; q++) { float2 v = src[q]; xg[q] = f2h2(v.x, v.y); }
        }
    }

    const int tokA = 16*wm + g, tokB = tokA + 8;

    for (int b2 = base; ; b2 += SPLITS * 128) {
        {   // store current tile's x into xsm
            uint* dst = xsm + myTok * 36 + part * 8;
            #pragma unroll
            for (int q = 0; q < 8; q++) dst[q] = xg[q];
        }

        uint idA = 0xFFFFFFFFu, idB = 0xFFFFFFFFu;
        float wtA = 0.0f, wtB = 0.0f;
        if (b2 + tokA < nt) {
            idA = g_ent_id[ent_base + b2 + tokA];
            wtA = g_ent_wt[ent_base + b2 + tokA];
        }
        if (b2 + tokB < nt) {
            idB = g_ent_id[ent_base + b2 + tokB];
            wtB = g_ent_wt[ent_base + b2 + tokB];
        }

        const int bn = b2 + SPLITS * 128;
        const bool has_next = bn < nt;
        uint idgn = 0xFFFFFFFFu;
        if (has_next && bn + myTok < nt) idgn = g_ent_id[ent_base + bn + myTok];

        __syncthreads();

        // ---- stage 1: H = gelu(X @ W1), K=64 (4 k-chunks), 8 n-tiles ----
        float c1[8][4];
        #pragma unroll
        for (int j = 0; j < 8; j++)
            #pragma unroll
            for (int r = 0; r < 4; r++) c1[j][r] = 0.0f;

        #pragma unroll
        for (int c = 0; c < 4; c++) {
            uint a[4];
            a[0] = xsm[(16*wm + g)    *36 + 8*c + tg];
            a[1] = xsm[(16*wm + g + 8)*36 + 8*c + tg];
            a[2] = xsm[(16*wm + g)    *36 + 8*c + tg + 4];
            a[3] = xsm[(16*wm + g + 8)*36 + 8*c + tg + 4];
            #pragma unroll
            for (int j = 0; j < 8; j++) {
                uint b0 = w1t[(64*wn + 8*j + g)*36 + 8*c + tg];
                uint b1 = w1t[(64*wn + 8*j + g)*36 + 8*c + tg + 4];
                mma_f16(c1[j], a, b0, b1);
            }
        }
        #pragma unroll
        for (int j = 0; j < 8; j++) {
            int col2 = 32*wn + 4*j + tg;          // half2 index along j
            hsm[(16*wm + g)    *68 + col2] = f2h2(gelu_tanh(c1[j][0]), gelu_tanh(c1[j][1]));
            hsm[(16*wm + g + 8)*68 + col2] = f2h2(gelu_tanh(c1[j][2]), gelu_tanh(c1[j][3]));
        }

        // gather next tile's x rows
        #pragma unroll
        for (int q = 0; q < 8; q++) xg[q] = 0u;
        if (idgn != 0xFFFFFFFFu) {
            const float2* src = (const float2*)(x + (size_t)(idgn & 0x7FFFFFFFu) * CC + h * DD + part * 16);
            #pragma unroll
            for (int q = 0; q < 8; q++) { float2 v = src[q]; xg[q] = f2h2(v.x, v.y); }
        }

        __syncthreads();

        // ---- stage 2: O = H @ W2, K=128 (8 k-chunks), 4 n-tiles ----
        float c2[4][4];
        #pragma unroll
        for (int j = 0; j < 4; j++)
            #pragma unroll
            for (int r = 0; r < 4; r++) c2[j][r] = 0.0f;

        #pragma unroll
        for (int c = 0; c < 8; c++) {
            uint a[4];
            a[0] = hsm[(16*wm + g)    *68 + 8*c + tg];
            a[1] = hsm[(16*wm + g + 8)*68 + 8*c + tg];
            a[2] = hsm[(16*wm + g)    *68 + 8*c + tg + 4];
            a[3] = hsm[(16*wm + g + 8)*68 + 8*c + tg + 4];
            #pragma unroll
            for (int j = 0; j < 4; j++) {
                uint b0 = w2t[(32*wn + 8*j + g)*68 + 8*c + tg];
                uint b1 = w2t[(32*wn + 8*j + g)*68 + 8*c + tg + 4];
                mma_f16(c2[j], a, b0, b1);
            }
        }

        if (idA != 0xFFFFFFFFu) {
            unsigned int slot = idA >> 31, tkk = idA & 0x7FFFFFFFu;
            float* dst = g_part + ((((size_t)slot*3 + proj)*HH + h)*NTOK + tkk)*DD;
            #pragma unroll
            for (int j = 0; j < 4; j++)
                *(float2*)&dst[32*wn + 8*j + 2*tg] =
                    make_float2(wtA*c2[j][0], wtA*c2[j][1]);
        }
        if (idB != 0xFFFFFFFFu) {
            unsigned int slot = idB >> 31, tkk = idB & 0x7FFFFFFFu;
            float* dst = g_part + ((((size_t)slot*3 + proj)*HH + h)*NTOK + tkk)*DD;
            #pragma unroll
            for (int j = 0; j < 4; j++)
                *(float2*)&dst[32*wn + 8*j + 2*tg] =
                    make_float2(wtB*c2[j][2], wtB*c2[j][3]);
        }

        if (!has_next) break;
    }
}

// ---------------------------------------------------------------------------
// Kernel 3: combine slots + RoPE; emits fp16 outputs.
// Lane owns d = 2*lane, 2*lane+1 (adjacent). RoPE partner = lane^16.
// ---------------------------------------------------------------------------
__global__ void __launch_bounds__(256) combine_rope_kernel(
    const int* __restrict__ pos_ids,
    const float* __restrict__ cosT, const float* __restrict__ sinT)
{
    const int gw   = blockIdx.x * 8 + (threadIdx.x >> 5);
    const int lane = threadIdx.x & 31;
    const int proj = gw / (HH * NTOK);
    const int rest = gw % (HH * NTOK);
    const int h  = rest / NTOK;
    const int tk = rest % NTOK;

    const size_t SLOT = (size_t)3 * HH * NTOK * DD;
    const size_t pbase = (((size_t)proj * HH + h) * NTOK + tk) * DD;
    float2 v1 = *(const float2*)&g_part[pbase + 2*lane];
    float2 v2 = *(const float2*)&g_part[pbase + SLOT + 2*lane];
    float a0 = v1.x + v2.x;
    float a1 = v1.y + v2.y;

    if (proj < 2) {
        int p = pos_ids[tk];
        float2 c = *(const float2*)&cosT[p*DD + 2*lane];
        float2 s = *(const float2*)&sinT[p*DD + 2*lane];
        float o0 = __shfl_xor_sync(0xffffffffu, a0, 16);
        float o1 = __shfl_xor_sync(0xffffffffu, a1, 16);
        float rot0 = (lane < 16) ? -o0 : o0;
        float rot1 = (lane < 16) ? -o1 : o1;
        a0 = a0 * c.x + rot0 * s.x;
        a1 = a1 * c.y + rot1 * s.y;
    }
    if (proj == 0) { a0 *= 0.125f; a1 *= 0.125f; }

    int b = tk >> 10, t = tk & 1023;
    int bh = b * HH + h;
    if (proj == 2) {
        // pair-along-t layout: g_vh[bh][t/2][d] with halves (t even=lo, odd=hi)
        size_t base = ((size_t)bh * 512 + (t >> 1)) * 64;
        half* vh = (half*)g_vh;
        vh[(base + 2*lane)     * 2 + (t & 1)] = __float2half(a0);
        vh[(base + 2*lane + 1) * 2 + (t & 1)] = __float2half(a1);
    } else {
        uint hv = f2h2(a0, a1);
        uint* outg = (proj == 0) ? g_qh : g_kh;
        outg[((size_t)bh * TT + t) * 32 + lane] = hv;
    }
}

// ---------------------------------------------------------------------------
// Kernel 4: causal flash attention, fp16 mma m16n8k16, BQ=128, BK=64.
// smem(uints): K 2x[64][36]=4608, V 2x[32][72]=4608, pw/Qstage 4608 -> 13824
// ---------------------------------------------------------------------------
#define ATTN_SMEM (13824 * 4)

__global__ void __launch_bounds__(256, 2) attn_kernel()
{
    extern __shared__ uint smu[];
    uint* psm = smu + 9216;           // Q staging [128][36] / per-warp P [16][36]

    const int wid = blockIdx.x;       // 0..511 heavy-major
    const int qtb = 7 - (wid >> 6);
    const int bh  = wid & 63;
    const int tid  = threadIdx.x;
    const int w    = tid >> 5;
    const int lane = tid & 31;
    const int g    = lane >> 2;
    const int tg   = lane & 3;
    uint* pw = psm + w * 576;         // [16][36]

    const uint* qg = g_qh + (size_t)bh * TT * 32;
    const uint* kg = g_kh + (size_t)bh * TT * 32;
    const uint* vg = g_vh + (size_t)bh * 512 * 64;
    const int q0 = qtb * 128;
    const uint sbase = (uint)__cvta_generic_to_shared(smu);

    // stage Q rows (raw half2 bits, pre-scaled) into psm [128][36]
    #pragma unroll
    for (int it = 0; it < 4; it++) {
        int idx = tid + it * 256;
        int row = idx >> 3, c4 = (idx & 7) * 4;
        *(uint4*)&psm[row*36 + c4] = *(const uint4*)&qg[(size_t)(q0 + row)*32 + c4];
    }
    __syncthreads();
    uint qa[4][4];
    {
        int rA = 16*w + g;
        #pragma unroll
        for (int c = 0; c < 4; c++) {
            qa[c][0] = psm[rA*36     + 8*c + tg];
            qa[c][1] = psm[(rA+8)*36 + 8*c + tg];
            qa[c][2] = psm[rA*36     + 8*c + tg + 4];
            qa[c][3] = psm[(rA+8)*36 + 8*c + tg + 4];
        }
    }

    float oa[8][4];
    #pragma unroll
    for (int j = 0; j < 8; j++)
        #pragma unroll
        for (int r = 0; r < 4; r++) oa[j][r] = 0.0f;
    float mA = -1e30f, mB = -1e30f, lA = 0.0f, lB = 0.0f;

    const int ktmax = 2*qtb + 1;

    // K buf kt&1 at smu + (kt&1)*2304, V buf at smu + 4608 + (kt&1)*2304
    #define ISSUE_TILE(kt_) do {                                              \
        int k0_ = (kt_) * 64;                                                 \
        uint kb_ = sbase + (((kt_) & 1) * 2304) * 4;                          \
        uint vb_ = sbase + (4608 + ((kt_) & 1) * 2304) * 4;                   \
        _Pragma("unroll")                                                     \
        for (int it_ = 0; it_ < 2; it_++) {                                   \
            int idx_ = tid + it_ * 256;                                       \
            int krow_ = idx_ >> 3, kc4_ = (idx_ & 7) * 4;                     \
            cpa16(kb_ + (krow_*36 + kc4_)*4,                                  \
                  &kg[(size_t)(k0_ + krow_)*32 + kc4_]);                      \
            int vrow_ = idx_ >> 4, vc4_ = (idx_ & 15) * 4;                    \
            cpa16(vb_ + (vrow_*72 + vc4_)*4,                                  \
                  &vg[(size_t)(k0_/2 + vrow_)*64 + vc4_]);                    \
        }                                                                     \
        asm volatile("cp.async.commit_group;");                               \
    } while (0)

    ISSUE_TILE(0);

    for (int kt = 0; kt <= ktmax; kt++) {
        if (kt < ktmax) {
            ISSUE_TILE(kt + 1);
            asm volatile("cp.async.wait_group 1;");
        } else {
            asm volatile("cp.async.wait_group 0;");
        }
        __syncthreads();
        const uint* ksm = smu + (kt & 1) * 2304;          // [64][36]
        const uint* vsm = smu + 4608 + (kt & 1) * 2304;   // [32][72]
        const int k0 = kt * 64;

        // ---- QK: 4 k-chunks x 8 key n-tiles ----
        float sc[8][4];
        #pragma unroll
        for (int j = 0; j < 8; j++)
            #pragma unroll
            for (int r = 0; r < 4; r++) sc[j][r] = 0.0f;

        #pragma unroll
        for (int c = 0; c < 4; c++) {
            #pragma unroll
            for (int j = 0; j < 8; j++) {
                uint b0 = ksm[(8*j + g)*36 + 8*c + tg];
                uint b1 = ksm[(8*j + g)*36 + 8*c + tg + 4];
                mma_f16(sc[j], qa[c], b0, b1);
            }
        }

        if (kt >= ktmax - 1) {
            const int rA = q0 + 16*w + g, rB = rA + 8;
            #pragma unroll
            for (int j = 0; j < 8; j++) {
                int col = k0 + 8*j + 2*tg;
                if (col     > rA) sc[j][0] = -1e30f;
                if (col + 1 > rA) sc[j][1] = -1e30f;
                if (col     > rB) sc[j][2] = -1e30f;
                if (col + 1 > rB) sc[j][3] = -1e30f;
            }
        }

        float mtA = -1e30f, mtB = -1e30f;
        #pragma unroll
        for (int j = 0; j < 8; j++) {
            mtA = fmaxf(mtA, fmaxf(sc[j][0], sc[j][1]));
            mtB = fmaxf(mtB, fmaxf(sc[j][2], sc[j][3]));
        }
        mtA = fmaxf(mtA, __shfl_xor_sync(0xffffffffu, mtA, 1));
        mtA = fmaxf(mtA, __shfl_xor_sync(0xffffffffu, mtA, 2));
        mtB = fmaxf(mtB, __shfl_xor_sync(0xffffffffu, mtB, 1));
        mtB = fmaxf(mtB, __shfl_xor_sync(0xffffffffu, mtB, 2));

        float mnA = fmaxf(mA, mtA), mnB = fmaxf(mB, mtB);
        float aA = __expf(mA - mnA), aB = __expf(mB - mnB);
        mA = mnA; mB = mnB;

        float psA = 0.0f, psB = 0.0f;
        #pragma unroll
        for (int j = 0; j < 8; j++) {
            sc[j][0] = __expf(sc[j][0] - mnA);
            sc[j][1] = __expf(sc[j][1] - mnA);
            sc[j][2] = __expf(sc[j][2] - mnB);
            sc[j][3] = __expf(sc[j][3] - mnB);
            psA += sc[j][0] + sc[j][1];
            psB += sc[j][2] + sc[j][3];
        }
        psA += __shfl_xor_sync(0xffffffffu, psA, 1);
        psA += __shfl_xor_sync(0xffffffffu, psA, 2);
        psB += __shfl_xor_sync(0xffffffffu, psB, 1);
        psB += __shfl_xor_sync(0xffffffffu, psB, 2);
        lA = lA * aA + psA;
        lB = lB * aB + psB;

        #pragma unroll
        for (int j = 0; j < 8; j++) {
            oa[j][0] *= aA; oa[j][1] *= aA;
            oa[j][2] *= aB; oa[j][3] *= aB;
        }

        // ---- P -> per-warp smem as half2 along key (direct pack) ----
        #pragma unroll
        for (int j = 0; j < 8; j++) {
            pw[g*36     + 4*j + tg] = f2h2(sc[j][0], sc[j][1]);
            pw[(g+8)*36 + 4*j + tg] = f2h2(sc[j][2], sc[j][3]);
        }
        __syncwarp();

        // ---- PV: 4 k-chunks (16 keys each) x 8 d n-tiles ----
        #pragma unroll
        for (int c = 0; c < 4; c++) {
            uint pa[4];
            pa[0] = pw[g*36     + 8*c + tg];
            pa[1] = pw[(g+8)*36 + 8*c + tg];
            pa[2] = pw[g*36     + 8*c + tg + 4];
            pa[3] = pw[(g+8)*36 + 8*c + tg + 4];
            #pragma unroll
            for (int jd = 0; jd < 8; jd++) {
                uint b0 = vsm[(8*c + tg)*72     + 8*jd + g];
                uint b1 = vsm[(8*c + tg + 4)*72 + 8*jd + g];
                mma_f16(oa[jd], pa, b0, b1);
            }
        }
        __syncthreads();
    }
    #undef ISSUE_TILE

    // epilogue: store half2 pairs (outproj consumes raw)
    const int b = bh / HH, h = bh % HH;
    float invA = 1.0f / lA, invB = 1.0f / lB;
    const int rA = q0 + 16*w + g, rB = rA + 8;
    #pragma unroll
    for (int jd = 0; jd < 8; jd++) {
        g_aoh[((size_t)(b * TT) + rA) * 512 + h * 32 + 4*jd + tg] =
            f2h2(oa[jd][0] * invA, oa[jd][1] * invA);
        g_aoh[((size_t)(b * TT) + rB) * 512 + h * 32 + 4*jd + tg] =
            f2h2(oa[jd][2] * invB, oa[jd][3] * invB);
    }
}

// ---------------------------------------------------------------------------
// Kernel 5: y = ao @ ow^T, fp16 mma, BM=128, BN=128, BK=32, cp.async pipelined.
// smem: 2 x (as[128][20] + bs[128][20]) = 10240 uints = 40960 B.
// ---------------------------------------------------------------------------
#define OUT_SMEM (10240 * 4)

__global__ void __launch_bounds__(256, 2) outproj_kernel(float* __restrict__ y)
{
    extern __shared__ uint osm[];

    const int tid  = threadIdx.x;
    const int w    = tid >> 5;
    const int lane = tid & 31;
    const int g    = lane >> 2;
    const int tg   = lane & 3;
    const int n0 = blockIdx.x * 128;
    const int m0 = blockIdx.y * 128;
    const uint sbase = (uint)__cvta_generic_to_shared(osm);

    float acc[16][4];
    #pragma unroll
    for (int j = 0; j < 16; j++)
        #pragma unroll
        for (int r = 0; r < 4; r++) acc[j][r] = 0.0f;

    // rows: 16 uints per 32-float k-chunk; stride 20
    #define OP_ISSUE(kc_, buf_) do {                                          \
        uint ab_ = sbase + (buf_) * 5120 * 4;                                 \
        uint bb_ = ab_ + 2560 * 4;                                            \
        _Pragma("unroll")                                                     \
        for (int it_ = 0; it_ < 2; it_++) {                                   \
            int idx_ = tid + it_ * 256;                                       \
            int row_ = idx_ >> 2, c4_ = (idx_ & 3) * 4;                       \
            cpa16(ab_ + (row_*20 + c4_)*4,                                    \
                  &g_aoh[(size_t)(m0 + row_) * 512 + (kc_)*16 + c4_]);        \
            cpa16(bb_ + (row_*20 + c4_)*4,                                    \
                  &g_owth[(size_t)(n0 + row_) * 512 + (kc_)*16 + c4_]);       \
        }                                                                     \
        asm volatile("cp.async.commit_group;");                               \
    } while (0)

    OP_ISSUE(0, 0);

    for (int kc = 0; kc < 32; kc++) {
        if (kc < 31) {
            OP_ISSUE(kc + 1, (kc + 1) & 1);
            asm volatile("cp.async.wait_group 1;");
        } else {
            asm volatile("cp.async.wait_group 0;");
        }
        __syncthreads();
        const uint* as = osm + (kc & 1) * 5120;
        const uint* bs = as + 2560;

        #pragma unroll
        for (int c = 0; c < 2; c++) {
            uint a[4];
            a[0] = as[(16*w + g)    *20 + 8*c + tg];
            a[1] = as[(16*w + g + 8)*20 + 8*c + tg];
            a[2] = as[(16*w + g)    *20 + 8*c + tg + 4];
            a[3] = as[(16*w + g + 8)*20 + 8*c + tg + 4];
            #pragma unroll
            for (int j = 0; j < 16; j++) {
                uint b0 = bs[(8*j + g)*20 + 8*c + tg];
                uint b1 = bs[(8*j + g)*20 + 8*c + tg + 4];
                mma_f16(acc[j], a, b0, b1);
            }
        }
        __syncthreads();
    }
    #undef OP_ISSUE

    const int rA = m0 + 16*w + g, rB = rA + 8;
    #pragma unroll
    for (int j = 0; j < 16; j++) {
        *(float2*)&y[(size_t)rA * 1024 + n0 + 8*j + 2*tg] =
            make_float2(acc[j][0], acc[j][1]);
        *(float2*)&y[(size_t)rB * 1024 + n0 + 8*j + 2*tg] =
            make_float2(acc[j][2], acc[j][3]);
    }
}

// ---------------------------------------------------------------------------
extern "C" void kernel_launch(void* const* d_in, const int* in_sizes, int n_in,
                              void* d_out, int out_size)
{
    const float* x    = (const float*)d_in[0];
    const int*   pid  = (const int*)  d_in[1];
    const float* cosT = (const float*)d_in[2];
    const float* sinT = (const float*)d_in[3];
    const float* rq   = (const float*)d_in[4];
    const float* rk   = (const float*)d_in[5];
    const float* rv   = (const float*)d_in[6];
    const float* qw1  = (const float*)d_in[7];
    const float* qw2  = (const float*)d_in[8];
    const float* kw1  = (const float*)d_in[9];
    const float* kw2  = (const float*)d_in[10];
    const float* vw1  = (const float*)d_in[11];
    const float* vw2  = (const float*)d_in[12];
    const float* ow   = (const float*)d_in[13];
    float* y = (float*)d_out;

    cudaFuncSetAttribute(moe_gemm_kernel,
                         cudaFuncAttributeMaxDynamicSharedMemorySize, MOE_SMEM);
    cudaFuncSetAttribute(attn_kernel,
                         cudaFuncAttributeMaxDynamicSharedMemorySize, ATTN_SMEM);
    cudaFuncSetAttribute(outproj_kernel,
                         cudaFuncAttributeMaxDynamicSharedMemorySize, OUT_SMEM);

    zero_cnt_kernel<<<1, 512>>>();
    route_kernel<<<NTOK, 96>>>(x, rq, rk, rv, ow);
    moe_gemm_kernel<<<NUNIT * SPLITS, 512, MOE_SMEM>>>(x, qw1, qw2, kw1, kw2, vw1, vw2);
    combine_rope_kernel<<<(3 * HH * NTOK) / 8, 256>>>(pid, cosT, sinT);

    attn_kernel<<<512, 256, ATTN_SMEM>>>();

    dim3 g3(CC / 128, (BB * TT) / 128);
    outproj_kernel<<<g3, 256, OUT_SMEM>>>(y);
}

// round 11
// speedup vs baseline: 1.8521x; 1.0675x over previous
#include <cuda_runtime.h>
#include <cuda_fp16.h>
#include <math.h>

#define BB 4
#define TT 1024
#define CC 1024
#define HH 16
#define DD 64
#define EE 8
#define HID 128
#define NTOK (BB*TT)
#define NUNIT (3*HH*EE)
#define SPLITS 3

#define NEG_HUGE (-3.38953139e38f)
#define L2E 1.4426950408889634f

typedef unsigned int uint;

// ---------------- fp16 mma helpers (m16n8k16, fp32 accumulate) ----------------
__device__ __forceinline__ uint f2h2(float lo, float hi) {
    __half2 h = __floats2half2_rn(lo, hi);
    return *(uint*)&h;
}
__device__ __forceinline__ void mma_f16(float c[4], const uint a[4], uint b0, uint b1) {
    asm("mma.sync.aligned.m16n8k16.row.col.f32.f16.f16.f32 "
        "{%0,%1,%2,%3}, {%4,%5,%6,%7}, {%8,%9}, {%0,%1,%2,%3};"
        : "+f"(c[0]), "+f"(c[1]), "+f"(c[2]), "+f"(c[3])
        : "r"(a[0]), "r"(a[1]), "r"(a[2]), "r"(a[3]), "r"(b0), "r"(b1));
}
__device__ __forceinline__ void cpa16(uint dst, const void* src) {
    asm volatile("cp.async.cg.shared.global [%0], [%1], 16;" :: "r"(dst), "l"(src));
}
// pack (lo,hi) to half2 then 2^x per half in ONE MUFU op
__device__ __forceinline__ uint ex2h2(float lo, float hi) {
    uint r;
    asm("cvt.rn.f16x2.f32 %0, %1, %2;" : "=r"(r) : "f"(hi), "f"(lo));
    asm("ex2.approx.f16x2 %0, %0;" : "+r"(r));
    return r;
}

// ---------------- device scratch ----------------
__device__ uint g_qh[BB*HH*TT*32];     // [bh][t][d/2] half2 along d, pre-scaled
__device__ uint g_kh[BB*HH*TT*32];
__device__ uint g_vh[BB*HH*512*64];    // [bh][t/2][d]  half2 along t
__device__ uint g_xh[NTOK*512];        // x as half2 along c
__device__ uint g_aoh[(size_t)BB*TT*512];      // [tok][c/2] half2 along c
__device__ uint g_owth[(size_t)CC*512];        // [n][k/2] half2 along k
__device__ unsigned int g_cnt[NUNIT];
__device__ unsigned int g_ent_id[NUNIT*NTOK];
__device__ float        g_ent_wt[NUNIT*NTOK];
__device__ float g_part[2ll*3*HH*NTOK*DD];     // fp32 partials

__device__ __forceinline__ float gelu_tanh(float t) {
    float t3 = t * t * t;
    return t / (1.0f + __expf(-1.5957691216057308f * (t + 0.044715f * t3)));
}

// ---------------------------------------------------------------------------
__global__ void zero_cnt_kernel() {
    if (threadIdx.x < NUNIT) g_cnt[threadIdx.x] = 0u;
}

// ---------------------------------------------------------------------------
// Kernel 1: routing + ow/x fp16 pre-conversion.
// ---------------------------------------------------------------------------
__global__ void __launch_bounds__(96) route_kernel(
    const float* __restrict__ x,
    const float* __restrict__ rq, const float* __restrict__ rk,
    const float* __restrict__ rv, const float* __restrict__ ow)
{
    const int tk   = blockIdx.x;
    const int tid  = threadIdx.x;
    const int w    = tid >> 5;
    const int lane = tid & 31;
    const int e    = lane & 7;
    const int hq   = lane >> 3;

    __shared__ float xs[CC];
    __shared__ float rs[3][DD*EE];

    for (int i = tid; i < 128; i += 96) {
        int idx = tk * 128 + i;
        float2 v = ((const float2*)ow)[idx];
        g_owth[idx] = f2h2(v.x, v.y);
    }

    for (int i = tid; i < CC/4; i += 96)
        ((float4*)xs)[i] = ((const float4*)(x + (size_t)tk * CC))[i];
    for (int i = tid; i < DD*EE; i += 96) {
        rs[0][i] = rq[i]; rs[1][i] = rk[i]; rs[2][i] = rv[i];
    }
    __syncthreads();

    // x -> half2
    for (int i = tid; i < 512; i += 96)
        g_xh[tk * 512 + i] = f2h2(xs[2*i], xs[2*i + 1]);

    const float* rw = rs[w];
    for (int hb = 0; hb < 4; hb++) {
        int h = hb * 4 + hq;
        float acc = 0.0f;
        #pragma unroll 16
        for (int d = 0; d < DD; d++) acc += xs[h*DD + d] * rw[d*EE + e];

        float m1 = NEG_HUGE, m2 = NEG_HUGE;
        int   i1 = 0, i2 = 0;
        #pragma unroll
        for (int ee = 0; ee < EE; ee++) {
            float v = __shfl_sync(0xffffffffu, acc, hq*8 + ee);
            if (v > m1)      { m2 = m1; i2 = i1; m1 = v; i1 = ee; }
            else if (v > m2) { m2 = v;  i2 = ee; }
        }
        if (e == 0) {
            float dex = expf(m2 - m1);
            float wt1 = 1.0f / (1.0f + dex);
            float wt2 = dex * wt1;
            int base = (w * HH + h) * EE;
            unsigned int p1 = atomicAdd(&g_cnt[base + i1], 1u);
            g_ent_id[(size_t)(base + i1) * NTOK + p1] = (unsigned int)tk;
            g_ent_wt[(size_t)(base + i1) * NTOK + p1] = wt1;
            unsigned int p2 = atomicAdd(&g_cnt[base + i2], 1u);
            g_ent_id[(size_t)(base + i2) * NTOK + p2] = (unsigned int)tk | 0x80000000u;
            g_ent_wt[(size_t)(base + i2) * NTOK + p2] = wt2;
        }
    }
}

// ---------------------------------------------------------------------------
// Kernel 2: expert-grouped MoE GEMM, fp16 mma, 512 threads, 128-token tiles.
// x gathered as half2 from g_xh (half the bytes, no converts).
// ---------------------------------------------------------------------------
#define MOE_SMEM (22272 * 4)

__global__ void __launch_bounds__(512) moe_gemm_kernel(
    const float* __restrict__ qw1, const float* __restrict__ qw2,
    const float* __restrict__ kw1, const float* __restrict__ kw2,
    const float* __restrict__ vw1, const float* __restrict__ vw2)
{
    const int gid  = blockIdx.x;
    const int unit = gid / SPLITS;
    const int s    = gid % SPLITS;
    const int proj = unit >> 7;
    const int h    = (unit >> 3) & 15;
    const int e    = unit & 7;

    const float* w1 = ((proj == 0) ? qw1 : (proj == 1) ? kw1 : vw1) + (size_t)e * DD * HID;
    const float* w2 = ((proj == 0) ? qw2 : (proj == 1) ? kw2 : vw2) + (size_t)e * HID * DD;

    extern __shared__ uint smu[];
    uint* w1t = smu;                    // [128 f][36]
    uint* w2t = smu + 128*36;           // [64 d][68]
    uint* hsm = w2t + 64*68;            // [128 tok][68]
    uint* xsm = hsm + 128*68;           // [128 tok][36]

    const int tid  = threadIdx.x;
    const int w    = tid >> 5;
    const int lane = tid & 31;
    const int g    = lane >> 2;
    const int tg   = lane & 3;
    const int wm   = w & 7;
    const int wn   = w >> 3;
    const int myTok = tid >> 2;
    const int part  = tid & 3;

    const int nt = (int)g_cnt[unit];
    const size_t ent_base = (size_t)unit * NTOK;

    int base = s * 128;
    if (base >= nt) return;

    for (int i = tid; i < DD*HID; i += 512) {
        int d = i >> 7, f = i & 127;
        ((half*)w1t)[f*72 + d] = __float2half(w1[i]);
    }
    for (int i = tid; i < HID*DD; i += 512) {
        int j = i >> 6, d = i & 63;
        ((half*)w2t)[d*136 + j] = __float2half(w2[i]);
    }

    uint xg[8];
    {
        uint idg = 0xFFFFFFFFu;
        int idx = base + myTok;
        if (idx < nt) idg = g_ent_id[ent_base + idx];
        #pragma unroll
        for (int q = 0; q < 8; q++) xg[q] = 0u;
        if (idg != 0xFFFFFFFFu) {
            const uint4* src = (const uint4*)(g_xh + (size_t)(idg & 0x7FFFFFFFu) * 512 + h * 32 + part * 8);
            uint4 v0 = src[0], v1 = src[1];
            xg[0]=v0.x; xg[1]=v0.y; xg[2]=v0.z; xg[3]=v0.w;
            xg[4]=v1.x; xg[5]=v1.y; xg[6]=v1.z; xg[7]=v1.w;
        }
    }

    const int tokA = 16*wm + g, tokB = tokA + 8;

    for (int b2 = base; ; b2 += SPLITS * 128) {
        {
            uint* dst = xsm + myTok * 36 + part * 8;
            #pragma unroll
            for (int q = 0; q < 8; q++) dst[q] = xg[q];
        }

        uint idA = 0xFFFFFFFFu, idB = 0xFFFFFFFFu;
        float wtA = 0.0f, wtB = 0.0f;
        if (b2 + tokA < nt) {
            idA = g_ent_id[ent_base + b2 + tokA];
            wtA = g_ent_wt[ent_base + b2 + tokA];
        }
        if (b2 + tokB < nt) {
            idB = g_ent_id[ent_base + b2 + tokB];
            wtB = g_ent_wt[ent_base + b2 + tokB];
        }

        const int bn = b2 + SPLITS * 128;
        const bool has_next = bn < nt;
        uint idgn = 0xFFFFFFFFu;
        if (has_next && bn + myTok < nt) idgn = g_ent_id[ent_base + bn + myTok];

        __syncthreads();

        // ---- stage 1: H = gelu(X @ W1) ----
        float c1[8][4];
        #pragma unroll
        for (int j = 0; j < 8; j++)
            #pragma unroll
            for (int r = 0; r < 4; r++) c1[j][r] = 0.0f;

        #pragma unroll
        for (int c = 0; c < 4; c++) {
            uint a[4];
            a[0] = xsm[(16*wm + g)    *36 + 8*c + tg];
            a[1] = xsm[(16*wm + g + 8)*36 + 8*c + tg];
            a[2] = xsm[(16*wm + g)    *36 + 8*c + tg + 4];
            a[3] = xsm[(16*wm + g + 8)*36 + 8*c + tg + 4];
            #pragma unroll
            for (int j = 0; j < 8; j++) {
                uint b0 = w1t[(64*wn + 8*j + g)*36 + 8*c + tg];
                uint b1 = w1t[(64*wn + 8*j + g)*36 + 8*c + tg + 4];
                mma_f16(c1[j], a, b0, b1);
            }
        }
        #pragma unroll
        for (int j = 0; j < 8; j++) {
            int col2 = 32*wn + 4*j + tg;
            hsm[(16*wm + g)    *68 + col2] = f2h2(gelu_tanh(c1[j][0]), gelu_tanh(c1[j][1]));
            hsm[(16*wm + g + 8)*68 + col2] = f2h2(gelu_tanh(c1[j][2]), gelu_tanh(c1[j][3]));
        }

        #pragma unroll
        for (int q = 0; q < 8; q++) xg[q] = 0u;
        if (idgn != 0xFFFFFFFFu) {
            const uint4* src = (const uint4*)(g_xh + (size_t)(idgn & 0x7FFFFFFFu) * 512 + h * 32 + part * 8);
            uint4 v0 = src[0], v1 = src[1];
            xg[0]=v0.x; xg[1]=v0.y; xg[2]=v0.z; xg[3]=v0.w;
            xg[4]=v1.x; xg[5]=v1.y; xg[6]=v1.z; xg[7]=v1.w;
        }

        __syncthreads();

        // ---- stage 2: O = H @ W2 ----
        float c2[4][4];
        #pragma unroll
        for (int j = 0; j < 4; j++)
            #pragma unroll
            for (int r = 0; r < 4; r++) c2[j][r] = 0.0f;

        #pragma unroll
        for (int c = 0; c < 8; c++) {
            uint a[4];
            a[0] = hsm[(16*wm + g)    *68 + 8*c + tg];
            a[1] = hsm[(16*wm + g + 8)*68 + 8*c + tg];
            a[2] = hsm[(16*wm + g)    *68 + 8*c + tg + 4];
            a[3] = hsm[(16*wm + g + 8)*68 + 8*c + tg + 4];
            #pragma unroll
            for (int j = 0; j < 4; j++) {
                uint b0 = w2t[(32*wn + 8*j + g)*68 + 8*c + tg];
                uint b1 = w2t[(32*wn + 8*j + g)*68 + 8*c + tg + 4];
                mma_f16(c2[j], a, b0, b1);
            }
        }

        if (idA != 0xFFFFFFFFu) {
            unsigned int slot = idA >> 31, tkk = idA & 0x7FFFFFFFu;
            float* dst = g_part + ((((size_t)slot*3 + proj)*HH + h)*NTOK + tkk)*DD;
            #pragma unroll
            for (int j = 0; j < 4; j++)
                *(float2*)&dst[32*wn + 8*j + 2*tg] =
                    make_float2(wtA*c2[j][0], wtA*c2[j][1]);
        }
        if (idB != 0xFFFFFFFFu) {
            unsigned int slot = idB >> 31, tkk = idB & 0x7FFFFFFFu;
            float* dst = g_part + ((((size_t)slot*3 + proj)*HH + h)*NTOK + tkk)*DD;
            #pragma unroll
            for (int j = 0; j < 4; j++)
                *(float2*)&dst[32*wn + 8*j + 2*tg] =
                    make_float2(wtB*c2[j][2], wtB*c2[j][3]);
        }

        if (!has_next) break;
    }
}

// ---------------------------------------------------------------------------
// Kernel 3: combine slots + RoPE; emits fp16 outputs (unchanged from R10).
// ---------------------------------------------------------------------------
__global__ void __launch_bounds__(256) combine_rope_kernel(
    const int* __restrict__ pos_ids,
    const float* __restrict__ cosT, const float* __restrict__ sinT)
{
    const int gw   = blockIdx.x * 8 + (threadIdx.x >> 5);
    const int lane = threadIdx.x & 31;
    const int proj = gw / (HH * NTOK);
    const int rest = gw % (HH * NTOK);
    const int h  = rest / NTOK;
    const int tk = rest % NTOK;

    const size_t SLOT = (size_t)3 * HH * NTOK * DD;
    const size_t pbase = (((size_t)proj * HH + h) * NTOK + tk) * DD;
    float2 v1 = *(const float2*)&g_part[pbase + 2*lane];
    float2 v2 = *(const float2*)&g_part[pbase + SLOT + 2*lane];
    float a0 = v1.x + v2.x;
    float a1 = v1.y + v2.y;

    if (proj < 2) {
        int p = pos_ids[tk];
        float2 c = *(const float2*)&cosT[p*DD + 2*lane];
        float2 s = *(const float2*)&sinT[p*DD + 2*lane];
        float o0 = __shfl_xor_sync(0xffffffffu, a0, 16);
        float o1 = __shfl_xor_sync(0xffffffffu, a1, 16);
        float rot0 = (lane < 16) ? -o0 : o0;
        float rot1 = (lane < 16) ? -o1 : o1;
        a0 = a0 * c.x + rot0 * s.x;
        a1 = a1 * c.y + rot1 * s.y;
    }
    if (proj == 0) { a0 *= 0.125f; a1 *= 0.125f; }

    int b = tk >> 10, t = tk & 1023;
    int bh = b * HH + h;
    if (proj == 2) {
        size_t base = ((size_t)bh * 512 + (t >> 1)) * 64;
        half* vh = (half*)g_vh;
        vh[(base + 2*lane)     * 2 + (t & 1)] = __float2half(a0);
        vh[(base + 2*lane + 1) * 2 + (t & 1)] = __float2half(a1);
    } else {
        uint hv = f2h2(a0, a1);
        uint* outg = (proj == 0) ? g_qh : g_kh;
        outg[((size_t)bh * TT + t) * 32 + lane] = hv;
    }
}

// ---------------------------------------------------------------------------
// Kernel 4: causal flash attention, fp16 mma, BQ=128, BK=64.
// P stays in registers (QK C-frag == PV A-frag); exp via ex2.approx.f16x2;
// l via ones-column of V (9th PV n-tile, auto-rescaled with o).
// smem(uints): K 2x[64][36]=4608, V 2x[32][72]=4608, Q stage [128][36]=4608
// ---------------------------------------------------------------------------
#define ATTN_SMEM (13824 * 4)

__global__ void __launch_bounds__(256, 2) attn_kernel()
{
    extern __shared__ uint smu[];
    uint* psm = smu + 9216;           // Q staging [128][36]

    const int wid = blockIdx.x;       // heavy-major
    const int qtb = 7 - (wid >> 6);
    const int bh  = wid & 63;
    const int tid  = threadIdx.x;
    const int w    = tid >> 5;
    const int lane = tid & 31;
    const int g    = lane >> 2;
    const int tg   = lane & 3;

    const uint* qg = g_qh + (size_t)bh * TT * 32;
    const uint* kg = g_kh + (size_t)bh * TT * 32;
    const uint* vg = g_vh + (size_t)bh * 512 * 64;
    const int q0 = qtb * 128;
    const uint sbase = (uint)__cvta_generic_to_shared(smu);

    // init the ones columns (cols 64..71) in both V buffers (cp.async never
    // touches them; col 64 = half2(1,1) provides the l accumulator)
    for (int i = tid; i < 512; i += 256) {
        int buf = i >> 8, rc = i & 255;
        int row = rc >> 3, c = rc & 7;
        smu[4608 + buf*2304 + row*72 + 64 + c] = (c == 0) ? 0x3C003C00u : 0u;
    }

    // stage Q
    #pragma unroll
    for (int it = 0; it < 4; it++) {
        int idx = tid + it * 256;
        int row = idx >> 3, c4 = (idx & 7) * 4;
        *(uint4*)&psm[row*36 + c4] = *(const uint4*)&qg[(size_t)(q0 + row)*32 + c4];
    }
    __syncthreads();
    uint qa[4][4];
    {
        int rA = 16*w + g;
        #pragma unroll
        for (int c = 0; c < 4; c++) {
            qa[c][0] = psm[rA*36     + 8*c + tg];
            qa[c][1] = psm[(rA+8)*36 + 8*c + tg];
            qa[c][2] = psm[rA*36     + 8*c + tg + 4];
            qa[c][3] = psm[(rA+8)*36 + 8*c + tg + 4];
        }
    }

    float oa[9][4];
    #pragma unroll
    for (int j = 0; j < 9; j++)
        #pragma unroll
        for (int r = 0; r < 4; r++) oa[j][r] = 0.0f;
    float mA = -1e30f, mB = -1e30f;

    const int ktmax = 2*qtb + 1;

    #define ISSUE_TILE(kt_) do {                                              \
        int k0_ = (kt_) * 64;                                                 \
        uint kb_ = sbase + (((kt_) & 1) * 2304) * 4;                          \
        uint vb_ = sbase + (4608 + ((kt_) & 1) * 2304) * 4;                   \
        _Pragma("unroll")                                                     \
        for (int it_ = 0; it_ < 2; it_++) {                                   \
            int idx_ = tid + it_ * 256;                                       \
            int krow_ = idx_ >> 3, kc4_ = (idx_ & 7) * 4;                     \
            cpa16(kb_ + (krow_*36 + kc4_)*4,                                  \
                  &kg[(size_t)(k0_ + krow_)*32 + kc4_]);                      \
            int vrow_ = idx_ >> 4, vc4_ = (idx_ & 15) * 4;                    \
            cpa16(vb_ + (vrow_*72 + vc4_)*4,                                  \
                  &vg[(size_t)(k0_/2 + vrow_)*64 + vc4_]);                    \
        }                                                                     \
        asm volatile("cp.async.commit_group;");                               \
    } while (0)

    ISSUE_TILE(0);

    for (int kt = 0; kt <= ktmax; kt++) {
        if (kt < ktmax) {
            ISSUE_TILE(kt + 1);
            asm volatile("cp.async.wait_group 1;");
        } else {
            asm volatile("cp.async.wait_group 0;");
        }
        __syncthreads();
        const uint* ksm = smu + (kt & 1) * 2304;          // [64][36]
        const uint* vsm = smu + 4608 + (kt & 1) * 2304;   // [32][72]
        const int k0 = kt * 64;

        // ---- QK ----
        float sc[8][4];
        #pragma unroll
        for (int j = 0; j < 8; j++)
            #pragma unroll
            for (int r = 0; r < 4; r++) sc[j][r] = 0.0f;

        #pragma unroll
        for (int c = 0; c < 4; c++) {
            #pragma unroll
            for (int j = 0; j < 8; j++) {
                uint b0 = ksm[(8*j + g)*36 + 8*c + tg];
                uint b1 = ksm[(8*j + g)*36 + 8*c + tg + 4];
                mma_f16(sc[j], qa[c], b0, b1);
            }
        }

        if (kt >= ktmax - 1) {
            const int rA = q0 + 16*w + g, rB = rA + 8;
            #pragma unroll
            for (int j = 0; j < 8; j++) {
                int col = k0 + 8*j + 2*tg;
                if (col     > rA) sc[j][0] = -1e30f;
                if (col + 1 > rA) sc[j][1] = -1e30f;
                if (col     > rB) sc[j][2] = -1e30f;
                if (col + 1 > rB) sc[j][3] = -1e30f;
            }
        }

        // ---- online max ----
        float mtA = -1e30f, mtB = -1e30f;
        #pragma unroll
        for (int j = 0; j < 8; j++) {
            mtA = fmaxf(mtA, fmaxf(sc[j][0], sc[j][1]));
            mtB = fmaxf(mtB, fmaxf(sc[j][2], sc[j][3]));
        }
        mtA = fmaxf(mtA, __shfl_xor_sync(0xffffffffu, mtA, 1));
        mtA = fmaxf(mtA, __shfl_xor_sync(0xffffffffu, mtA, 2));
        mtB = fmaxf(mtB, __shfl_xor_sync(0xffffffffu, mtB, 1));
        mtB = fmaxf(mtB, __shfl_xor_sync(0xffffffffu, mtB, 2));

        float mnA = fmaxf(mA, mtA), mnB = fmaxf(mB, mtB);
        float aA = __expf(mA - mnA), aB = __expf(mB - mnB);
        mA = mnA; mB = mnB;

        // rescale accumulators (incl. the l column, tile 8)
        #pragma unroll
        for (int j = 0; j < 9; j++) {
            oa[j][0] *= aA; oa[j][1] *= aA;
            oa[j][2] *= aB; oa[j][3] *= aB;
        }

        // ---- p = 2^((s - mn)*log2e) in f16x2, stored back into sc regs ----
        float nAL = -mnA * L2E, nBL = -mnB * L2E;
        #pragma unroll
        for (int j = 0; j < 8; j++) {
            float t0 = fmaf(sc[j][0], L2E, nAL);
            float t1 = fmaf(sc[j][1], L2E, nAL);
            float t2 = fmaf(sc[j][2], L2E, nBL);
            float t3 = fmaf(sc[j][3], L2E, nBL);
            sc[j][0] = __uint_as_float(ex2h2(t0, t1));   // row A half2
            sc[j][1] = __uint_as_float(ex2h2(t2, t3));   // row B half2
        }

        // ---- PV (9 n-tiles: d0..63 + l column), P from registers ----
        #pragma unroll
        for (int c = 0; c < 4; c++) {
            uint a[4];
            a[0] = __float_as_uint(sc[2*c][0]);
            a[1] = __float_as_uint(sc[2*c][1]);
            a[2] = __float_as_uint(sc[2*c + 1][0]);
            a[3] = __float_as_uint(sc[2*c + 1][1]);
            #pragma unroll
            for (int jd = 0; jd < 9; jd++) {
                uint b0 = vsm[(8*c + tg)*72     + 8*jd + g];
                uint b1 = vsm[(8*c + tg + 4)*72 + 8*jd + g];
                mma_f16(oa[jd], a, b0, b1);
            }
        }
        __syncthreads();
    }
    #undef ISSUE_TILE

    // epilogue: l lives in oa[8][0]/oa[8][2] of lanes with tg==0
    float lA = __shfl_sync(0xffffffffu, oa[8][0], lane & 28);
    float lB = __shfl_sync(0xffffffffu, oa[8][2], lane & 28);
    const int b = bh / HH, h = bh % HH;
    float invA = 1.0f / lA, invB = 1.0f / lB;
    const int rA = q0 + 16*w + g, rB = rA + 8;
    #pragma unroll
    for (int jd = 0; jd < 8; jd++) {
        g_aoh[((size_t)(b * TT) + rA) * 512 + h * 32 + 4*jd + tg] =
            f2h2(oa[jd][0] * invA, oa[jd][1] * invA);
        g_aoh[((size_t)(b * TT) + rB) * 512 + h * 32 + 4*jd + tg] =
            f2h2(oa[jd][2] * invB, oa[jd][3] * invB);
    }
}

// ---------------------------------------------------------------------------
// Kernel 5: y = ao @ ow^T, fp16 mma (unchanged from R10).
// ---------------------------------------------------------------------------
#define OUT_SMEM (10240 * 4)

__global__ void __launch_bounds__(256, 2) outproj_kernel(float* __restrict__ y)
{
    extern __shared__ uint osm[];

    const int tid  = threadIdx.x;
    const int w    = tid >> 5;
    const int lane = tid & 31;
    const int g    = lane >> 2;
    const int tg   = lane & 3;
    const int n0 = blockIdx.x * 128;
    const int m0 = blockIdx.y * 128;
    const uint sbase = (uint)__cvta_generic_to_shared(osm);

    float acc[16][4];
    #pragma unroll
    for (int j = 0; j < 16; j++)
        #pragma unroll
        for (int r = 0; r < 4; r++) acc[j][r] = 0.0f;

    #define OP_ISSUE(kc_, buf_) do {                                          \
        uint ab_ = sbase + (buf_) * 5120 * 4;                                 \
        uint bb_ = ab_ + 2560 * 4;                                            \
        _Pragma("unroll")                                                     \
        for (int it_ = 0; it_ < 2; it_++) {                                   \
            int idx_ = tid + it_ * 256;                                       \
            int row_ = idx_ >> 2, c4_ = (idx_ & 3) * 4;                       \
            cpa16(ab_ + (row_*20 + c4_)*4,                                    \
                  &g_aoh[(size_t)(m0 + row_) * 512 + (kc_)*16 + c4_]);        \
            cpa16(bb_ + (row_*20 + c4_)*4,                                    \
                  &g_owth[(size_t)(n0 + row_) * 512 + (kc_)*16 + c4_]);       \
        }                                                                     \
        asm volatile("cp.async.commit_group;");                               \
    } while (0)

    OP_ISSUE(0, 0);

    for (int kc = 0; kc < 32; kc++) {
        if (kc < 31) {
            OP_ISSUE(kc + 1, (kc + 1) & 1);
            asm volatile("cp.async.wait_group 1;");
        } else {
            asm volatile("cp.async.wait_group 0;");
        }
        __syncthreads();
        const uint* as = osm + (kc & 1) * 5120;
        const uint* bs = as + 2560;

        #pragma unroll
        for (int c = 0; c < 2; c++) {
            uint a[4];
            a[0] = as[(16*w + g)    *20 + 8*c + tg];
            a[1] = as[(16*w + g + 8)*20 + 8*c + tg];
            a[2] = as[(16*w + g)    *20 + 8*c + tg + 4];
            a[3] = as[(16*w + g + 8)*20 + 8*c + tg + 4];
            #pragma unroll
            for (int j = 0; j < 16; j++) {
                uint b0 = bs[(8*j + g)*20 + 8*c + tg];
                uint b1 = bs[(8*j + g)*20 + 8*c + tg + 4];
                mma_f16(acc[j], a, b0, b1);
            }
        }
        __syncthreads();
    }
    #undef OP_ISSUE

    const int rA = m0 + 16*w + g, rB = rA + 8;
    #pragma unroll
    for (int j = 0; j < 16; j++) {
        *(float2*)&y[(size_t)rA * 1024 + n0 + 8*j + 2*tg] =
            make_float2(acc[j][0], acc[j][1]);
        *(float2*)&y[(size_t)rB * 1024 + n0 + 8*j + 2*tg] =
            make_float2(acc[j][2], acc[j][3]);
    }
}

// ---------------------------------------------------------------------------
extern "C" void kernel_launch(void* const* d_in, const int* in_sizes, int n_in,
                              void* d_out, int out_size)
{
    const float* x    = (const float*)d_in[0];
    const int*   pid  = (const int*)  d_in[1];
    const float* cosT = (const float*)d_in[2];
    const float* sinT = (const float*)d_in[3];
    const float* rq   = (const float*)d_in[4];
    const float* rk   = (const float*)d_in[5];
    const float* rv   = (const float*)d_in[6];
    const float* qw1  = (const float*)d_in[7];
    const float* qw2  = (const float*)d_in[8];
    const float* kw1  = (const float*)d_in[9];
    const float* kw2  = (const float*)d_in[10];
    const float* vw1  = (const float*)d_in[11];
    const float* vw2  = (const float*)d_in[12];
    const float* ow   = (const float*)d_in[13];
    float* y = (float*)d_out;

    cudaFuncSetAttribute(moe_gemm_kernel,
                         cudaFuncAttributeMaxDynamicSharedMemorySize, MOE_SMEM);
    cudaFuncSetAttribute(attn_kernel,
                         cudaFuncAttributeMaxDynamicSharedMemorySize, ATTN_SMEM);
    cudaFuncSetAttribute(outproj_kernel,
                         cudaFuncAttributeMaxDynamicSharedMemorySize, OUT_SMEM);

    zero_cnt_kernel<<<1, 512>>>();
    route_kernel<<<NTOK, 96>>>(x, rq, rk, rv, ow);
    moe_gemm_kernel<<<NUNIT * SPLITS, 512, MOE_SMEM>>>(qw1, qw2, kw1, kw2, vw1, vw2);
    combine_rope_kernel<<<(3 * HH * NTOK) / 8, 256>>>(pid, cosT, sinT);

    attn_kernel<<<512, 256, ATTN_SMEM>>>();

    dim3 g3(CC / 128, (BB * TT) / 128);
    outproj_kernel<<<g3, 256, OUT_SMEM>>>(y);
}

// round 12
// speedup vs baseline: 1.9384x; 1.0466x over previous
#include <cuda_runtime.h>
#include <cuda_fp16.h>
#include <math.h>

#define BB 4
#define TT 1024
#define CC 1024
#define HH 16
#define DD 64
#define EE 8
#define HID 128
#define NTOK (BB*TT)
#define NUNIT (3*HH*EE)
#define SPLITS 3

#define NEG_HUGE (-3.38953139e38f)
#define L2E 1.4426950408889634f

typedef unsigned int uint;

// ---------------- fp16 mma helpers (m16n8k16, fp32 accumulate) ----------------
__device__ __forceinline__ uint f2h2(float lo, float hi) {
    __half2 h = __floats2half2_rn(lo, hi);
    return *(uint*)&h;
}
__device__ __forceinline__ void mma_f16(float c[4], const uint a[4], uint b0, uint b1) {
    asm("mma.sync.aligned.m16n8k16.row.col.f32.f16.f16.f32 "
        "{%0,%1,%2,%3}, {%4,%5,%6,%7}, {%8,%9}, {%0,%1,%2,%3};"
        : "+f"(c[0]), "+f"(c[1]), "+f"(c[2]), "+f"(c[3])
        : "r"(a[0]), "r"(a[1]), "r"(a[2]), "r"(a[3]), "r"(b0), "r"(b1));
}
__device__ __forceinline__ void cpa16(uint dst, const void* src) {
    asm volatile("cp.async.cg.shared.global [%0], [%1], 16;" :: "r"(dst), "l"(src));
}
__device__ __forceinline__ uint ex2h2(float lo, float hi) {
    uint r;
    asm("cvt.rn.f16x2.f32 %0, %1, %2;" : "=r"(r) : "f"(hi), "f"(lo));
    asm("ex2.approx.f16x2 %0, %0;" : "+r"(r));
    return r;
}

// ---------------- device scratch ----------------
__device__ uint g_qh[BB*HH*TT*32];     // [bh][t][d/2] half2 along d, pre-scaled
__device__ uint g_kh[BB*HH*TT*32];
__device__ uint g_vh[BB*HH*512*64];    // [bh][t/2][d]  half2 along t
__device__ uint g_xh[NTOK*512];        // x as half2 along c
__device__ uint g_aoh[(size_t)BB*TT*512];      // [tok][c/2] half2 along c
__device__ uint g_owth[(size_t)CC*512];        // [n][k/2] half2 along k
__device__ unsigned int g_cnt[NUNIT];
__device__ unsigned int g_ent_id[NUNIT*NTOK];
__device__ float        g_ent_wt[NUNIT*NTOK];
__device__ uint g_parth[2ll*3*HH*NTOK*32];     // half2 partials [slot][proj][h][tk][d/2]

__device__ __forceinline__ float gelu_tanh(float t) {
    float t3 = t * t * t;
    return t / (1.0f + __expf(-1.5957691216057308f * (t + 0.044715f * t3)));
}

// ---------------------------------------------------------------------------
__global__ void zero_cnt_kernel() {
    if (threadIdx.x < NUNIT) g_cnt[threadIdx.x] = 0u;
}

// ---------------------------------------------------------------------------
// Kernel 1: routing + ow/x fp16 pre-conversion.
// ---------------------------------------------------------------------------
__global__ void __launch_bounds__(96) route_kernel(
    const float* __restrict__ x,
    const float* __restrict__ rq, const float* __restrict__ rk,
    const float* __restrict__ rv, const float* __restrict__ ow)
{
    const int tk   = blockIdx.x;
    const int tid  = threadIdx.x;
    const int w    = tid >> 5;
    const int lane = tid & 31;
    const int e    = lane & 7;
    const int hq   = lane >> 3;

    __shared__ float xs[CC];
    __shared__ float rs[3][DD*EE];

    for (int i = tid; i < 128; i += 96) {
        int idx = tk * 128 + i;
        float2 v = ((const float2*)ow)[idx];
        g_owth[idx] = f2h2(v.x, v.y);
    }

    for (int i = tid; i < CC/4; i += 96)
        ((float4*)xs)[i] = ((const float4*)(x + (size_t)tk * CC))[i];
    for (int i = tid; i < DD*EE; i += 96) {
        rs[0][i] = rq[i]; rs[1][i] = rk[i]; rs[2][i] = rv[i];
    }
    __syncthreads();

    for (int i = tid; i < 512; i += 96)
        g_xh[tk * 512 + i] = f2h2(xs[2*i], xs[2*i + 1]);

    const float* rw = rs[w];
    for (int hb = 0; hb < 4; hb++) {
        int h = hb * 4 + hq;
        float acc = 0.0f;
        #pragma unroll 16
        for (int d = 0; d < DD; d++) acc += xs[h*DD + d] * rw[d*EE + e];

        float m1 = NEG_HUGE, m2 = NEG_HUGE;
        int   i1 = 0, i2 = 0;
        #pragma unroll
        for (int ee = 0; ee < EE; ee++) {
            float v = __shfl_sync(0xffffffffu, acc, hq*8 + ee);
            if (v > m1)      { m2 = m1; i2 = i1; m1 = v; i1 = ee; }
            else if (v > m2) { m2 = v;  i2 = ee; }
        }
        if (e == 0) {
            float dex = expf(m2 - m1);
            float wt1 = 1.0f / (1.0f + dex);
            float wt2 = dex * wt1;
            int base = (w * HH + h) * EE;
            unsigned int p1 = atomicAdd(&g_cnt[base + i1], 1u);
            g_ent_id[(size_t)(base + i1) * NTOK + p1] = (unsigned int)tk;
            g_ent_wt[(size_t)(base + i1) * NTOK + p1] = wt1;
            unsigned int p2 = atomicAdd(&g_cnt[base + i2], 1u);
            g_ent_id[(size_t)(base + i2) * NTOK + p2] = (unsigned int)tk | 0x80000000u;
            g_ent_wt[(size_t)(base + i2) * NTOK + p2] = wt2;
        }
    }
}

// ---------------------------------------------------------------------------
// Kernel 2: expert-grouped MoE GEMM, fp16 mma, 512 threads, 128-token tiles.
// Partials now written as half2 (halves epilogue traffic).
// ---------------------------------------------------------------------------
#define MOE_SMEM (22272 * 4)

__global__ void __launch_bounds__(512) moe_gemm_kernel(
    const float* __restrict__ qw1, const float* __restrict__ qw2,
    const float* __restrict__ kw1, const float* __restrict__ kw2,
    const float* __restrict__ vw1, const float* __restrict__ vw2)
{
    const int gid  = blockIdx.x;
    const int unit = gid / SPLITS;
    const int s    = gid % SPLITS;
    const int proj = unit >> 7;
    const int h    = (unit >> 3) & 15;
    const int e    = unit & 7;

    const float* w1 = ((proj == 0) ? qw1 : (proj == 1) ? kw1 : vw1) + (size_t)e * DD * HID;
    const float* w2 = ((proj == 0) ? qw2 : (proj == 1) ? kw2 : vw2) + (size_t)e * HID * DD;

    extern __shared__ uint smu[];
    uint* w1t = smu;                    // [128 f][36]
    uint* w2t = smu + 128*36;           // [64 d][68]
    uint* hsm = w2t + 64*68;            // [128 tok][68]
    uint* xsm = hsm + 128*68;           // [128 tok][36]

    const int tid  = threadIdx.x;
    const int w    = tid >> 5;
    const int lane = tid & 31;
    const int g    = lane >> 2;
    const int tg   = lane & 3;
    const int wm   = w & 7;
    const int wn   = w >> 3;
    const int myTok = tid >> 2;
    const int part  = tid & 3;

    const int nt = (int)g_cnt[unit];
    const size_t ent_base = (size_t)unit * NTOK;

    int base = s * 128;
    if (base >= nt) return;

    for (int i = tid; i < DD*HID; i += 512) {
        int d = i >> 7, f = i & 127;
        ((half*)w1t)[f*72 + d] = __float2half(w1[i]);
    }
    for (int i = tid; i < HID*DD; i += 512) {
        int j = i >> 6, d = i & 63;
        ((half*)w2t)[d*136 + j] = __float2half(w2[i]);
    }

    uint xg[8];
    {
        uint idg = 0xFFFFFFFFu;
        int idx = base + myTok;
        if (idx < nt) idg = g_ent_id[ent_base + idx];
        #pragma unroll
        for (int q = 0; q < 8; q++) xg[q] = 0u;
        if (idg != 0xFFFFFFFFu) {
            const uint4* src = (const uint4*)(g_xh + (size_t)(idg & 0x7FFFFFFFu) * 512 + h * 32 + part * 8);
            uint4 v0 = src[0], v1 = src[1];
            xg[0]=v0.x; xg[1]=v0.y; xg[2]=v0.z; xg[3]=v0.w;
            xg[4]=v1.x; xg[5]=v1.y; xg[6]=v1.z; xg[7]=v1.w;
        }
    }

    const int tokA = 16*wm + g, tokB = tokA + 8;

    for (int b2 = base; ; b2 += SPLITS * 128) {
        {
            uint* dst = xsm + myTok * 36 + part * 8;
            #pragma unroll
            for (int q = 0; q < 8; q++) dst[q] = xg[q];
        }

        uint idA = 0xFFFFFFFFu, idB = 0xFFFFFFFFu;
        float wtA = 0.0f, wtB = 0.0f;
        if (b2 + tokA < nt) {
            idA = g_ent_id[ent_base + b2 + tokA];
            wtA = g_ent_wt[ent_base + b2 + tokA];
        }
        if (b2 + tokB < nt) {
            idB = g_ent_id[ent_base + b2 + tokB];
            wtB = g_ent_wt[ent_base + b2 + tokB];
        }

        const int bn = b2 + SPLITS * 128;
        const bool has_next = bn < nt;
        uint idgn = 0xFFFFFFFFu;
        if (has_next && bn + myTok < nt) idgn = g_ent_id[ent_base + bn + myTok];

        __syncthreads();

        // ---- stage 1: H = gelu(X @ W1) ----
        float c1[8][4];
        #pragma unroll
        for (int j = 0; j < 8; j++)
            #pragma unroll
            for (int r = 0; r < 4; r++) c1[j][r] = 0.0f;

        #pragma unroll
        for (int c = 0; c < 4; c++) {
            uint a[4];
            a[0] = xsm[(16*wm + g)    *36 + 8*c + tg];
            a[1] = xsm[(16*wm + g + 8)*36 + 8*c + tg];
            a[2] = xsm[(16*wm + g)    *36 + 8*c + tg + 4];
            a[3] = xsm[(16*wm + g + 8)*36 + 8*c + tg + 4];
            #pragma unroll
            for (int j = 0; j < 8; j++) {
                uint b0 = w1t[(64*wn + 8*j + g)*36 + 8*c + tg];
                uint b1 = w1t[(64*wn + 8*j + g)*36 + 8*c + tg + 4];
                mma_f16(c1[j], a, b0, b1);
            }
        }
        #pragma unroll
        for (int j = 0; j < 8; j++) {
            int col2 = 32*wn + 4*j + tg;
            hsm[(16*wm + g)    *68 + col2] = f2h2(gelu_tanh(c1[j][0]), gelu_tanh(c1[j][1]));
            hsm[(16*wm + g + 8)*68 + col2] = f2h2(gelu_tanh(c1[j][2]), gelu_tanh(c1[j][3]));
        }

        #pragma unroll
        for (int q = 0; q < 8; q++) xg[q] = 0u;
        if (idgn != 0xFFFFFFFFu) {
            const uint4* src = (const uint4*)(g_xh + (size_t)(idgn & 0x7FFFFFFFu) * 512 + h * 32 + part * 8);
            uint4 v0 = src[0], v1 = src[1];
            xg[0]=v0.x; xg[1]=v0.y; xg[2]=v0.z; xg[3]=v0.w;
            xg[4]=v1.x; xg[5]=v1.y; xg[6]=v1.z; xg[7]=v1.w;
        }

        __syncthreads();

        // ---- stage 2: O = H @ W2 ----
        float c2[4][4];
        #pragma unroll
        for (int j = 0; j < 4; j++)
            #pragma unroll
            for (int r = 0; r < 4; r++) c2[j][r] = 0.0f;

        #pragma unroll
        for (int c = 0; c < 8; c++) {
            uint a[4];
            a[0] = hsm[(16*wm + g)    *68 + 8*c + tg];
            a[1] = hsm[(16*wm + g + 8)*68 + 8*c + tg];
            a[2] = hsm[(16*wm + g)    *68 + 8*c + tg + 4];
            a[3] = hsm[(16*wm + g + 8)*68 + 8*c + tg + 4];
            #pragma unroll
            for (int j = 0; j < 4; j++) {
                uint b0 = w2t[(32*wn + 8*j + g)*68 + 8*c + tg];
                uint b1 = w2t[(32*wn + 8*j + g)*68 + 8*c + tg + 4];
                mma_f16(c2[j], a, b0, b1);
            }
        }

        if (idA != 0xFFFFFFFFu) {
            unsigned int slot = idA >> 31, tkk = idA & 0x7FFFFFFFu;
            uint* dst = g_parth + ((((size_t)slot*3 + proj)*HH + h)*NTOK + tkk)*32;
            #pragma unroll
            for (int j = 0; j < 4; j++)
                dst[16*wn + 4*j + tg] = f2h2(wtA*c2[j][0], wtA*c2[j][1]);
        }
        if (idB != 0xFFFFFFFFu) {
            unsigned int slot = idB >> 31, tkk = idB & 0x7FFFFFFFu;
            uint* dst = g_parth + ((((size_t)slot*3 + proj)*HH + h)*NTOK + tkk)*32;
            #pragma unroll
            for (int j = 0; j < 4; j++)
                dst[16*wn + 4*j + tg] = f2h2(wtB*c2[j][2], wtB*c2[j][3]);
        }

        if (!has_next) break;
    }
}

// ---------------------------------------------------------------------------
// Kernel 3: combine slots + RoPE; reads half2 partials, emits fp16.
// ---------------------------------------------------------------------------
__global__ void __launch_bounds__(256) combine_rope_kernel(
    const int* __restrict__ pos_ids,
    const float* __restrict__ cosT, const float* __restrict__ sinT)
{
    const int gw   = blockIdx.x * 8 + (threadIdx.x >> 5);
    const int lane = threadIdx.x & 31;
    const int proj = gw / (HH * NTOK);
    const int rest = gw % (HH * NTOK);
    const int h  = rest / NTOK;
    const int tk = rest % NTOK;

    const size_t SLOT2 = (size_t)3 * HH * NTOK * 32;
    const size_t pbase = (((size_t)proj * HH + h) * NTOK + tk) * 32;
    float2 v1 = __half22float2(*(const __half2*)&g_parth[pbase + lane]);
    float2 v2 = __half22float2(*(const __half2*)&g_parth[pbase + SLOT2 + lane]);
    float a0 = v1.x + v2.x;
    float a1 = v1.y + v2.y;

    if (proj < 2) {
        int p = pos_ids[tk];
        float2 c = *(const float2*)&cosT[p*DD + 2*lane];
        float2 s = *(const float2*)&sinT[p*DD + 2*lane];
        float o0 = __shfl_xor_sync(0xffffffffu, a0, 16);
        float o1 = __shfl_xor_sync(0xffffffffu, a1, 16);
        float rot0 = (lane < 16) ? -o0 : o0;
        float rot1 = (lane < 16) ? -o1 : o1;
        a0 = a0 * c.x + rot0 * s.x;
        a1 = a1 * c.y + rot1 * s.y;
    }
    if (proj == 0) { a0 *= 0.125f; a1 *= 0.125f; }

    int b = tk >> 10, t = tk & 1023;
    int bh = b * HH + h;
    if (proj == 2) {
        size_t base = ((size_t)bh * 512 + (t >> 1)) * 64;
        half* vh = (half*)g_vh;
        vh[(base + 2*lane)     * 2 + (t & 1)] = __float2half(a0);
        vh[(base + 2*lane + 1) * 2 + (t & 1)] = __float2half(a1);
    } else {
        uint hv = f2h2(a0, a1);
        uint* outg = (proj == 0) ? g_qh : g_kh;
        outg[((size_t)bh * TT + t) * 32 + lane] = hv;
    }
}

// ---------------------------------------------------------------------------
// Kernel 4: causal flash attention, fp16 mma (unchanged from R11).
// ---------------------------------------------------------------------------
#define ATTN_SMEM (13824 * 4)

__global__ void __launch_bounds__(256, 2) attn_kernel()
{
    extern __shared__ uint smu[];
    uint* psm = smu + 9216;

    const int wid = blockIdx.x;
    const int qtb = 7 - (wid >> 6);
    const int bh  = wid & 63;
    const int tid  = threadIdx.x;
    const int w    = tid >> 5;
    const int lane = tid & 31;
    const int g    = lane >> 2;
    const int tg   = lane & 3;

    const uint* qg = g_qh + (size_t)bh * TT * 32;
    const uint* kg = g_kh + (size_t)bh * TT * 32;
    const uint* vg = g_vh + (size_t)bh * 512 * 64;
    const int q0 = qtb * 128;
    const uint sbase = (uint)__cvta_generic_to_shared(smu);

    for (int i = tid; i < 512; i += 256) {
        int buf = i >> 8, rc = i & 255;
        int row = rc >> 3, c = rc & 7;
        smu[4608 + buf*2304 + row*72 + 64 + c] = (c == 0) ? 0x3C003C00u : 0u;
    }

    #pragma unroll
    for (int it = 0; it < 4; it++) {
        int idx = tid + it * 256;
        int row = idx >> 3, c4 = (idx & 7) * 4;
        *(uint4*)&psm[row*36 + c4] = *(const uint4*)&qg[(size_t)(q0 + row)*32 + c4];
    }
    __syncthreads();
    uint qa[4][4];
    {
        int rA = 16*w + g;
        #pragma unroll
        for (int c = 0; c < 4; c++) {
            qa[c][0] = psm[rA*36     + 8*c + tg];
            qa[c][1] = psm[(rA+8)*36 + 8*c + tg];
            qa[c][2] = psm[rA*36     + 8*c + tg + 4];
            qa[c][3] = psm[(rA+8)*36 + 8*c + tg + 4];
        }
    }

    float oa[9][4];
    #pragma unroll
    for (int j = 0; j < 9; j++)
        #pragma unroll
        for (int r = 0; r < 4; r++) oa[j][r] = 0.0f;
    float mA = -1e30f, mB = -1e30f;

    const int ktmax = 2*qtb + 1;

    #define ISSUE_TILE(kt_) do {                                              \
        int k0_ = (kt_) * 64;                                                 \
        uint kb_ = sbase + (((kt_) & 1) * 2304) * 4;                          \
        uint vb_ = sbase + (4608 + ((kt_) & 1) * 2304) * 4;                   \
        _Pragma("unroll")                                                     \
        for (int it_ = 0; it_ < 2; it_++) {                                   \
            int idx_ = tid + it_ * 256;                                       \
            int krow_ = idx_ >> 3, kc4_ = (idx_ & 7) * 4;                     \
            cpa16(kb_ + (krow_*36 + kc4_)*4,                                  \
                  &kg[(size_t)(k0_ + krow_)*32 + kc4_]);                      \
            int vrow_ = idx_ >> 4, vc4_ = (idx_ & 15) * 4;                    \
            cpa16(vb_ + (vrow_*72 + vc4_)*4,                                  \
                  &vg[(size_t)(k0_/2 + vrow_)*64 + vc4_]);                    \
        }                                                                     \
        asm volatile("cp.async.commit_group;");                               \
    } while (0)

    ISSUE_TILE(0);

    for (int kt = 0; kt <= ktmax; kt++) {
        if (kt < ktmax) {
            ISSUE_TILE(kt + 1);
            asm volatile("cp.async.wait_group 1;");
        } else {
            asm volatile("cp.async.wait_group 0;");
        }
        __syncthreads();
        const uint* ksm = smu + (kt & 1) * 2304;
        const uint* vsm = smu + 4608 + (kt & 1) * 2304;
        const int k0 = kt * 64;

        float sc[8][4];
        #pragma unroll
        for (int j = 0; j < 8; j++)
            #pragma unroll
            for (int r = 0; r < 4; r++) sc[j][r] = 0.0f;

        #pragma unroll
        for (int c = 0; c < 4; c++) {
            #pragma unroll
            for (int j = 0; j < 8; j++) {
                uint b0 = ksm[(8*j + g)*36 + 8*c + tg];
                uint b1 = ksm[(8*j + g)*36 + 8*c + tg + 4];
                mma_f16(sc[j], qa[c], b0, b1);
            }
        }

        if (kt >= ktmax - 1) {
            const int rA = q0 + 16*w + g, rB = rA + 8;
            #pragma unroll
            for (int j = 0; j < 8; j++) {
                int col = k0 + 8*j + 2*tg;
                if (col     > rA) sc[j][0] = -1e30f;
                if (col + 1 > rA) sc[j][1] = -1e30f;
                if (col     > rB) sc[j][2] = -1e30f;
                if (col + 1 > rB) sc[j][3] = -1e30f;
            }
        }

        float mtA = -1e30f, mtB = -1e30f;
        #pragma unroll
        for (int j = 0; j < 8; j++) {
            mtA = fmaxf(mtA, fmaxf(sc[j][0], sc[j][1]));
            mtB = fmaxf(mtB, fmaxf(sc[j][2], sc[j][3]));
        }
        mtA = fmaxf(mtA, __shfl_xor_sync(0xffffffffu, mtA, 1));
        mtA = fmaxf(mtA, __shfl_xor_sync(0xffffffffu, mtA, 2));
        mtB = fmaxf(mtB, __shfl_xor_sync(0xffffffffu, mtB, 1));
        mtB = fmaxf(mtB, __shfl_xor_sync(0xffffffffu, mtB, 2));

        float mnA = fmaxf(mA, mtA), mnB = fmaxf(mB, mtB);
        float aA = __expf(mA - mnA), aB = __expf(mB - mnB);
        mA = mnA; mB = mnB;

        #pragma unroll
        for (int j = 0; j < 9; j++) {
            oa[j][0] *= aA; oa[j][1] *= aA;
            oa[j][2] *= aB; oa[j][3] *= aB;
        }

        float nAL = -mnA * L2E, nBL = -mnB * L2E;
        #pragma unroll
        for (int j = 0; j < 8; j++) {
            float t0 = fmaf(sc[j][0], L2E, nAL);
            float t1 = fmaf(sc[j][1], L2E, nAL);
            float t2 = fmaf(sc[j][2], L2E, nBL);
            float t3 = fmaf(sc[j][3], L2E, nBL);
            sc[j][0] = __uint_as_float(ex2h2(t0, t1));
            sc[j][1] = __uint_as_float(ex2h2(t2, t3));
        }

        #pragma unroll
        for (int c = 0; c < 4; c++) {
            uint a[4];
            a[0] = __float_as_uint(sc[2*c][0]);
            a[1] = __float_as_uint(sc[2*c][1]);
            a[2] = __float_as_uint(sc[2*c + 1][0]);
            a[3] = __float_as_uint(sc[2*c + 1][1]);
            #pragma unroll
            for (int jd = 0; jd < 9; jd++) {
                uint b0 = vsm[(8*c + tg)*72     + 8*jd + g];
                uint b1 = vsm[(8*c + tg + 4)*72 + 8*jd + g];
                mma_f16(oa[jd], a, b0, b1);
            }
        }
        __syncthreads();
    }
    #undef ISSUE_TILE

    float lA = __shfl_sync(0xffffffffu, oa[8][0], lane & 28);
    float lB = __shfl_sync(0xffffffffu, oa[8][2], lane & 28);
    const int b = bh / HH, h = bh % HH;
    float invA = 1.0f / lA, invB = 1.0f / lB;
    const int rA = q0 + 16*w + g, rB = rA + 8;
    #pragma unroll
    for (int jd = 0; jd < 8; jd++) {
        g_aoh[((size_t)(b * TT) + rA) * 512 + h * 32 + 4*jd + tg] =
            f2h2(oa[jd][0] * invA, oa[jd][1] * invA);
        g_aoh[((size_t)(b * TT) + rB) * 512 + h * 32 + 4*jd + tg] =
            f2h2(oa[jd][2] * invB, oa[jd][3] * invB);
    }
}

// ---------------------------------------------------------------------------
// Kernel 5: y = ao @ ow^T, fp16 mma, BM=128, BN=128, BK=64 (16 k-iters).
// smem: 2 x (as[128][36] + bs[128][36]) = 18432 uints = 73728 B.
// ---------------------------------------------------------------------------
#define OUT_SMEM (18432 * 4)

__global__ void __launch_bounds__(256, 2) outproj_kernel(float* __restrict__ y)
{
    extern __shared__ uint osm[];

    const int tid  = threadIdx.x;
    const int w    = tid >> 5;
    const int lane = tid & 31;
    const int g    = lane >> 2;
    const int tg   = lane & 3;
    const int n0 = blockIdx.x * 128;
    const int m0 = blockIdx.y * 128;
    const uint sbase = (uint)__cvta_generic_to_shared(osm);

    float acc[16][4];
    #pragma unroll
    for (int j = 0; j < 16; j++)
        #pragma unroll
        for (int r = 0; r < 4; r++) acc[j][r] = 0.0f;

    // k-chunk = 64 floats = 32 uints per row; row stride 36
    #define OP_ISSUE(kc_, buf_) do {                                          \
        uint ab_ = sbase + (buf_) * 9216 * 4;                                 \
        uint bb_ = ab_ + 4608 * 4;                                            \
        _Pragma("unroll")                                                     \
        for (int it_ = 0; it_ < 4; it_++) {                                   \
            int idx_ = tid + it_ * 256;                                       \
            int row_ = idx_ >> 3, c4_ = (idx_ & 7) * 4;                       \
            cpa16(ab_ + (row_*36 + c4_)*4,                                    \
                  &g_aoh[(size_t)(m0 + row_) * 512 + (kc_)*32 + c4_]);        \
            cpa16(bb_ + (row_*36 + c4_)*4,                                    \
                  &g_owth[(size_t)(n0 + row_) * 512 + (kc_)*32 + c4_]);       \
        }                                                                     \
        asm volatile("cp.async.commit_group;");                               \
    } while (0)

    OP_ISSUE(0, 0);

    for (int kc = 0; kc < 16; kc++) {
        if (kc < 15) {
            OP_ISSUE(kc + 1, (kc + 1) & 1);
            asm volatile("cp.async.wait_group 1;");
        } else {
            asm volatile("cp.async.wait_group 0;");
        }
        __syncthreads();
        const uint* as = osm + (kc & 1) * 9216;
        const uint* bs = as + 4608;

        #pragma unroll
        for (int c = 0; c < 4; c++) {
            uint a[4];
            a[0] = as[(16*w + g)    *36 + 8*c + tg];
            a[1] = as[(16*w + g + 8)*36 + 8*c + tg];
            a[2] = as[(16*w + g)    *36 + 8*c + tg + 4];
            a[3] = as[(16*w + g + 8)*36 + 8*c + tg + 4];
            #pragma unroll
            for (int j = 0; j < 16; j++) {
                uint b0 = bs[(8*j + g)*36 + 8*c + tg];
                uint b1 = bs[(8*j + g)*36 + 8*c + tg + 4];
                mma_f16(acc[j], a, b0, b1);
            }
        }
        __syncthreads();
    }
    #undef OP_ISSUE

    const int rA = m0 + 16*w + g, rB = rA + 8;
    #pragma unroll
    for (int j = 0; j < 16; j++) {
        *(float2*)&y[(size_t)rA * 1024 + n0 + 8*j + 2*tg] =
            make_float2(acc[j][0], acc[j][1]);
        *(float2*)&y[(size_t)rB * 1024 + n0 + 8*j + 2*tg] =
            make_float2(acc[j][2], acc[j][3]);
    }
}

// ---------------------------------------------------------------------------
extern "C" void kernel_launch(void* const* d_in, const int* in_sizes, int n_in,
                              void* d_out, int out_size)
{
    const float* x    = (const float*)d_in[0];
    const int*   pid  = (const int*)  d_in[1];
    const float* cosT = (const float*)d_in[2];
    const float* sinT = (const float*)d_in[3];
    const float* rq   = (const float*)d_in[4];
    const float* rk   = (const float*)d_in[5];
    const float* rv   = (const float*)d_in[6];
    const float* qw1  = (const float*)d_in[7];
    const float* qw2  = (const float*)d_in[8];
    const float* kw1  = (const float*)d_in[9];
    const float* kw2  = (const float*)d_in[10];
    const float* vw1  = (const float*)d_in[11];
    const float* vw2  = (const float*)d_in[12];
    const float* ow   = (const float*)d_in[13];
    float* y = (float*)d_out;

    cudaFuncSetAttribute(moe_gemm_kernel,
                         cudaFuncAttributeMaxDynamicSharedMemorySize, MOE_SMEM);
    cudaFuncSetAttribute(attn_kernel,
                         cudaFuncAttributeMaxDynamicSharedMemorySize, ATTN_SMEM);
    cudaFuncSetAttribute(outproj_kernel,
                         cudaFuncAttributeMaxDynamicSharedMemorySize, OUT_SMEM);

    zero_cnt_kernel<<<1, 512>>>();
    route_kernel<<<NTOK, 96>>>(x, rq, rk, rv, ow);
    moe_gemm_kernel<<<NUNIT * SPLITS, 512, MOE_SMEM>>>(qw1, qw2, kw1, kw2, vw1, vw2);
    combine_rope_kernel<<<(3 * HH * NTOK) / 8, 256>>>(pid, cosT, sinT);

    attn_kernel<<<512, 256, ATTN_SMEM>>>();

    dim3 g3(CC / 128, (BB * TT) / 128);
    outproj_kernel<<<g3, 256, OUT_SMEM>>>(y);
}

// round 13
// speedup vs baseline: 1.9435x; 1.0026x over previous
#include <cuda_runtime.h>
#include <cuda_fp16.h>
#include <math.h>

#define BB 4
#define TT 1024
#define CC 1024
#define HH 16
#define DD 64
#define EE 8
#define HID 128
#define NTOK (BB*TT)
#define NUNIT (3*HH*EE)
#define SPLITS 3

#define NEG_HUGE (-3.38953139e38f)
#define L2E 1.4426950408889634f

typedef unsigned int uint;

// ---------------- fp16 mma helpers (m16n8k16, fp32 accumulate) ----------------
__device__ __forceinline__ uint f2h2(float lo, float hi) {
    __half2 h = __floats2half2_rn(lo, hi);
    return *(uint*)&h;
}
__device__ __forceinline__ void mma_f16(float c[4], const uint a[4], uint b0, uint b1) {
    asm("mma.sync.aligned.m16n8k16.row.col.f32.f16.f16.f32 "
        "{%0,%1,%2,%3}, {%4,%5,%6,%7}, {%8,%9}, {%0,%1,%2,%3};"
        : "+f"(c[0]), "+f"(c[1]), "+f"(c[2]), "+f"(c[3])
        : "r"(a[0]), "r"(a[1]), "r"(a[2]), "r"(a[3]), "r"(b0), "r"(b1));
}
__device__ __forceinline__ void cpa16(uint dst, const void* src) {
    asm volatile("cp.async.cg.shared.global [%0], [%1], 16;" :: "r"(dst), "l"(src));
}
__device__ __forceinline__ uint ex2h2(float lo, float hi) {
    uint r;
    asm("cvt.rn.f16x2.f32 %0, %1, %2;" : "=r"(r) : "f"(hi), "f"(lo));
    asm("ex2.approx.f16x2 %0, %0;" : "+r"(r));
    return r;
}

// ---------------- device scratch ----------------
__device__ uint g_qh[BB*HH*TT*32];     // [bh][t][d/2] half2 along d, pre-scaled
__device__ uint g_kh[BB*HH*TT*32];
__device__ uint g_vh[BB*HH*512*64];    // [bh][t/2][d]  half2 along t
__device__ uint g_xh[NTOK*512];        // x as half2 along c
__device__ uint g_aoh[(size_t)BB*TT*512];      // [tok][c/2] half2 along c
__device__ uint g_owth[(size_t)CC*512];        // [n][k/2] half2 along k
__device__ unsigned int g_cnt[NUNIT];
__device__ unsigned int g_ent_id[NUNIT*NTOK];
__device__ float        g_ent_wt[NUNIT*NTOK];
__device__ uint g_parth[2ll*3*HH*NTOK*32];     // half2 partials

__device__ __forceinline__ float gelu_tanh(float t) {
    float t3 = t * t * t;
    return t / (1.0f + __expf(-1.5957691216057308f * (t + 0.044715f * t3)));
}

// ---------------------------------------------------------------------------
__global__ void zero_cnt_kernel() {
    if (threadIdx.x < NUNIT) g_cnt[threadIdx.x] = 0u;
}

// ---------------------------------------------------------------------------
// Kernel 1: routing + ow/x fp16 pre-conversion.
// ---------------------------------------------------------------------------
__global__ void __launch_bounds__(96) route_kernel(
    const float* __restrict__ x,
    const float* __restrict__ rq, const float* __restrict__ rk,
    const float* __restrict__ rv, const float* __restrict__ ow)
{
    const int tk   = blockIdx.x;
    const int tid  = threadIdx.x;
    const int w    = tid >> 5;
    const int lane = tid & 31;
    const int e    = lane & 7;
    const int hq   = lane >> 3;

    __shared__ float xs[CC];
    __shared__ float rs[3][DD*EE];

    for (int i = tid; i < 128; i += 96) {
        int idx = tk * 128 + i;
        float2 v = ((const float2*)ow)[idx];
        g_owth[idx] = f2h2(v.x, v.y);
    }

    for (int i = tid; i < CC/4; i += 96)
        ((float4*)xs)[i] = ((const float4*)(x + (size_t)tk * CC))[i];
    for (int i = tid; i < DD*EE; i += 96) {
        rs[0][i] = rq[i]; rs[1][i] = rk[i]; rs[2][i] = rv[i];
    }
    __syncthreads();

    for (int i = tid; i < 512; i += 96)
        g_xh[tk * 512 + i] = f2h2(xs[2*i], xs[2*i + 1]);

    const float* rw = rs[w];
    for (int hb = 0; hb < 4; hb++) {
        int h = hb * 4 + hq;
        float acc = 0.0f;
        #pragma unroll 16
        for (int d = 0; d < DD; d++) acc += xs[h*DD + d] * rw[d*EE + e];

        float m1 = NEG_HUGE, m2 = NEG_HUGE;
        int   i1 = 0, i2 = 0;
        #pragma unroll
        for (int ee = 0; ee < EE; ee++) {
            float v = __shfl_sync(0xffffffffu, acc, hq*8 + ee);
            if (v > m1)      { m2 = m1; i2 = i1; m1 = v; i1 = ee; }
            else if (v > m2) { m2 = v;  i2 = ee; }
        }
        if (e == 0) {
            float dex = expf(m2 - m1);
            float wt1 = 1.0f / (1.0f + dex);
            float wt2 = dex * wt1;
            int base = (w * HH + h) * EE;
            unsigned int p1 = atomicAdd(&g_cnt[base + i1], 1u);
            g_ent_id[(size_t)(base + i1) * NTOK + p1] = (unsigned int)tk;
            g_ent_wt[(size_t)(base + i1) * NTOK + p1] = wt1;
            unsigned int p2 = atomicAdd(&g_cnt[base + i2], 1u);
            g_ent_id[(size_t)(base + i2) * NTOK + p2] = (unsigned int)tk | 0x80000000u;
            g_ent_wt[(size_t)(base + i2) * NTOK + p2] = wt2;
        }
    }
}

// ---------------------------------------------------------------------------
// Kernel 2: expert-grouped MoE GEMM, fp16 mma (unchanged from R12).
// ---------------------------------------------------------------------------
#define MOE_SMEM (22272 * 4)

__global__ void __launch_bounds__(512) moe_gemm_kernel(
    const float* __restrict__ qw1, const float* __restrict__ qw2,
    const float* __restrict__ kw1, const float* __restrict__ kw2,
    const float* __restrict__ vw1, const float* __restrict__ vw2)
{
    const int gid  = blockIdx.x;
    const int unit = gid / SPLITS;
    const int s    = gid % SPLITS;
    const int proj = unit >> 7;
    const int h    = (unit >> 3) & 15;
    const int e    = unit & 7;

    const float* w1 = ((proj == 0) ? qw1 : (proj == 1) ? kw1 : vw1) + (size_t)e * DD * HID;
    const float* w2 = ((proj == 0) ? qw2 : (proj == 1) ? kw2 : vw2) + (size_t)e * HID * DD;

    extern __shared__ uint smu[];
    uint* w1t = smu;                    // [128 f][36]
    uint* w2t = smu + 128*36;           // [64 d][68]
    uint* hsm = w2t + 64*68;            // [128 tok][68]
    uint* xsm = hsm + 128*68;           // [128 tok][36]

    const int tid  = threadIdx.x;
    const int w    = tid >> 5;
    const int lane = tid & 31;
    const int g    = lane >> 2;
    const int tg   = lane & 3;
    const int wm   = w & 7;
    const int wn   = w >> 3;
    const int myTok = tid >> 2;
    const int part  = tid & 3;

    const int nt = (int)g_cnt[unit];
    const size_t ent_base = (size_t)unit * NTOK;

    int base = s * 128;
    if (base >= nt) return;

    for (int i = tid; i < DD*HID; i += 512) {
        int d = i >> 7, f = i & 127;
        ((half*)w1t)[f*72 + d] = __float2half(w1[i]);
    }
    for (int i = tid; i < HID*DD; i += 512) {
        int j = i >> 6, d = i & 63;
        ((half*)w2t)[d*136 + j] = __float2half(w2[i]);
    }

    uint xg[8];
    {
        uint idg = 0xFFFFFFFFu;
        int idx = base + myTok;
        if (idx < nt) idg = g_ent_id[ent_base + idx];
        #pragma unroll
        for (int q = 0; q < 8; q++) xg[q] = 0u;
        if (idg != 0xFFFFFFFFu) {
            const uint4* src = (const uint4*)(g_xh + (size_t)(idg & 0x7FFFFFFFu) * 512 + h * 32 + part * 8);
            uint4 v0 = src[0], v1 = src[1];
            xg[0]=v0.x; xg[1]=v0.y; xg[2]=v0.z; xg[3]=v0.w;
            xg[4]=v1.x; xg[5]=v1.y; xg[6]=v1.z; xg[7]=v1.w;
        }
    }

    const int tokA = 16*wm + g, tokB = tokA + 8;

    for (int b2 = base; ; b2 += SPLITS * 128) {
        {
            uint* dst = xsm + myTok * 36 + part * 8;
            #pragma unroll
            for (int q = 0; q < 8; q++) dst[q] = xg[q];
        }

        uint idA = 0xFFFFFFFFu, idB = 0xFFFFFFFFu;
        float wtA = 0.0f, wtB = 0.0f;
        if (b2 + tokA < nt) {
            idA = g_ent_id[ent_base + b2 + tokA];
            wtA = g_ent_wt[ent_base + b2 + tokA];
        }
        if (b2 + tokB < nt) {
            idB = g_ent_id[ent_base + b2 + tokB];
            wtB = g_ent_wt[ent_base + b2 + tokB];
        }

        const int bn = b2 + SPLITS * 128;
        const bool has_next = bn < nt;
        uint idgn = 0xFFFFFFFFu;
        if (has_next && bn + myTok < nt) idgn = g_ent_id[ent_base + bn + myTok];

        __syncthreads();

        float c1[8][4];
        #pragma unroll
        for (int j = 0; j < 8; j++)
            #pragma unroll
            for (int r = 0; r < 4; r++) c1[j][r] = 0.0f;

        #pragma unroll
        for (int c = 0; c < 4; c++) {
            uint a[4];
            a[0] = xsm[(16*wm + g)    *36 + 8*c + tg];
            a[1] = xsm[(16*wm + g + 8)*36 + 8*c + tg];
            a[2] = xsm[(16*wm + g)    *36 + 8*c + tg + 4];
            a[3] = xsm[(16*wm + g + 8)*36 + 8*c + tg + 4];
            #pragma unroll
            for (int j = 0; j < 8; j++) {
                uint b0 = w1t[(64*wn + 8*j + g)*36 + 8*c + tg];
                uint b1 = w1t[(64*wn + 8*j + g)*36 + 8*c + tg + 4];
                mma_f16(c1[j], a, b0, b1);
            }
        }
        #pragma unroll
        for (int j = 0; j < 8; j++) {
            int col2 = 32*wn + 4*j + tg;
            hsm[(16*wm + g)    *68 + col2] = f2h2(gelu_tanh(c1[j][0]), gelu_tanh(c1[j][1]));
            hsm[(16*wm + g + 8)*68 + col2] = f2h2(gelu_tanh(c1[j][2]), gelu_tanh(c1[j][3]));
        }

        #pragma unroll
        for (int q = 0; q < 8; q++) xg[q] = 0u;
        if (idgn != 0xFFFFFFFFu) {
            const uint4* src = (const uint4*)(g_xh + (size_t)(idgn & 0x7FFFFFFFu) * 512 + h * 32 + part * 8);
            uint4 v0 = src[0], v1 = src[1];
            xg[0]=v0.x; xg[1]=v0.y; xg[2]=v0.z; xg[3]=v0.w;
            xg[4]=v1.x; xg[5]=v1.y; xg[6]=v1.z; xg[7]=v1.w;
        }

        __syncthreads();

        float c2[4][4];
        #pragma unroll
        for (int j = 0; j < 4; j++)
            #pragma unroll
            for (int r = 0; r < 4; r++) c2[j][r] = 0.0f;

        #pragma unroll
        for (int c = 0; c < 8; c++) {
            uint a[4];
            a[0] = hsm[(16*wm + g)    *68 + 8*c + tg];
            a[1] = hsm[(16*wm + g + 8)*68 + 8*c + tg];
            a[2] = hsm[(16*wm + g)    *68 + 8*c + tg + 4];
            a[3] = hsm[(16*wm + g + 8)*68 + 8*c + tg + 4];
            #pragma unroll
            for (int j = 0; j < 4; j++) {
                uint b0 = w2t[(32*wn + 8*j + g)*68 + 8*c + tg];
                uint b1 = w2t[(32*wn + 8*j + g)*68 + 8*c + tg + 4];
                mma_f16(c2[j], a, b0, b1);
            }
        }

        if (idA != 0xFFFFFFFFu) {
            unsigned int slot = idA >> 31, tkk = idA & 0x7FFFFFFFu;
            uint* dst = g_parth + ((((size_t)slot*3 + proj)*HH + h)*NTOK + tkk)*32;
            #pragma unroll
            for (int j = 0; j < 4; j++)
                dst[16*wn + 4*j + tg] = f2h2(wtA*c2[j][0], wtA*c2[j][1]);
        }
        if (idB != 0xFFFFFFFFu) {
            unsigned int slot = idB >> 31, tkk = idB & 0x7FFFFFFFu;
            uint* dst = g_parth + ((((size_t)slot*3 + proj)*HH + h)*NTOK + tkk)*32;
            #pragma unroll
            for (int j = 0; j < 4; j++)
                dst[16*wn + 4*j + tg] = f2h2(wtB*c2[j][2], wtB*c2[j][3]);
        }

        if (!has_next) break;
    }
}

// ---------------------------------------------------------------------------
// Kernel 3: combine slots + RoPE; 4 rows per warp (amortize block overhead).
// ---------------------------------------------------------------------------
__global__ void __launch_bounds__(256) combine_rope_kernel(
    const int* __restrict__ pos_ids,
    const float* __restrict__ cosT, const float* __restrict__ sinT)
{
    const int warp = threadIdx.x >> 5;
    const int lane = threadIdx.x & 31;
    const int row0 = (blockIdx.x * 8 + warp) * 4;
    const size_t SLOT2 = (size_t)3 * HH * NTOK * 32;

    #pragma unroll
    for (int r = 0; r < 4; r++) {
        const int row  = row0 + r;
        const int proj = row / (HH * NTOK);
        const int rest = row % (HH * NTOK);
        const int h  = rest / NTOK;
        const int tk = rest % NTOK;

        const size_t pbase = (size_t)row * 32;
        float2 v1 = __half22float2(*(const __half2*)&g_parth[pbase + lane]);
        float2 v2 = __half22float2(*(const __half2*)&g_parth[pbase + SLOT2 + lane]);
        float a0 = v1.x + v2.x;
        float a1 = v1.y + v2.y;

        if (proj < 2) {
            int p = pos_ids[tk];
            float2 c = *(const float2*)&cosT[p*DD + 2*lane];
            float2 s = *(const float2*)&sinT[p*DD + 2*lane];
            float o0 = __shfl_xor_sync(0xffffffffu, a0, 16);
            float o1 = __shfl_xor_sync(0xffffffffu, a1, 16);
            float rot0 = (lane < 16) ? -o0 : o0;
            float rot1 = (lane < 16) ? -o1 : o1;
            a0 = a0 * c.x + rot0 * s.x;
            a1 = a1 * c.y + rot1 * s.y;
        }
        if (proj == 0) { a0 *= 0.125f; a1 *= 0.125f; }

        int b = tk >> 10, t = tk & 1023;
        int bh = b * HH + h;
        if (proj == 2) {
            size_t base = ((size_t)bh * 512 + (t >> 1)) * 64;
            half* vh = (half*)g_vh;
            vh[(base + 2*lane)     * 2 + (t & 1)] = __float2half(a0);
            vh[(base + 2*lane + 1) * 2 + (t & 1)] = __float2half(a1);
        } else {
            uint hv = f2h2(a0, a1);
            uint* outg = (proj == 0) ? g_qh : g_kh;
            outg[((size_t)bh * TT + t) * 32 + lane] = hv;
        }
    }
}

// ---------------------------------------------------------------------------
// Kernel 4: causal flash attention, fp16 mma, BQ=128, BK=64.
// 3-stage cp.async pipeline -> ONE __syncthreads per tile.
// smem(uints): K 3x[64][36]=6912, V 3x[32][72]=6912, Qstage [128][36]=4608
//   total 18432 uints = 73728 B
// ---------------------------------------------------------------------------
#define ATTN_SMEM (18432 * 4)

__global__ void __launch_bounds__(256, 2) attn_kernel()
{
    extern __shared__ uint smu[];
    uint* psm = smu + 13824;          // Q staging [128][36]

    const int wid = blockIdx.x;
    const int qtb = 7 - (wid >> 6);
    const int bh  = wid & 63;
    const int tid  = threadIdx.x;
    const int w    = tid >> 5;
    const int lane = tid & 31;
    const int g    = lane >> 2;
    const int tg   = lane & 3;

    const uint* qg = g_qh + (size_t)bh * TT * 32;
    const uint* kg = g_kh + (size_t)bh * TT * 32;
    const uint* vg = g_vh + (size_t)bh * 512 * 64;
    const int q0 = qtb * 128;
    const uint sbase = (uint)__cvta_generic_to_shared(smu);

    // ones columns (cols 64..71) of all 3 V buffers; cp.async writes cols 0..63 only
    for (int i = tid; i < 768; i += 256) {
        int buf = i >> 8, rc = i & 255;
        int row = rc >> 3, c = rc & 7;
        smu[6912 + buf*2304 + row*72 + 64 + c] = (c == 0) ? 0x3C003C00u : 0u;
    }

    #pragma unroll
    for (int it = 0; it < 4; it++) {
        int idx = tid + it * 256;
        int row = idx >> 3, c4 = (idx & 7) * 4;
        *(uint4*)&psm[row*36 + c4] = *(const uint4*)&qg[(size_t)(q0 + row)*32 + c4];
    }
    __syncthreads();
    uint qa[4][4];
    {
        int rA = 16*w + g;
        #pragma unroll
        for (int c = 0; c < 4; c++) {
            qa[c][0] = psm[rA*36     + 8*c + tg];
            qa[c][1] = psm[(rA+8)*36 + 8*c + tg];
            qa[c][2] = psm[rA*36     + 8*c + tg + 4];
            qa[c][3] = psm[(rA+8)*36 + 8*c + tg + 4];
        }
    }

    float oa[9][4];
    #pragma unroll
    for (int j = 0; j < 9; j++)
        #pragma unroll
        for (int r = 0; r < 4; r++) oa[j][r] = 0.0f;
    float mA = -1e30f, mB = -1e30f;

    const int ktmax = 2*qtb + 1;    // >= 1 always

    #define ISSUE_TILE(kt_) do {                                              \
        int k0_ = (kt_) * 64;                                                 \
        int buf_ = (kt_) % 3;                                                 \
        uint kb_ = sbase + (buf_ * 2304) * 4;                                 \
        uint vb_ = sbase + ((6912 + buf_ * 2304)) * 4;                        \
        _Pragma("unroll")                                                     \
        for (int it_ = 0; it_ < 2; it_++) {                                   \
            int idx_ = tid + it_ * 256;                                       \
            int krow_ = idx_ >> 3, kc4_ = (idx_ & 7) * 4;                     \
            cpa16(kb_ + (krow_*36 + kc4_)*4,                                  \
                  &kg[(size_t)(k0_ + krow_)*32 + kc4_]);                      \
            int vrow_ = idx_ >> 4, vc4_ = (idx_ & 15) * 4;                    \
            cpa16(vb_ + (vrow_*72 + vc4_)*4,                                  \
                  &vg[(size_t)(k0_/2 + vrow_)*64 + vc4_]);                    \
        }                                                                     \
        asm volatile("cp.async.commit_group;");                               \
    } while (0)

    ISSUE_TILE(0);
    ISSUE_TILE(1);

    for (int kt = 0; kt <= ktmax; kt++) {
        if (kt < ktmax) {
            asm volatile("cp.async.wait_group 1;");
        } else {
            asm volatile("cp.async.wait_group 0;");
        }
        __syncthreads();                       // single sync per tile
        if (kt + 2 <= ktmax) ISSUE_TILE(kt + 2);

        const uint* ksm = smu + (kt % 3) * 2304;
        const uint* vsm = smu + 6912 + (kt % 3) * 2304;
        const int k0 = kt * 64;

        float sc[8][4];
        #pragma unroll
        for (int j = 0; j < 8; j++)
            #pragma unroll
            for (int r = 0; r < 4; r++) sc[j][r] = 0.0f;

        #pragma unroll
        for (int c = 0; c < 4; c++) {
            #pragma unroll
            for (int j = 0; j < 8; j++) {
                uint b0 = ksm[(8*j + g)*36 + 8*c + tg];
                uint b1 = ksm[(8*j + g)*36 + 8*c + tg + 4];
                mma_f16(sc[j], qa[c], b0, b1);
            }
        }

        if (kt >= ktmax - 1) {
            const int rA = q0 + 16*w + g, rB = rA + 8;
            #pragma unroll
            for (int j = 0; j < 8; j++) {
                int col = k0 + 8*j + 2*tg;
                if (col     > rA) sc[j][0] = -1e30f;
                if (col + 1 > rA) sc[j][1] = -1e30f;
                if (col     > rB) sc[j][2] = -1e30f;
                if (col + 1 > rB) sc[j][3] = -1e30f;
            }
        }

        float mtA = -1e30f, mtB = -1e30f;
        #pragma unroll
        for (int j = 0; j < 8; j++) {
            mtA = fmaxf(mtA, fmaxf(sc[j][0], sc[j][1]));
            mtB = fmaxf(mtB, fmaxf(sc[j][2], sc[j][3]));
        }
        mtA = fmaxf(mtA, __shfl_xor_sync(0xffffffffu, mtA, 1));
        mtA = fmaxf(mtA, __shfl_xor_sync(0xffffffffu, mtA, 2));
        mtB = fmaxf(mtB, __shfl_xor_sync(0xffffffffu, mtB, 1));
        mtB = fmaxf(mtB, __shfl_xor_sync(0xffffffffu, mtB, 2));

        float mnA = fmaxf(mA, mtA), mnB = fmaxf(mB, mtB);
        float aA = __expf(mA - mnA), aB = __expf(mB - mnB);
        mA = mnA; mB = mnB;

        #pragma unroll
        for (int j = 0; j < 9; j++) {
            oa[j][0] *= aA; oa[j][1] *= aA;
            oa[j][2] *= aB; oa[j][3] *= aB;
        }

        float nAL = -mnA * L2E, nBL = -mnB * L2E;
        #pragma unroll
        for (int j = 0; j < 8; j++) {
            float t0 = fmaf(sc[j][0], L2E, nAL);
            float t1 = fmaf(sc[j][1], L2E, nAL);
            float t2 = fmaf(sc[j][2], L2E, nBL);
            float t3 = fmaf(sc[j][3], L2E, nBL);
            sc[j][0] = __uint_as_float(ex2h2(t0, t1));
            sc[j][1] = __uint_as_float(ex2h2(t2, t3));
        }

        #pragma unroll
        for (int c = 0; c < 4; c++) {
            uint a[4];
            a[0] = __float_as_uint(sc[2*c][0]);
            a[1] = __float_as_uint(sc[2*c][1]);
            a[2] = __float_as_uint(sc[2*c + 1][0]);
            a[3] = __float_as_uint(sc[2*c + 1][1]);
            #pragma unroll
            for (int jd = 0; jd < 9; jd++) {
                uint b0 = vsm[(8*c + tg)*72     + 8*jd + g];
                uint b1 = vsm[(8*c + tg + 4)*72 + 8*jd + g];
                mma_f16(oa[jd], a, b0, b1);
            }
        }
    }
    #undef ISSUE_TILE

    float lA = __shfl_sync(0xffffffffu, oa[8][0], lane & 28);
    float lB = __shfl_sync(0xffffffffu, oa[8][2], lane & 28);
    const int b = bh / HH, h = bh % HH;
    float invA = 1.0f / lA, invB = 1.0f / lB;
    const int rA = q0 + 16*w + g, rB = rA + 8;
    #pragma unroll
    for (int jd = 0; jd < 8; jd++) {
        g_aoh[((size_t)(b * TT) + rA) * 512 + h * 32 + 4*jd + tg] =
            f2h2(oa[jd][0] * invA, oa[jd][1] * invA);
        g_aoh[((size_t)(b * TT) + rB) * 512 + h * 32 + 4*jd + tg] =
            f2h2(oa[jd][2] * invB, oa[jd][3] * invB);
    }
}

// ---------------------------------------------------------------------------
// Kernel 5: y = ao @ ow^T, fp16 mma, BM=128, BN=128, BK=64 (unchanged).
// ---------------------------------------------------------------------------
#define OUT_SMEM (18432 * 4)

__global__ void __launch_bounds__(256, 2) outproj_kernel(float* __restrict__ y)
{
    extern __shared__ uint osm[];

    const int tid  = threadIdx.x;
    const int w    = tid >> 5;
    const int lane = tid & 31;
    const int g    = lane >> 2;
    const int tg   = lane & 3;
    const int n0 = blockIdx.x * 128;
    const int m0 = blockIdx.y * 128;
    const uint sbase = (uint)__cvta_generic_to_shared(osm);

    float acc[16][4];
    #pragma unroll
    for (int j = 0; j < 16; j++)
        #pragma unroll
        for (int r = 0; r < 4; r++) acc[j][r] = 0.0f;

    #define OP_ISSUE(kc_, buf_) do {                                          \
        uint ab_ = sbase + (buf_) * 9216 * 4;                                 \
        uint bb_ = ab_ + 4608 * 4;                                            \
        _Pragma("unroll")                                                     \
        for (int it_ = 0; it_ < 4; it_++) {                                   \
            int idx_ = tid + it_ * 256;                                       \
            int row_ = idx_ >> 3, c4_ = (idx_ & 7) * 4;                       \
            cpa16(ab_ + (row_*36 + c4_)*4,                                    \
                  &g_aoh[(size_t)(m0 + row_) * 512 + (kc_)*32 + c4_]);        \
            cpa16(bb_ + (row_*36 + c4_)*4,                                    \
                  &g_owth[(size_t)(n0 + row_) * 512 + (kc_)*32 + c4_]);       \
        }                                                                     \
        asm volatile("cp.async.commit_group;");                               \
    } while (0)

    OP_ISSUE(0, 0);

    for (int kc = 0; kc < 16; kc++) {
        if (kc < 15) {
            OP_ISSUE(kc + 1, (kc + 1) & 1);
            asm volatile("cp.async.wait_group 1;");
        } else {
            asm volatile("cp.async.wait_group 0;");
        }
        __syncthreads();
        const uint* as = osm + (kc & 1) * 9216;
        const uint* bs = as + 4608;

        #pragma unroll
        for (int c = 0; c < 4; c++) {
            uint a[4];
            a[0] = as[(16*w + g)    *36 + 8*c + tg];
            a[1] = as[(16*w + g + 8)*36 + 8*c + tg];
            a[2] = as[(16*w + g)    *36 + 8*c + tg + 4];
            a[3] = as[(16*w + g + 8)*36 + 8*c + tg + 4];
            #pragma unroll
            for (int j = 0; j < 16; j++) {
                uint b0 = bs[(8*j + g)*36 + 8*c + tg];
                uint b1 = bs[(8*j + g)*36 + 8*c + tg + 4];
                mma_f16(acc[j], a, b0, b1);
            }
        }
        __syncthreads();
    }
    #undef OP_ISSUE

    const int rA = m0 + 16*w + g, rB = rA + 8;
    #pragma unroll
    for (int j = 0; j < 16; j++) {
        *(float2*)&y[(size_t)rA * 1024 + n0 + 8*j + 2*tg] =
            make_float2(acc[j][0], acc[j][1]);
        *(float2*)&y[(size_t)rB * 1024 + n0 + 8*j + 2*tg] =
            make_float2(acc[j][2], acc[j][3]);
    }
}

// ---------------------------------------------------------------------------
extern "C" void kernel_launch(void* const* d_in, const int* in_sizes, int n_in,
                              void* d_out, int out_size)
{
    const float* x    = (const float*)d_in[0];
    const int*   pid  = (const int*)  d_in[1];
    const float* cosT = (const float*)d_in[2];
    const float* sinT = (const float*)d_in[3];
    const float* rq   = (const float*)d_in[4];
    const float* rk   = (const float*)d_in[5];
    const float* rv   = (const float*)d_in[6];
    const float* qw1  = (const float*)d_in[7];
    const float* qw2  = (const float*)d_in[8];
    const float* kw1  = (const float*)d_in[9];
    const float* kw2  = (const float*)d_in[10];
    const float* vw1  = (const float*)d_in[11];
    const float* vw2  = (const float*)d_in[12];
    const float* ow   = (const float*)d_in[13];
    float* y = (float*)d_out;

    cudaFuncSetAttribute(moe_gemm_kernel,
                         cudaFuncAttributeMaxDynamicSharedMemorySize, MOE_SMEM);
    cudaFuncSetAttribute(attn_kernel,
                         cudaFuncAttributeMaxDynamicSharedMemorySize, ATTN_SMEM);
    cudaFuncSetAttribute(outproj_kernel,
                         cudaFuncAttributeMaxDynamicSharedMemorySize, OUT_SMEM);

    zero_cnt_kernel<<<1, 512>>>();
    route_kernel<<<NTOK, 96>>>(x, rq, rk, rv, ow);
    moe_gemm_kernel<<<NUNIT * SPLITS, 512, MOE_SMEM>>>(qw1, qw2, kw1, kw2, vw1, vw2);
    combine_rope_kernel<<<(3 * HH * NTOK) / 32, 256>>>(pid, cosT, sinT);

    attn_kernel<<<512, 256, ATTN_SMEM>>>();

    dim3 g3(CC / 128, (BB * TT) / 128);
    outproj_kernel<<<g3, 256, OUT_SMEM>>>(y);
}

// round 14
// speedup vs baseline: 2.2212x; 1.1429x over previous
#include <cuda_runtime.h>
#include <cuda_fp16.h>
#include <math.h>

#define BB 4
#define TT 1024
#define CC 1024
#define HH 16
#define DD 64
#define EE 8
#define HID 128
#define NTOK (BB*TT)
#define NUNIT (3*HH*EE)
#define SPLITS 3

#define NEG_HUGE (-3.38953139e38f)
#define L2E 1.4426950408889634f

typedef unsigned int uint;

// ---------------- fp16 mma helpers (m16n8k16, fp32 accumulate) ----------------
__device__ __forceinline__ uint f2h2(float lo, float hi) {
    __half2 h = __floats2half2_rn(lo, hi);
    return *(uint*)&h;
}
__device__ __forceinline__ void mma_f16(float c[4], const uint a[4], uint b0, uint b1) {
    asm("mma.sync.aligned.m16n8k16.row.col.f32.f16.f16.f32 "
        "{%0,%1,%2,%3}, {%4,%5,%6,%7}, {%8,%9}, {%0,%1,%2,%3};"
        : "+f"(c[0]), "+f"(c[1]), "+f"(c[2]), "+f"(c[3])
        : "r"(a[0]), "r"(a[1]), "r"(a[2]), "r"(a[3]), "r"(b0), "r"(b1));
}
__device__ __forceinline__ void cpa16(uint dst, const void* src) {
    asm volatile("cp.async.cg.shared.global [%0], [%1], 16;" :: "r"(dst), "l"(src));
}
__device__ __forceinline__ uint ex2h2(float lo, float hi) {
    uint r;
    asm("cvt.rn.f16x2.f32 %0, %1, %2;" : "=r"(r) : "f"(hi), "f"(lo));
    asm("ex2.approx.f16x2 %0, %0;" : "+r"(r));
    return r;
}

// ---------------- device scratch ----------------
__device__ uint g_qh[BB*HH*TT*32];     // [bh][t][d/2] half2 along d, pre-scaled
__device__ uint g_kh[BB*HH*TT*32];
__device__ uint g_vh[BB*HH*512*64];    // [bh][t/2][d]  half2 along t
__device__ uint g_xh[NTOK*512];        // x as half2 along c
__device__ uint g_aoh[(size_t)BB*TT*512];      // [tok][c/2] half2 along c
__device__ uint g_owth[(size_t)CC*512];        // [n][k/2] half2 along k
__device__ uint g_w1th[24*4096];       // [proj*8+e][f][d/2] transposed half2
__device__ uint g_w2th[24*4096];       // [proj*8+e][d][j/2] transposed half2
__device__ unsigned int g_cnt[NUNIT];
__device__ unsigned int g_ent_id[NUNIT*NTOK];
__device__ float        g_ent_wt[NUNIT*NTOK];
__device__ uint g_parth[2ll*3*HH*NTOK*32];     // half2 partials

__device__ __forceinline__ float gelu_tanh(float t) {
    float t3 = t * t * t;
    return t / (1.0f + __expf(-1.5957691216057308f * (t + 0.044715f * t3)));
}

// ---------------------------------------------------------------------------
// Kernel 0: zero counters + convert/transpose expert weights to half2 layouts.
// grid 24 (one block per (proj, e)), 256 threads.
// ---------------------------------------------------------------------------
__global__ void __launch_bounds__(256) prep_kernel(
    const float* __restrict__ qw1, const float* __restrict__ qw2,
    const float* __restrict__ kw1, const float* __restrict__ kw2,
    const float* __restrict__ vw1, const float* __restrict__ vw2)
{
    const int u    = blockIdx.x;      // 0..23
    const int tid  = threadIdx.x;
    const int proj = u >> 3;
    const int e    = u & 7;

    int z = u * 256 + tid;
    if (z < NUNIT) g_cnt[z] = 0u;

    const float* w1 = ((proj == 0) ? qw1 : (proj == 1) ? kw1 : vw1) + (size_t)e * DD * HID;
    const float* w2 = ((proj == 0) ? qw2 : (proj == 1) ? kw2 : vw2) + (size_t)e * HID * DD;
    uint* d1 = g_w1th + u * 4096;
    uint* d2 = g_w2th + u * 4096;

    // w1 [d][f] -> d1[f*32 + d2] = half2(w1[2d2][f], w1[2d2+1][f])
    for (int i = tid; i < 4096; i += 256) {
        int f = i >> 5, dd2 = i & 31;
        d1[i] = f2h2(w1[(2*dd2)*HID + f], w1[(2*dd2 + 1)*HID + f]);
    }
    // w2 [j][d] -> d2[d*64 + j2] = half2(w2[2j2][d], w2[2j2+1][d])
    for (int i = tid; i < 4096; i += 256) {
        int d = i >> 6, j2 = i & 63;
        d2[i] = f2h2(w2[(2*j2)*DD + d], w2[(2*j2 + 1)*DD + d]);
    }
}

// ---------------------------------------------------------------------------
// Kernel 1: routing + ow/x fp16 pre-conversion. 4 tokens per block.
// ---------------------------------------------------------------------------
__global__ void __launch_bounds__(96) route_kernel(
    const float* __restrict__ x,
    const float* __restrict__ rq, const float* __restrict__ rk,
    const float* __restrict__ rv, const float* __restrict__ ow)
{
    const int tk0  = blockIdx.x * 4;
    const int tid  = threadIdx.x;
    const int w    = tid >> 5;
    const int lane = tid & 31;
    const int e    = lane & 7;
    const int hq   = lane >> 3;

    __shared__ float xs[4*CC];
    __shared__ float rs[3][DD*EE];

    for (int i = tid; i < 512; i += 96) {
        int idx = blockIdx.x * 512 + i;
        float2 v = ((const float2*)ow)[idx];
        g_owth[idx] = f2h2(v.x, v.y);
    }

    for (int i = tid; i < CC; i += 96)    // 4*CC/4 float4
        ((float4*)xs)[i] = ((const float4*)(x + (size_t)tk0 * CC))[i];
    for (int i = tid; i < DD*EE; i += 96) {
        rs[0][i] = rq[i]; rs[1][i] = rk[i]; rs[2][i] = rv[i];
    }
    __syncthreads();

    for (int i = tid; i < 2048; i += 96)
        g_xh[(size_t)tk0 * 512 + i] = f2h2(xs[2*i], xs[2*i + 1]);

    const float* rw = rs[w];
    for (int tt = 0; tt < 4; tt++) {
        const int tk = tk0 + tt;
        const float* xrow = xs + tt * CC;
        for (int hb = 0; hb < 4; hb++) {
            int h = hb * 4 + hq;
            float acc = 0.0f;
            #pragma unroll 16
            for (int d = 0; d < DD; d++) acc += xrow[h*DD + d] * rw[d*EE + e];

            float m1 = NEG_HUGE, m2 = NEG_HUGE;
            int   i1 = 0, i2 = 0;
            #pragma unroll
            for (int ee = 0; ee < EE; ee++) {
                float v = __shfl_sync(0xffffffffu, acc, hq*8 + ee);
                if (v > m1)      { m2 = m1; i2 = i1; m1 = v; i1 = ee; }
                else if (v > m2) { m2 = v;  i2 = ee; }
            }
            if (e == 0) {
                float dex = expf(m2 - m1);
                float wt1 = 1.0f / (1.0f + dex);
                float wt2 = dex * wt1;
                int base = (w * HH + h) * EE;
                unsigned int p1 = atomicAdd(&g_cnt[base + i1], 1u);
                g_ent_id[(size_t)(base + i1) * NTOK + p1] = (unsigned int)tk;
                g_ent_wt[(size_t)(base + i1) * NTOK + p1] = wt1;
                unsigned int p2 = atomicAdd(&g_cnt[base + i2], 1u);
                g_ent_id[(size_t)(base + i2) * NTOK + p2] = (unsigned int)tk | 0x80000000u;
                g_ent_wt[(size_t)(base + i2) * NTOK + p2] = wt2;
            }
        }
    }
}

// ---------------------------------------------------------------------------
// Kernel 2: expert-grouped MoE GEMM, fp16 mma; weights cp.async'd from
// pre-transposed half2 arrays (prologue: 4 cpa16 per thread).
// ---------------------------------------------------------------------------
#define MOE_SMEM (22272 * 4)

__global__ void __launch_bounds__(512) moe_gemm_kernel()
{
    const int gid  = blockIdx.x;
    const int unit = gid / SPLITS;
    const int s    = gid % SPLITS;
    const int proj = unit >> 7;
    const int h    = (unit >> 3) & 15;
    const int e    = unit & 7;
    const int u24  = proj * 8 + e;

    extern __shared__ uint smu[];
    uint* w1t = smu;                    // [128 f][36]
    uint* w2t = smu + 128*36;           // [64 d][68]
    uint* hsm = w2t + 64*68;            // [128 tok][68]
    uint* xsm = hsm + 128*68;           // [128 tok][36]

    const int tid  = threadIdx.x;
    const int w    = tid >> 5;
    const int lane = tid & 31;
    const int g    = lane >> 2;
    const int tg   = lane & 3;
    const int wm   = w & 7;
    const int wn   = w >> 3;
    const int myTok = tid >> 2;
    const int part  = tid & 3;

    const int nt = (int)g_cnt[unit];
    const size_t ent_base = (size_t)unit * NTOK;

    int base = s * 128;
    if (base >= nt) return;

    // prologue: cp.async pre-transposed weights into smem
    const uint sbase = (uint)__cvta_generic_to_shared(smu);
    {
        const uint* w1g = g_w1th + u24 * 4096;
        const uint* w2g = g_w2th + u24 * 4096;
        #pragma unroll
        for (int it = 0; it < 2; it++) {
            int idx = tid + it * 512;
            int row = idx >> 3, c4 = (idx & 7) * 4;          // w1: 128 rows x 32
            cpa16(sbase + (row*36 + c4)*4, &w1g[row*32 + c4]);
            int row2 = idx >> 4, c42 = (idx & 15) * 4;       // w2: 64 rows x 64
            cpa16(sbase + (128*36 + row2*68 + c42)*4, &w2g[row2*64 + c42]);
        }
        asm volatile("cp.async.commit_group;");
    }

    uint xg[8];
    {
        uint idg = 0xFFFFFFFFu;
        int idx = base + myTok;
        if (idx < nt) idg = g_ent_id[ent_base + idx];
        #pragma unroll
        for (int q = 0; q < 8; q++) xg[q] = 0u;
        if (idg != 0xFFFFFFFFu) {
            const uint4* src = (const uint4*)(g_xh + (size_t)(idg & 0x7FFFFFFFu) * 512 + h * 32 + part * 8);
            uint4 v0 = src[0], v1 = src[1];
            xg[0]=v0.x; xg[1]=v0.y; xg[2]=v0.z; xg[3]=v0.w;
            xg[4]=v1.x; xg[5]=v1.y; xg[6]=v1.z; xg[7]=v1.w;
        }
    }
    asm volatile("cp.async.wait_group 0;");

    const int tokA = 16*wm + g, tokB = tokA + 8;

    for (int b2 = base; ; b2 += SPLITS * 128) {
        {
            uint* dst = xsm + myTok * 36 + part * 8;
            #pragma unroll
            for (int q = 0; q < 8; q++) dst[q] = xg[q];
        }

        uint idA = 0xFFFFFFFFu, idB = 0xFFFFFFFFu;
        float wtA = 0.0f, wtB = 0.0f;
        if (b2 + tokA < nt) {
            idA = g_ent_id[ent_base + b2 + tokA];
            wtA = g_ent_wt[ent_base + b2 + tokA];
        }
        if (b2 + tokB < nt) {
            idB = g_ent_id[ent_base + b2 + tokB];
            wtB = g_ent_wt[ent_base + b2 + tokB];
        }

        const int bn = b2 + SPLITS * 128;
        const bool has_next = bn < nt;
        uint idgn = 0xFFFFFFFFu;
        if (has_next && bn + myTok < nt) idgn = g_ent_id[ent_base + bn + myTok];

        __syncthreads();

        float c1[8][4];
        #pragma unroll
        for (int j = 0; j < 8; j++)
            #pragma unroll
            for (int r = 0; r < 4; r++) c1[j][r] = 0.0f;

        #pragma unroll
        for (int c = 0; c < 4; c++) {
            uint a[4];
            a[0] = xsm[(16*wm + g)    *36 + 8*c + tg];
            a[1] = xsm[(16*wm + g + 8)*36 + 8*c + tg];
            a[2] = xsm[(16*wm + g)    *36 + 8*c + tg + 4];
            a[3] = xsm[(16*wm + g + 8)*36 + 8*c + tg + 4];
            #pragma unroll
            for (int j = 0; j < 8; j++) {
                uint b0 = w1t[(64*wn + 8*j + g)*36 + 8*c + tg];
                uint b1 = w1t[(64*wn + 8*j + g)*36 + 8*c + tg + 4];
                mma_f16(c1[j], a, b0, b1);
            }
        }
        #pragma unroll
        for (int j = 0; j < 8; j++) {
            int col2 = 32*wn + 4*j + tg;
            hsm[(16*wm + g)    *68 + col2] = f2h2(gelu_tanh(c1[j][0]), gelu_tanh(c1[j][1]));
            hsm[(16*wm + g + 8)*68 + col2] = f2h2(gelu_tanh(c1[j][2]), gelu_tanh(c1[j][3]));
        }

        #pragma unroll
        for (int q = 0; q < 8; q++) xg[q] = 0u;
        if (idgn != 0xFFFFFFFFu) {
            const uint4* src = (const uint4*)(g_xh + (size_t)(idgn & 0x7FFFFFFFu) * 512 + h * 32 + part * 8);
            uint4 v0 = src[0], v1 = src[1];
            xg[0]=v0.x; xg[1]=v0.y; xg[2]=v0.z; xg[3]=v0.w;
            xg[4]=v1.x; xg[5]=v1.y; xg[6]=v1.z; xg[7]=v1.w;
        }

        __syncthreads();

        float c2[4][4];
        #pragma unroll
        for (int j = 0; j < 4; j++)
            #pragma unroll
            for (int r = 0; r < 4; r++) c2[j][r] = 0.0f;

        #pragma unroll
        for (int c = 0; c < 8; c++) {
            uint a[4];
            a[0] = hsm[(16*wm + g)    *68 + 8*c + tg];
            a[1] = hsm[(16*wm + g + 8)*68 + 8*c + tg];
            a[2] = hsm[(16*wm + g)    *68 + 8*c + tg + 4];
            a[3] = hsm[(16*wm + g + 8)*68 + 8*c + tg + 4];
            #pragma unroll
            for (int j = 0; j < 4; j++) {
                uint b0 = w2t[(32*wn + 8*j + g)*68 + 8*c + tg];
                uint b1 = w2t[(32*wn + 8*j + g)*68 + 8*c + tg + 4];
                mma_f16(c2[j], a, b0, b1);
            }
        }

        if (idA != 0xFFFFFFFFu) {
            unsigned int slot = idA >> 31, tkk = idA & 0x7FFFFFFFu;
            uint* dst = g_parth + ((((size_t)slot*3 + proj)*HH + h)*NTOK + tkk)*32;
            #pragma unroll
            for (int j = 0; j < 4; j++)
                dst[16*wn + 4*j + tg] = f2h2(wtA*c2[j][0], wtA*c2[j][1]);
        }
        if (idB != 0xFFFFFFFFu) {
            unsigned int slot = idB >> 31, tkk = idB & 0x7FFFFFFFu;
            uint* dst = g_parth + ((((size_t)slot*3 + proj)*HH + h)*NTOK + tkk)*32;
            #pragma unroll
            for (int j = 0; j < 4; j++)
                dst[16*wn + 4*j + tg] = f2h2(wtB*c2[j][2], wtB*c2[j][3]);
        }

        if (!has_next) break;
    }
}

// ---------------------------------------------------------------------------
// Kernel 3: combine slots + RoPE; 4 rows per warp (unchanged from R13).
// ---------------------------------------------------------------------------
__global__ void __launch_bounds__(256) combine_rope_kernel(
    const int* __restrict__ pos_ids,
    const float* __restrict__ cosT, const float* __restrict__ sinT)
{
    const int warp = threadIdx.x >> 5;
    const int lane = threadIdx.x & 31;
    const int row0 = (blockIdx.x * 8 + warp) * 4;
    const size_t SLOT2 = (size_t)3 * HH * NTOK * 32;

    #pragma unroll
    for (int r = 0; r < 4; r++) {
        const int row  = row0 + r;
        const int proj = row / (HH * NTOK);
        const int rest = row % (HH * NTOK);
        const int h  = rest / NTOK;
        const int tk = rest % NTOK;

        const size_t pbase = (size_t)row * 32;
        float2 v1 = __half22float2(*(const __half2*)&g_parth[pbase + lane]);
        float2 v2 = __half22float2(*(const __half2*)&g_parth[pbase + SLOT2 + lane]);
        float a0 = v1.x + v2.x;
        float a1 = v1.y + v2.y;

        if (proj < 2) {
            int p = pos_ids[tk];
            float2 c = *(const float2*)&cosT[p*DD + 2*lane];
            float2 s = *(const float2*)&sinT[p*DD + 2*lane];
            float o0 = __shfl_xor_sync(0xffffffffu, a0, 16);
            float o1 = __shfl_xor_sync(0xffffffffu, a1, 16);
            float rot0 = (lane < 16) ? -o0 : o0;
            float rot1 = (lane < 16) ? -o1 : o1;
            a0 = a0 * c.x + rot0 * s.x;
            a1 = a1 * c.y + rot1 * s.y;
        }
        if (proj == 0) { a0 *= 0.125f; a1 *= 0.125f; }

        int b = tk >> 10, t = tk & 1023;
        int bh = b * HH + h;
        if (proj == 2) {
            size_t base = ((size_t)bh * 512 + (t >> 1)) * 64;
            half* vh = (half*)g_vh;
            vh[(base + 2*lane)     * 2 + (t & 1)] = __float2half(a0);
            vh[(base + 2*lane + 1) * 2 + (t & 1)] = __float2half(a1);
        } else {
            uint hv = f2h2(a0, a1);
            uint* outg = (proj == 0) ? g_qh : g_kh;
            outg[((size_t)bh * TT + t) * 32 + lane] = hv;
        }
    }
}

// ---------------------------------------------------------------------------
// Kernel 4: causal flash attention, fp16 mma (unchanged from R13).
// ---------------------------------------------------------------------------
#define ATTN_SMEM (18432 * 4)

__global__ void __launch_bounds__(256, 2) attn_kernel()
{
    extern __shared__ uint smu[];
    uint* psm = smu + 13824;

    const int wid = blockIdx.x;
    const int qtb = 7 - (wid >> 6);
    const int bh  = wid & 63;
    const int tid  = threadIdx.x;
    const int w    = tid >> 5;
    const int lane = tid & 31;
    const int g    = lane >> 2;
    const int tg   = lane & 3;

    const uint* qg = g_qh + (size_t)bh * TT * 32;
    const uint* kg = g_kh + (size_t)bh * TT * 32;
    const uint* vg = g_vh + (size_t)bh * 512 * 64;
    const int q0 = qtb * 128;
    const uint sbase = (uint)__cvta_generic_to_shared(smu);

    for (int i = tid; i < 768; i += 256) {
        int buf = i >> 8, rc = i & 255;
        int row = rc >> 3, c = rc & 7;
        smu[6912 + buf*2304 + row*72 + 64 + c] = (c == 0) ? 0x3C003C00u : 0u;
    }

    #pragma unroll
    for (int it = 0; it < 4; it++) {
        int idx = tid + it * 256;
        int row = idx >> 3, c4 = (idx & 7) * 4;
        *(uint4*)&psm[row*36 + c4] = *(const uint4*)&qg[(size_t)(q0 + row)*32 + c4];
    }
    __syncthreads();
    uint qa[4][4];
    {
        int rA = 16*w + g;
        #pragma unroll
        for (int c = 0; c < 4; c++) {
            qa[c][0] = psm[rA*36     + 8*c + tg];
            qa[c][1] = psm[(rA+8)*36 + 8*c + tg];
            qa[c][2] = psm[rA*36     + 8*c + tg + 4];
            qa[c][3] = psm[(rA+8)*36 + 8*c + tg + 4];
        }
    }

    float oa[9][4];
    #pragma unroll
    for (int j = 0; j < 9; j++)
        #pragma unroll
        for (int r = 0; r < 4; r++) oa[j][r] = 0.0f;
    float mA = -1e30f, mB = -1e30f;

    const int ktmax = 2*qtb + 1;

    #define ISSUE_TILE(kt_) do {                                              \
        int k0_ = (kt_) * 64;                                                 \
        int buf_ = (kt_) % 3;                                                 \
        uint kb_ = sbase + (buf_ * 2304) * 4;                                 \
        uint vb_ = sbase + ((6912 + buf_ * 2304)) * 4;                        \
        _Pragma("unroll")                                                     \
        for (int it_ = 0; it_ < 2; it_++) {                                   \
            int idx_ = tid + it_ * 256;                                       \
            int krow_ = idx_ >> 3, kc4_ = (idx_ & 7) * 4;                     \
            cpa16(kb_ + (krow_*36 + kc4_)*4,                                  \
                  &kg[(size_t)(k0_ + krow_)*32 + kc4_]);                      \
            int vrow_ = idx_ >> 4, vc4_ = (idx_ & 15) * 4;                    \
            cpa16(vb_ + (vrow_*72 + vc4_)*4,                                  \
                  &vg[(size_t)(k0_/2 + vrow_)*64 + vc4_]);                    \
        }                                                                     \
        asm volatile("cp.async.commit_group;");                               \
    } while (0)

    ISSUE_TILE(0);
    ISSUE_TILE(1);

    for (int kt = 0; kt <= ktmax; kt++) {
        if (kt < ktmax) {
            asm volatile("cp.async.wait_group 1;");
        } else {
            asm volatile("cp.async.wait_group 0;");
        }
        __syncthreads();
        if (kt + 2 <= ktmax) ISSUE_TILE(kt + 2);

        const uint* ksm = smu + (kt % 3) * 2304;
        const uint* vsm = smu + 6912 + (kt % 3) * 2304;
        const int k0 = kt * 64;

        float sc[8][4];
        #pragma unroll
        for (int j = 0; j < 8; j++)
            #pragma unroll
            for (int r = 0; r < 4; r++) sc[j][r] = 0.0f;

        #pragma unroll
        for (int c = 0; c < 4; c++) {
            #pragma unroll
            for (int j = 0; j < 8; j++) {
                uint b0 = ksm[(8*j + g)*36 + 8*c + tg];
                uint b1 = ksm[(8*j + g)*36 + 8*c + tg + 4];
                mma_f16(sc[j], qa[c], b0, b1);
            }
        }

        if (kt >= ktmax - 1) {
            const int rA = q0 + 16*w + g, rB = rA + 8;
            #pragma unroll
            for (int j = 0; j < 8; j++) {
                int col = k0 + 8*j + 2*tg;
                if (col     > rA) sc[j][0] = -1e30f;
                if (col + 1 > rA) sc[j][1] = -1e30f;
                if (col     > rB) sc[j][2] = -1e30f;
                if (col + 1 > rB) sc[j][3] = -1e30f;
            }
        }

        float mtA = -1e30f, mtB = -1e30f;
        #pragma unroll
        for (int j = 0; j < 8; j++) {
            mtA = fmaxf(mtA, fmaxf(sc[j][0], sc[j][1]));
            mtB = fmaxf(mtB, fmaxf(sc[j][2], sc[j][3]));
        }
        mtA = fmaxf(mtA, __shfl_xor_sync(0xffffffffu, mtA, 1));
        mtA = fmaxf(mtA, __shfl_xor_sync(0xffffffffu, mtA, 2));
        mtB = fmaxf(mtB, __shfl_xor_sync(0xffffffffu, mtB, 1));
        mtB = fmaxf(mtB, __shfl_xor_sync(0xffffffffu, mtB, 2));

        float mnA = fmaxf(mA, mtA), mnB = fmaxf(mB, mtB);
        float aA = __expf(mA - mnA), aB = __expf(mB - mnB);
        mA = mnA; mB = mnB;

        #pragma unroll
        for (int j = 0; j < 9; j++) {
            oa[j][0] *= aA; oa[j][1] *= aA;
            oa[j][2] *= aB; oa[j][3] *= aB;
        }

        float nAL = -mnA * L2E, nBL = -mnB * L2E;
        #pragma unroll
        for (int j = 0; j < 8; j++) {
            float t0 = fmaf(sc[j][0], L2E, nAL);
            float t1 = fmaf(sc[j][1], L2E, nAL);
            float t2 = fmaf(sc[j][2], L2E, nBL);
            float t3 = fmaf(sc[j][3], L2E, nBL);
            sc[j][0] = __uint_as_float(ex2h2(t0, t1));
            sc[j][1] = __uint_as_float(ex2h2(t2, t3));
        }

        #pragma unroll
        for (int c = 0; c < 4; c++) {
            uint a[4];
            a[0] = __float_as_uint(sc[2*c][0]);
            a[1] = __float_as_uint(sc[2*c][1]);
            a[2] = __float_as_uint(sc[2*c + 1][0]);
            a[3] = __float_as_uint(sc[2*c + 1][1]);
            #pragma unroll
            for (int jd = 0; jd < 9; jd++) {
                uint b0 = vsm[(8*c + tg)*72     + 8*jd + g];
                uint b1 = vsm[(8*c + tg + 4)*72 + 8*jd + g];
                mma_f16(oa[jd], a, b0, b1);
            }
        }
    }
    #undef ISSUE_TILE

    float lA = __shfl_sync(0xffffffffu, oa[8][0], lane & 28);
    float lB = __shfl_sync(0xffffffffu, oa[8][2], lane & 28);
    const int b = bh / HH, h = bh % HH;
    float invA = 1.0f / lA, invB = 1.0f / lB;
    const int rA = q0 + 16*w + g, rB = rA + 8;
    #pragma unroll
    for (int jd = 0; jd < 8; jd++) {
        g_aoh[((size_t)(b * TT) + rA) * 512 + h * 32 + 4*jd + tg] =
            f2h2(oa[jd][0] * invA, oa[jd][1] * invA);
        g_aoh[((size_t)(b * TT) + rB) * 512 + h * 32 + 4*jd + tg] =
            f2h2(oa[jd][2] * invB, oa[jd][3] * invB);
    }
}

// ---------------------------------------------------------------------------
// Kernel 5: y = ao @ ow^T, fp16 mma, BM=128, BN=128, BK=64 (unchanged).
// ---------------------------------------------------------------------------
#define OUT_SMEM (18432 * 4)

__global__ void __launch_bounds__(256, 2) outproj_kernel(float* __restrict__ y)
{
    extern __shared__ uint osm[];

    const int tid  = threadIdx.x;
    const int w    = tid >> 5;
    const int lane = tid & 31;
    const int g    = lane >> 2;
    const int tg   = lane & 3;
    const int n0 = blockIdx.x * 128;
    const int m0 = blockIdx.y * 128;
    const uint sbase = (uint)__cvta_generic_to_shared(osm);

    float acc[16][4];
    #pragma unroll
    for (int j = 0; j < 16; j++)
        #pragma unroll
        for (int r = 0; r < 4; r++) acc[j][r] = 0.0f;

    #define OP_ISSUE(kc_, buf_) do {                                          \
        uint ab_ = sbase + (buf_) * 9216 * 4;                                 \
        uint bb_ = ab_ + 4608 * 4;                                            \
        _Pragma("unroll")                                                     \
        for (int it_ = 0; it_ < 4; it_++) {                                   \
            int idx_ = tid + it_ * 256;                                       \
            int row_ = idx_ >> 3, c4_ = (idx_ & 7) * 4;                       \
            cpa16(ab_ + (row_*36 + c4_)*4,                                    \
                  &g_aoh[(size_t)(m0 + row_) * 512 + (kc_)*32 + c4_]);        \
            cpa16(bb_ + (row_*36 + c4_)*4,                                    \
                  &g_owth[(size_t)(n0 + row_) * 512 + (kc_)*32 + c4_]);       \
        }                                                                     \
        asm volatile("cp.async.commit_group;");                               \
    } while (0)

    OP_ISSUE(0, 0);

    for (int kc = 0; kc < 16; kc++) {
        if (kc < 15) {
            OP_ISSUE(kc + 1, (kc + 1) & 1);
            asm volatile("cp.async.wait_group 1;");
        } else {
            asm volatile("cp.async.wait_group 0;");
        }
        __syncthreads();
        const uint* as = osm + (kc & 1) * 9216;
        const uint* bs = as + 4608;

        #pragma unroll
        for (int c = 0; c < 4; c++) {
            uint a[4];
            a[0] = as[(16*w + g)    *36 + 8*c + tg];
            a[1] = as[(16*w + g + 8)*36 + 8*c + tg];
            a[2] = as[(16*w + g)    *36 + 8*c + tg + 4];
            a[3] = as[(16*w + g + 8)*36 + 8*c + tg + 4];
            #pragma unroll
            for (int j = 0; j < 16; j++) {
                uint b0 = bs[(8*j + g)*36 + 8*c + tg];
                uint b1 = bs[(8*j + g)*36 + 8*c + tg + 4];
                mma_f16(acc[j], a, b0, b1);
            }
        }
        __syncthreads();
    }
    #undef OP_ISSUE

    const int rA = m0 + 16*w + g, rB = rA + 8;
    #pragma unroll
    for (int j = 0; j < 16; j++) {
        *(float2*)&y[(size_t)rA * 1024 + n0 + 8*j + 2*tg] =
            make_float2(acc[j][0], acc[j][1]);
        *(float2*)&y[(size_t)rB * 1024 + n0 + 8*j + 2*tg] =
            make_float2(acc[j][2], acc[j][3]);
    }
}

// ---------------------------------------------------------------------------
extern "C" void kernel_launch(void* const* d_in, const int* in_sizes, int n_in,
                              void* d_out, int out_size)
{
    const float* x    = (const float*)d_in[0];
    const int*   pid  = (const int*)  d_in[1];
    const float* cosT = (const float*)d_in[2];
    const float* sinT = (const float*)d_in[3];
    const float* rq   = (const float*)d_in[4];
    const float* rk   = (const float*)d_in[5];
    const float* rv   = (const float*)d_in[6];
    const float* qw1  = (const float*)d_in[7];
    const float* qw2  = (const float*)d_in[8];
    const float* kw1  = (const float*)d_in[9];
    const float* kw2  = (const float*)d_in[10];
    const float* vw1  = (const float*)d_in[11];
    const float* vw2  = (const float*)d_in[12];
    const float* ow   = (const float*)d_in[13];
    float* y = (float*)d_out;

    cudaFuncSetAttribute(moe_gemm_kernel,
                         cudaFuncAttributeMaxDynamicSharedMemorySize, MOE_SMEM);
    cudaFuncSetAttribute(attn_kernel,
                         cudaFuncAttributeMaxDynamicSharedMemorySize, ATTN_SMEM);
    cudaFuncSetAttribute(outproj_kernel,
                         cudaFuncAttributeMaxDynamicSharedMemorySize, OUT_SMEM);

    prep_kernel<<<24, 256>>>(qw1, qw2, kw1, kw2, vw1, vw2);
    route_kernel<<<NTOK / 4, 96>>>(x, rq, rk, rv, ow);
    moe_gemm_kernel<<<NUNIT * SPLITS, 512, MOE_SMEM>>>();
    combine_rope_kernel<<<(3 * HH * NTOK) / 32, 256>>>(pid, cosT, sinT);

    attn_kernel<<<512, 256, ATTN_SMEM>>>();

    dim3 g3(CC / 128, (BB * TT) / 128);
    outproj_kernel<<<g3, 256, OUT_SMEM>>>(y);
}

// round 15
// speedup vs baseline: 2.3223x; 1.0455x over previous
#include <cuda_runtime.h>
#include <cuda_fp16.h>
#include <math.h>

#define BB 4
#define TT 1024
#define CC 1024
#define HH 16
#define DD 64
#define EE 8
#define HID 128
#define NTOK (BB*TT)
#define NUNIT (3*HH*EE)
#define SPLITS 3

#define NEG_HUGE (-3.38953139e38f)
#define L2E 1.4426950408889634f

typedef unsigned int uint;

// ---------------- fp16 mma helpers (m16n8k16, fp32 accumulate) ----------------
__device__ __forceinline__ uint f2h2(float lo, float hi) {
    __half2 h = __floats2half2_rn(lo, hi);
    return *(uint*)&h;
}
__device__ __forceinline__ void mma_f16(float c[4], const uint a[4], uint b0, uint b1) {
    asm("mma.sync.aligned.m16n8k16.row.col.f32.f16.f16.f32 "
        "{%0,%1,%2,%3}, {%4,%5,%6,%7}, {%8,%9}, {%0,%1,%2,%3};"
        : "+f"(c[0]), "+f"(c[1]), "+f"(c[2]), "+f"(c[3])
        : "r"(a[0]), "r"(a[1]), "r"(a[2]), "r"(a[3]), "r"(b0), "r"(b1));
}
__device__ __forceinline__ void cpa16(uint dst, const void* src) {
    asm volatile("cp.async.cg.shared.global [%0], [%1], 16;" :: "r"(dst), "l"(src));
}
__device__ __forceinline__ uint ex2h2(float lo, float hi) {
    uint r;
    asm("cvt.rn.f16x2.f32 %0, %1, %2;" : "=r"(r) : "f"(hi), "f"(lo));
    asm("ex2.approx.f16x2 %0, %0;" : "+r"(r));
    return r;
}

// ---------------- device scratch ----------------
__device__ uint g_qh[BB*HH*TT*32];     // [bh][t][d/2] half2 along d, pre-scaled
__device__ uint g_kh[BB*HH*TT*32];
__device__ uint g_vh[BB*HH*512*64];    // [bh][t/2][d]  half2 along t
__device__ uint g_xh[NTOK*512];        // x as half2 along c
__device__ uint g_aoh[(size_t)BB*TT*512];      // [tok][c/2] half2 along c
__device__ uint g_owth[(size_t)CC*512];        // [n][k/2] half2 along k
__device__ uint g_w1th[24*4096];       // [proj*8+e][f][d/2] transposed half2
__device__ uint g_w2th[24*4096];       // [proj*8+e][d][j/2] transposed half2
__device__ unsigned int g_cnt[NUNIT];  // zero-init statically; re-zeroed by combine
__device__ unsigned int g_ent_id[NUNIT*NTOK];
__device__ float        g_ent_wt[NUNIT*NTOK];
__device__ uint g_parth[2ll*3*HH*NTOK*32];     // half2 partials

__device__ __forceinline__ float gelu_tanh(float t) {
    float t3 = t * t * t;
    return t / (1.0f + __expf(-1.5957691216057308f * (t + 0.044715f * t3)));
}

// ---------------------------------------------------------------------------
// Kernel 1: routing + ow/x fp16 pre-conversion + (blocks 0..23) weight prep.
// g_cnt is zeroed by the PREVIOUS execution's combine kernel (static init on
// the first run), so no separate zero kernel is needed.
// ---------------------------------------------------------------------------
__global__ void __launch_bounds__(96) route_kernel(
    const float* __restrict__ x,
    const float* __restrict__ rq, const float* __restrict__ rk,
    const float* __restrict__ rv, const float* __restrict__ ow,
    const float* __restrict__ qw1, const float* __restrict__ qw2,
    const float* __restrict__ kw1, const float* __restrict__ kw2,
    const float* __restrict__ vw1, const float* __restrict__ vw2)
{
    const int tk0  = blockIdx.x * 4;
    const int tid  = threadIdx.x;
    const int w    = tid >> 5;
    const int lane = tid & 31;
    const int e    = lane & 7;
    const int hq   = lane >> 3;

    __shared__ float xs[4*CC];
    __shared__ float rs[3][DD*EE];

    for (int i = tid; i < 512; i += 96) {
        int idx = blockIdx.x * 512 + i;
        float2 v = ((const float2*)ow)[idx];
        g_owth[idx] = f2h2(v.x, v.y);
    }

    for (int i = tid; i < CC; i += 96)
        ((float4*)xs)[i] = ((const float4*)(x + (size_t)tk0 * CC))[i];
    for (int i = tid; i < DD*EE; i += 96) {
        rs[0][i] = rq[i]; rs[1][i] = rk[i]; rs[2][i] = rv[i];
    }
    __syncthreads();

    for (int i = tid; i < 2048; i += 96)
        g_xh[(size_t)tk0 * 512 + i] = f2h2(xs[2*i], xs[2*i + 1]);

    const float* rw = rs[w];
    for (int tt = 0; tt < 4; tt++) {
        const int tk = tk0 + tt;
        const float* xrow = xs + tt * CC;
        for (int hb = 0; hb < 4; hb++) {
            int h = hb * 4 + hq;
            float acc = 0.0f;
            #pragma unroll 16
            for (int d = 0; d < DD; d++) acc += xrow[h*DD + d] * rw[d*EE + e];

            float m1 = NEG_HUGE, m2 = NEG_HUGE;
            int   i1 = 0, i2 = 0;
            #pragma unroll
            for (int ee = 0; ee < EE; ee++) {
                float v = __shfl_sync(0xffffffffu, acc, hq*8 + ee);
                if (v > m1)      { m2 = m1; i2 = i1; m1 = v; i1 = ee; }
                else if (v > m2) { m2 = v;  i2 = ee; }
            }
            if (e == 0) {
                float dex = expf(m2 - m1);
                float wt1 = 1.0f / (1.0f + dex);
                float wt2 = dex * wt1;
                int base = (w * HH + h) * EE;
                unsigned int p1 = atomicAdd(&g_cnt[base + i1], 1u);
                g_ent_id[(size_t)(base + i1) * NTOK + p1] = (unsigned int)tk;
                g_ent_wt[(size_t)(base + i1) * NTOK + p1] = wt1;
                unsigned int p2 = atomicAdd(&g_cnt[base + i2], 1u);
                g_ent_id[(size_t)(base + i2) * NTOK + p2] = (unsigned int)tk | 0x80000000u;
                g_ent_wt[(size_t)(base + i2) * NTOK + p2] = wt2;
            }
        }
    }

    // blocks 0..23: convert/transpose one expert's weights to half2 layouts
    if (blockIdx.x < 24) {
        const int u    = blockIdx.x;
        const int proj = u >> 3;
        const int ee   = u & 7;
        const float* w1 = ((proj == 0) ? qw1 : (proj == 1) ? kw1 : vw1) + (size_t)ee * DD * HID;
        const float* w2 = ((proj == 0) ? qw2 : (proj == 1) ? kw2 : vw2) + (size_t)ee * HID * DD;
        uint* d1 = g_w1th + u * 4096;
        uint* d2 = g_w2th + u * 4096;
        for (int i = tid; i < 4096; i += 96) {
            int f = i >> 5, dd2 = i & 31;
            d1[i] = f2h2(w1[(2*dd2)*HID + f], w1[(2*dd2 + 1)*HID + f]);
        }
        for (int i = tid; i < 4096; i += 96) {
            int d = i >> 6, j2 = i & 63;
            d2[i] = f2h2(w2[(2*j2)*DD + d], w2[(2*j2 + 1)*DD + d]);
        }
    }
}

// ---------------------------------------------------------------------------
// Kernel 2: expert-grouped MoE GEMM, fp16 mma (unchanged from R14).
// ---------------------------------------------------------------------------
#define MOE_SMEM (22272 * 4)

__global__ void __launch_bounds__(512) moe_gemm_kernel()
{
    const int gid  = blockIdx.x;
    const int unit = gid / SPLITS;
    const int s    = gid % SPLITS;
    const int proj = unit >> 7;
    const int h    = (unit >> 3) & 15;
    const int e    = unit & 7;
    const int u24  = proj * 8 + e;

    extern __shared__ uint smu[];
    uint* w1t = smu;                    // [128 f][36]
    uint* w2t = smu + 128*36;           // [64 d][68]
    uint* hsm = w2t + 64*68;            // [128 tok][68]
    uint* xsm = hsm + 128*68;           // [128 tok][36]

    const int tid  = threadIdx.x;
    const int w    = tid >> 5;
    const int lane = tid & 31;
    const int g    = lane >> 2;
    const int tg   = lane & 3;
    const int wm   = w & 7;
    const int wn   = w >> 3;
    const int myTok = tid >> 2;
    const int part  = tid & 3;

    const int nt = (int)g_cnt[unit];
    const size_t ent_base = (size_t)unit * NTOK;

    int base = s * 128;
    if (base >= nt) return;

    const uint sbase = (uint)__cvta_generic_to_shared(smu);
    {
        const uint* w1g = g_w1th + u24 * 4096;
        const uint* w2g = g_w2th + u24 * 4096;
        #pragma unroll
        for (int it = 0; it < 2; it++) {
            int idx = tid + it * 512;
            int row = idx >> 3, c4 = (idx & 7) * 4;
            cpa16(sbase + (row*36 + c4)*4, &w1g[row*32 + c4]);
            int row2 = idx >> 4, c42 = (idx & 15) * 4;
            cpa16(sbase + (128*36 + row2*68 + c42)*4, &w2g[row2*64 + c42]);
        }
        asm volatile("cp.async.commit_group;");
    }

    uint xg[8];
    {
        uint idg = 0xFFFFFFFFu;
        int idx = base + myTok;
        if (idx < nt) idg = g_ent_id[ent_base + idx];
        #pragma unroll
        for (int q = 0; q < 8; q++) xg[q] = 0u;
        if (idg != 0xFFFFFFFFu) {
            const uint4* src = (const uint4*)(g_xh + (size_t)(idg & 0x7FFFFFFFu) * 512 + h * 32 + part * 8);
            uint4 v0 = src[0], v1 = src[1];
            xg[0]=v0.x; xg[1]=v0.y; xg[2]=v0.z; xg[3]=v0.w;
            xg[4]=v1.x; xg[5]=v1.y; xg[6]=v1.z; xg[7]=v1.w;
        }
    }
    asm volatile("cp.async.wait_group 0;");

    const int tokA = 16*wm + g, tokB = tokA + 8;

    for (int b2 = base; ; b2 += SPLITS * 128) {
        {
            uint* dst = xsm + myTok * 36 + part * 8;
            #pragma unroll
            for (int q = 0; q < 8; q++) dst[q] = xg[q];
        }

        uint idA = 0xFFFFFFFFu, idB = 0xFFFFFFFFu;
        float wtA = 0.0f, wtB = 0.0f;
        if (b2 + tokA < nt) {
            idA = g_ent_id[ent_base + b2 + tokA];
            wtA = g_ent_wt[ent_base + b2 + tokA];
        }
        if (b2 + tokB < nt) {
            idB = g_ent_id[ent_base + b2 + tokB];
            wtB = g_ent_wt[ent_base + b2 + tokB];
        }

        const int bn = b2 + SPLITS * 128;
        const bool has_next = bn < nt;
        uint idgn = 0xFFFFFFFFu;
        if (has_next && bn + myTok < nt) idgn = g_ent_id[ent_base + bn + myTok];

        __syncthreads();

        float c1[8][4];
        #pragma unroll
        for (int j = 0; j < 8; j++)
            #pragma unroll
            for (int r = 0; r < 4; r++) c1[j][r] = 0.0f;

        #pragma unroll
        for (int c = 0; c < 4; c++) {
            uint a[4];
            a[0] = xsm[(16*wm + g)    *36 + 8*c + tg];
            a[1] = xsm[(16*wm + g + 8)*36 + 8*c + tg];
            a[2] = xsm[(16*wm + g)    *36 + 8*c + tg + 4];
            a[3] = xsm[(16*wm + g + 8)*36 + 8*c + tg + 4];
            #pragma unroll
            for (int j = 0; j < 8; j++) {
                uint b0 = w1t[(64*wn + 8*j + g)*36 + 8*c + tg];
                uint b1 = w1t[(64*wn + 8*j + g)*36 + 8*c + tg + 4];
                mma_f16(c1[j], a, b0, b1);
            }
        }
        #pragma unroll
        for (int j = 0; j < 8; j++) {
            int col2 = 32*wn + 4*j + tg;
            hsm[(16*wm + g)    *68 + col2] = f2h2(gelu_tanh(c1[j][0]), gelu_tanh(c1[j][1]));
            hsm[(16*wm + g + 8)*68 + col2] = f2h2(gelu_tanh(c1[j][2]), gelu_tanh(c1[j][3]));
        }

        #pragma unroll
        for (int q = 0; q < 8; q++) xg[q] = 0u;
        if (idgn != 0xFFFFFFFFu) {
            const uint4* src = (const uint4*)(g_xh + (size_t)(idgn & 0x7FFFFFFFu) * 512 + h * 32 + part * 8);
            uint4 v0 = src[0], v1 = src[1];
            xg[0]=v0.x; xg[1]=v0.y; xg[2]=v0.z; xg[3]=v0.w;
            xg[4]=v1.x; xg[5]=v1.y; xg[6]=v1.z; xg[7]=v1.w;
        }

        __syncthreads();

        float c2[4][4];
        #pragma unroll
        for (int j = 0; j < 4; j++)
            #pragma unroll
            for (int r = 0; r < 4; r++) c2[j][r] = 0.0f;

        #pragma unroll
        for (int c = 0; c < 8; c++) {
            uint a[4];
            a[0] = hsm[(16*wm + g)    *68 + 8*c + tg];
            a[1] = hsm[(16*wm + g + 8)*68 + 8*c + tg];
            a[2] = hsm[(16*wm + g)    *68 + 8*c + tg + 4];
            a[3] = hsm[(16*wm + g + 8)*68 + 8*c + tg + 4];
            #pragma unroll
            for (int j = 0; j < 4; j++) {
                uint b0 = w2t[(32*wn + 8*j + g)*68 + 8*c + tg];
                uint b1 = w2t[(32*wn + 8*j + g)*68 + 8*c + tg + 4];
                mma_f16(c2[j], a, b0, b1);
            }
        }

        if (idA != 0xFFFFFFFFu) {
            unsigned int slot = idA >> 31, tkk = idA & 0x7FFFFFFFu;
            uint* dst = g_parth + ((((size_t)slot*3 + proj)*HH + h)*NTOK + tkk)*32;
            #pragma unroll
            for (int j = 0; j < 4; j++)
                dst[16*wn + 4*j + tg] = f2h2(wtA*c2[j][0], wtA*c2[j][1]);
        }
        if (idB != 0xFFFFFFFFu) {
            unsigned int slot = idB >> 31, tkk = idB & 0x7FFFFFFFu;
            uint* dst = g_parth + ((((size_t)slot*3 + proj)*HH + h)*NTOK + tkk)*32;
            #pragma unroll
            for (int j = 0; j < 4; j++)
                dst[16*wn + 4*j + tg] = f2h2(wtB*c2[j][2], wtB*c2[j][3]);
        }

        if (!has_next) break;
    }
}

// ---------------------------------------------------------------------------
// Kernel 3: combine slots + RoPE; 4 rows per warp, coalesced uint V writes.
// Also re-zeroes g_cnt for the next graph replay (moe has already read it).
// ---------------------------------------------------------------------------
__global__ void __launch_bounds__(256) combine_rope_kernel(
    const int* __restrict__ pos_ids,
    const float* __restrict__ cosT, const float* __restrict__ sinT)
{
    if (blockIdx.x == 0) {
        for (int i = threadIdx.x; i < NUNIT; i += 256) g_cnt[i] = 0u;
    }

    const int warp = threadIdx.x >> 5;
    const int lane = threadIdx.x & 31;
    const int row0 = (blockIdx.x * 8 + warp) * 4;
    const size_t SLOT2 = (size_t)3 * HH * NTOK * 32;

    // proj/h constant across the 4 rows (row0 is 4-aligned, NTOK % 4 == 0)
    const int proj = row0 / (HH * NTOK);
    const int rest = row0 % (HH * NTOK);
    const int h   = rest / NTOK;
    const int tk0 = rest % NTOK;
    const int b   = tk0 >> 10, t0 = tk0 & 1023;
    const int bh  = b * HH + h;

    float va0[4], va1[4];
    #pragma unroll
    for (int r = 0; r < 4; r++) {
        const int tk = tk0 + r;
        const size_t pbase = (size_t)(row0 + r) * 32;
        float2 v1 = __half22float2(*(const __half2*)&g_parth[pbase + lane]);
        float2 v2 = __half22float2(*(const __half2*)&g_parth[pbase + SLOT2 + lane]);
        float a0 = v1.x + v2.x;
        float a1 = v1.y + v2.y;

        if (proj < 2) {
            int p = pos_ids[tk];
            float2 c = *(const float2*)&cosT[p*DD + 2*lane];
            float2 s = *(const float2*)&sinT[p*DD + 2*lane];
            float o0 = __shfl_xor_sync(0xffffffffu, a0, 16);
            float o1 = __shfl_xor_sync(0xffffffffu, a1, 16);
            float rot0 = (lane < 16) ? -o0 : o0;
            float rot1 = (lane < 16) ? -o1 : o1;
            a0 = a0 * c.x + rot0 * s.x;
            a1 = a1 * c.y + rot1 * s.y;
        }
        if (proj == 0) { a0 *= 0.125f; a1 *= 0.125f; }
        va0[r] = a0; va1[r] = a1;
    }

    if (proj == 2) {
        // pack (t even, t odd) pairs into uints: fully 4-byte coalesced
        #pragma unroll
        for (int p = 0; p < 2; p++) {
            size_t base = (size_t)bh * 512 * 64 + (size_t)((t0 >> 1) + p) * 64;
            g_vh[base + 2*lane]     = f2h2(va0[2*p], va0[2*p + 1]);
            g_vh[base + 2*lane + 1] = f2h2(va1[2*p], va1[2*p + 1]);
        }
    } else {
        uint* outg = (proj == 0) ? g_qh : g_kh;
        #pragma unroll
        for (int r = 0; r < 4; r++)
            outg[((size_t)bh * TT + t0 + r) * 32 + lane] = f2h2(va0[r], va1[r]);
    }
}

// ---------------------------------------------------------------------------
// Kernel 4: causal flash attention, fp16 mma (unchanged from R14).
// ---------------------------------------------------------------------------
#define ATTN_SMEM (18432 * 4)

__global__ void __launch_bounds__(256, 2) attn_kernel()
{
    extern __shared__ uint smu[];
    uint* psm = smu + 13824;

    const int wid = blockIdx.x;
    const int qtb = 7 - (wid >> 6);
    const int bh  = wid & 63;
    const int tid  = threadIdx.x;
    const int w    = tid >> 5;
    const int lane = tid & 31;
    const int g    = lane >> 2;
    const int tg   = lane & 3;

    const uint* qg = g_qh + (size_t)bh * TT * 32;
    const uint* kg = g_kh + (size_t)bh * TT * 32;
    const uint* vg = g_vh + (size_t)bh * 512 * 64;
    const int q0 = qtb * 128;
    const uint sbase = (uint)__cvta_generic_to_shared(smu);

    for (int i = tid; i < 768; i += 256) {
        int buf = i >> 8, rc = i & 255;
        int row = rc >> 3, c = rc & 7;
        smu[6912 + buf*2304 + row*72 + 64 + c] = (c == 0) ? 0x3C003C00u : 0u;
    }

    #pragma unroll
    for (int it = 0; it < 4; it++) {
        int idx = tid + it * 256;
        int row = idx >> 3, c4 = (idx & 7) * 4;
        *(uint4*)&psm[row*36 + c4] = *(const uint4*)&qg[(size_t)(q0 + row)*32 + c4];
    }
    __syncthreads();
    uint qa[4][4];
    {
        int rA = 16*w + g;
        #pragma unroll
        for (int c = 0; c < 4; c++) {
            qa[c][0] = psm[rA*36     + 8*c + tg];
            qa[c][1] = psm[(rA+8)*36 + 8*c + tg];
            qa[c][2] = psm[rA*36     + 8*c + tg + 4];
            qa[c][3] = psm[(rA+8)*36 + 8*c + tg + 4];
        }
    }

    float oa[9][4];
    #pragma unroll
    for (int j = 0; j < 9; j++)
        #pragma unroll
        for (int r = 0; r < 4; r++) oa[j][r] = 0.0f;
    float mA = -1e30f, mB = -1e30f;

    const int ktmax = 2*qtb + 1;

    #define ISSUE_TILE(kt_) do {                                              \
        int k0_ = (kt_) * 64;                                                 \
        int buf_ = (kt_) % 3;                                                 \
        uint kb_ = sbase + (buf_ * 2304) * 4;                                 \
        uint vb_ = sbase + ((6912 + buf_ * 2304)) * 4;                        \
        _Pragma("unroll")                                                     \
        for (int it_ = 0; it_ < 2; it_++) {                                   \
            int idx_ = tid + it_ * 256;                                       \
            int krow_ = idx_ >> 3, kc4_ = (idx_ & 7) * 4;                     \
            cpa16(kb_ + (krow_*36 + kc4_)*4,                                  \
                  &kg[(size_t)(k0_ + krow_)*32 + kc4_]);                      \
            int vrow_ = idx_ >> 4, vc4_ = (idx_ & 15) * 4;                    \
            cpa16(vb_ + (vrow_*72 + vc4_)*4,                                  \
                  &vg[(size_t)(k0_/2 + vrow_)*64 + vc4_]);                    \
        }                                                                     \
        asm volatile("cp.async.commit_group;");                               \
    } while (0)

    ISSUE_TILE(0);
    ISSUE_TILE(1);

    for (int kt = 0; kt <= ktmax; kt++) {
        if (kt < ktmax) {
            asm volatile("cp.async.wait_group 1;");
        } else {
            asm volatile("cp.async.wait_group 0;");
        }
        __syncthreads();
        if (kt + 2 <= ktmax) ISSUE_TILE(kt + 2);

        const uint* ksm = smu + (kt % 3) * 2304;
        const uint* vsm = smu + 6912 + (kt % 3) * 2304;
        const int k0 = kt * 64;

        float sc[8][4];
        #pragma unroll
        for (int j = 0; j < 8; j++)
            #pragma unroll
            for (int r = 0; r < 4; r++) sc[j][r] = 0.0f;

        #pragma unroll
        for (int c = 0; c < 4; c++) {
            #pragma unroll
            for (int j = 0; j < 8; j++) {
                uint b0 = ksm[(8*j + g)*36 + 8*c + tg];
                uint b1 = ksm[(8*j + g)*36 + 8*c + tg + 4];
                mma_f16(sc[j], qa[c], b0, b1);
            }
        }

        if (kt >= ktmax - 1) {
            const int rA = q0 + 16*w + g, rB = rA + 8;
            #pragma unroll
            for (int j = 0; j < 8; j++) {
                int col = k0 + 8*j + 2*tg;
                if (col     > rA) sc[j][0] = -1e30f;
                if (col + 1 > rA) sc[j][1] = -1e30f;
                if (col     > rB) sc[j][2] = -1e30f;
                if (col + 1 > rB) sc[j][3] = -1e30f;
            }
        }

        float mtA = -1e30f, mtB = -1e30f;
        #pragma unroll
        for (int j = 0; j < 8; j++) {
            mtA = fmaxf(mtA, fmaxf(sc[j][0], sc[j][1]));
            mtB = fmaxf(mtB, fmaxf(sc[j][2], sc[j][3]));
        }
        mtA = fmaxf(mtA, __shfl_xor_sync(0xffffffffu, mtA, 1));
        mtA = fmaxf(mtA, __shfl_xor_sync(0xffffffffu, mtA, 2));
        mtB = fmaxf(mtB, __shfl_xor_sync(0xffffffffu, mtB, 1));
        mtB = fmaxf(mtB, __shfl_xor_sync(0xffffffffu, mtB, 2));

        float mnA = fmaxf(mA, mtA), mnB = fmaxf(mB, mtB);
        float aA = __expf(mA - mnA), aB = __expf(mB - mnB);
        mA = mnA; mB = mnB;

        #pragma unroll
        for (int j = 0; j < 9; j++) {
            oa[j][0] *= aA; oa[j][1] *= aA;
            oa[j][2] *= aB; oa[j][3] *= aB;
        }

        float nAL = -mnA * L2E, nBL = -mnB * L2E;
        #pragma unroll
        for (int j = 0; j < 8; j++) {
            float t0 = fmaf(sc[j][0], L2E, nAL);
            float t1 = fmaf(sc[j][1], L2E, nAL);
            float t2 = fmaf(sc[j][2], L2E, nBL);
            float t3 = fmaf(sc[j][3], L2E, nBL);
            sc[j][0] = __uint_as_float(ex2h2(t0, t1));
            sc[j][1] = __uint_as_float(ex2h2(t2, t3));
        }

        #pragma unroll
        for (int c = 0; c < 4; c++) {
            uint a[4];
            a[0] = __float_as_uint(sc[2*c][0]);
            a[1] = __float_as_uint(sc[2*c][1]);
            a[2] = __float_as_uint(sc[2*c + 1][0]);
            a[3] = __float_as_uint(sc[2*c + 1][1]);
            #pragma unroll
            for (int jd = 0; jd < 9; jd++) {
                uint b0 = vsm[(8*c + tg)*72     + 8*jd + g];
                uint b1 = vsm[(8*c + tg + 4)*72 + 8*jd + g];
                mma_f16(oa[jd], a, b0, b1);
            }
        }
    }
    #undef ISSUE_TILE

    float lA = __shfl_sync(0xffffffffu, oa[8][0], lane & 28);
    float lB = __shfl_sync(0xffffffffu, oa[8][2], lane & 28);
    const int b = bh / HH, h = bh % HH;
    float invA = 1.0f / lA, invB = 1.0f / lB;
    const int rA = q0 + 16*w + g, rB = rA + 8;
    #pragma unroll
    for (int jd = 0; jd < 8; jd++) {
        g_aoh[((size_t)(b * TT) + rA) * 512 + h * 32 + 4*jd + tg] =
            f2h2(oa[jd][0] * invA, oa[jd][1] * invA);
        g_aoh[((size_t)(b * TT) + rB) * 512 + h * 32 + 4*jd + tg] =
            f2h2(oa[jd][2] * invB, oa[jd][3] * invB);
    }
}

// ---------------------------------------------------------------------------
// Kernel 5: y = ao @ ow^T, fp16 mma, BM=128, BN=128, BK=64.
// 3-stage cp.async pipeline -> ONE __syncthreads per k-iter.
// smem = 3 x 9216 uints = 110592 B (2 CTA/SM).
// ---------------------------------------------------------------------------
#define OUT_SMEM (3 * 9216 * 4)

__global__ void __launch_bounds__(256, 2) outproj_kernel(float* __restrict__ y)
{
    extern __shared__ uint osm[];

    const int tid  = threadIdx.x;
    const int w    = tid >> 5;
    const int lane = tid & 31;
    const int g    = lane >> 2;
    const int tg   = lane & 3;
    const int n0 = blockIdx.x * 128;
    const int m0 = blockIdx.y * 128;
    const uint sbase = (uint)__cvta_generic_to_shared(osm);

    float acc[16][4];
    #pragma unroll
    for (int j = 0; j < 16; j++)
        #pragma unroll
        for (int r = 0; r < 4; r++) acc[j][r] = 0.0f;

    #define OP_ISSUE(kc_) do {                                                \
        uint ab_ = sbase + ((kc_) % 3) * 9216 * 4;                            \
        uint bb_ = ab_ + 4608 * 4;                                            \
        _Pragma("unroll")                                                     \
        for (int it_ = 0; it_ < 4; it_++) {                                   \
            int idx_ = tid + it_ * 256;                                       \
            int row_ = idx_ >> 3, c4_ = (idx_ & 7) * 4;                       \
            cpa16(ab_ + (row_*36 + c4_)*4,                                    \
                  &g_aoh[(size_t)(m0 + row_) * 512 + (kc_)*32 + c4_]);        \
            cpa16(bb_ + (row_*36 + c4_)*4,                                    \
                  &g_owth[(size_t)(n0 + row_) * 512 + (kc_)*32 + c4_]);       \
        }                                                                     \
        asm volatile("cp.async.commit_group;");                               \
    } while (0)

    OP_ISSUE(0);
    OP_ISSUE(1);

    for (int kc = 0; kc < 16; kc++) {
        if (kc < 15) {
            asm volatile("cp.async.wait_group 1;");
        } else {
            asm volatile("cp.async.wait_group 0;");
        }
        __syncthreads();
        if (kc + 2 <= 15) OP_ISSUE(kc + 2);

        const uint* as = osm + (kc % 3) * 9216;
        const uint* bs = as + 4608;

        #pragma unroll
        for (int c = 0; c < 4; c++) {
            uint a[4];
            a[0] = as[(16*w + g)    *36 + 8*c + tg];
            a[1] = as[(16*w + g + 8)*36 + 8*c + tg];
            a[2] = as[(16*w + g)    *36 + 8*c + tg + 4];
            a[3] = as[(16*w + g + 8)*36 + 8*c + tg + 4];
            #pragma unroll
            for (int j = 0; j < 16; j++) {
                uint b0 = bs[(8*j + g)*36 + 8*c + tg];
                uint b1 = bs[(8*j + g)*36 + 8*c + tg + 4];
                mma_f16(acc[j], a, b0, b1);
            }
        }
    }
    #undef OP_ISSUE

    const int rA = m0 + 16*w + g, rB = rA + 8;
    #pragma unroll
    for (int j = 0; j < 16; j++) {
        *(float2*)&y[(size_t)rA * 1024 + n0 + 8*j + 2*tg] =
            make_float2(acc[j][0], acc[j][1]);
        *(float2*)&y[(size_t)rB * 1024 + n0 + 8*j + 2*tg] =
            make_float2(acc[j][2], acc[j][3]);
    }
}

// ---------------------------------------------------------------------------
extern "C" void kernel_launch(void* const* d_in, const int* in_sizes, int n_in,
                              void* d_out, int out_size)
{
    const float* x    = (const float*)d_in[0];
    const int*   pid  = (const int*)  d_in[1];
    const float* cosT = (const float*)d_in[2];
    const float* sinT = (const float*)d_in[3];
    const float* rq   = (const float*)d_in[4];
    const float* rk   = (const float*)d_in[5];
    const float* rv   = (const float*)d_in[6];
    const float* qw1  = (const float*)d_in[7];
    const float* qw2  = (const float*)d_in[8];
    const float* kw1  = (const float*)d_in[9];
    const float* kw2  = (const float*)d_in[10];
    const float* vw1  = (const float*)d_in[11];
    const float* vw2  = (const float*)d_in[12];
    const float* ow   = (const float*)d_in[13];
    float* y = (float*)d_out;

    cudaFuncSetAttribute(moe_gemm_kernel,
                         cudaFuncAttributeMaxDynamicSharedMemorySize, MOE_SMEM);
    cudaFuncSetAttribute(attn_kernel,
                         cudaFuncAttributeMaxDynamicSharedMemorySize, ATTN_SMEM);
    cudaFuncSetAttribute(outproj_kernel,
                         cudaFuncAttributeMaxDynamicSharedMemorySize, OUT_SMEM);

    route_kernel<<<NTOK / 4, 96>>>(x, rq, rk, rv, ow,
                                   qw1, qw2, kw1, kw2, vw1, vw2);
    moe_gemm_kernel<<<NUNIT * SPLITS, 512, MOE_SMEM>>>();
    combine_rope_kernel<<<(3 * HH * NTOK) / 32, 256>>>(pid, cosT, sinT);

    attn_kernel<<<512, 256, ATTN_SMEM>>>();

    dim3 g3(CC / 128, (BB * TT) / 128);
    outproj_kernel<<<g3, 256, OUT_SMEM>>>(y);
}

// round 16
// speedup vs baseline: 2.3345x; 1.0053x over previous
#include <cuda_runtime.h>
#include <cuda_fp16.h>
#include <math.h>

#define BB 4
#define TT 1024
#define CC 1024
#define HH 16
#define DD 64
#define EE 8
#define HID 128
#define NTOK (BB*TT)
#define NUNIT (3*HH*EE)
#define SPLITS 3

#define NEG_HUGE (-3.38953139e38f)
#define L2E 1.4426950408889634f

typedef unsigned int uint;

// ---------------- fp16 mma helpers (m16n8k16, fp32 accumulate) ----------------
__device__ __forceinline__ uint f2h2(float lo, float hi) {
    __half2 h = __floats2half2_rn(lo, hi);
    return *(uint*)&h;
}
__device__ __forceinline__ void mma_f16(float c[4], const uint a[4], uint b0, uint b1) {
    asm("mma.sync.aligned.m16n8k16.row.col.f32.f16.f16.f32 "
        "{%0,%1,%2,%3}, {%4,%5,%6,%7}, {%8,%9}, {%0,%1,%2,%3};"
        : "+f"(c[0]), "+f"(c[1]), "+f"(c[2]), "+f"(c[3])
        : "r"(a[0]), "r"(a[1]), "r"(a[2]), "r"(a[3]), "r"(b0), "r"(b1));
}
__device__ __forceinline__ void cpa16(uint dst, const void* src) {
    asm volatile("cp.async.cg.shared.global [%0], [%1], 16;" :: "r"(dst), "l"(src));
}
__device__ __forceinline__ uint ex2h2(float lo, float hi) {
    uint r;
    asm("cvt.rn.f16x2.f32 %0, %1, %2;" : "=r"(r) : "f"(hi), "f"(lo));
    asm("ex2.approx.f16x2 %0, %0;" : "+r"(r));
    return r;
}

// ---------------- device scratch ----------------
__device__ uint g_qh[BB*HH*TT*32];     // [bh][t][d/2] half2 along d, pre-scaled
__device__ uint g_kh[BB*HH*TT*32];
__device__ uint g_vh[BB*HH*512*64];    // [bh][t/2][d]  half2 along t
__device__ uint g_xh[NTOK*512];        // x as half2 along c
__device__ uint g_aoh[(size_t)BB*TT*512];      // [tok][c/2] half2 along c
__device__ uint g_owth[(size_t)CC*512];        // [n][k/2] half2 along k
__device__ uint g_w1th[24*4096];       // [proj*8+e][f][d/2] transposed half2
__device__ uint g_w2th[24*4096];       // [proj*8+e][d][j/2] transposed half2
__device__ unsigned int g_cnt[NUNIT];  // zero-init statically; re-zeroed by combine
__device__ unsigned int g_ent_id[NUNIT*NTOK];
__device__ float        g_ent_wt[NUNIT*NTOK];
__device__ uint g_parth[2ll*3*HH*NTOK*32];     // half2 partials

__device__ __forceinline__ float gelu_tanh(float t) {
    float t3 = t * t * t;
    return t / (1.0f + __expf(-1.5957691216057308f * (t + 0.044715f * t3)));
}

// ---------------------------------------------------------------------------
// Kernel 1: routing + ow/x fp16 pre-conversion + (blocks 0..23) weight prep.
// ---------------------------------------------------------------------------
__global__ void __launch_bounds__(96) route_kernel(
    const float* __restrict__ x,
    const float* __restrict__ rq, const float* __restrict__ rk,
    const float* __restrict__ rv, const float* __restrict__ ow,
    const float* __restrict__ qw1, const float* __restrict__ qw2,
    const float* __restrict__ kw1, const float* __restrict__ kw2,
    const float* __restrict__ vw1, const float* __restrict__ vw2)
{
    const int tk0  = blockIdx.x * 4;
    const int tid  = threadIdx.x;
    const int w    = tid >> 5;
    const int lane = tid & 31;
    const int e    = lane & 7;
    const int hq   = lane >> 3;

    __shared__ float xs[4*CC];
    __shared__ float rs[3][DD*EE];

    for (int i = tid; i < 512; i += 96) {
        int idx = blockIdx.x * 512 + i;
        float2 v = ((const float2*)ow)[idx];
        g_owth[idx] = f2h2(v.x, v.y);
    }

    for (int i = tid; i < CC; i += 96)
        ((float4*)xs)[i] = ((const float4*)(x + (size_t)tk0 * CC))[i];
    for (int i = tid; i < DD*EE; i += 96) {
        rs[0][i] = rq[i]; rs[1][i] = rk[i]; rs[2][i] = rv[i];
    }
    __syncthreads();

    for (int i = tid; i < 2048; i += 96)
        g_xh[(size_t)tk0 * 512 + i] = f2h2(xs[2*i], xs[2*i + 1]);

    const float* rw = rs[w];
    for (int tt = 0; tt < 4; tt++) {
        const int tk = tk0 + tt;
        const float* xrow = xs + tt * CC;
        for (int hb = 0; hb < 4; hb++) {
            int h = hb * 4 + hq;
            float acc = 0.0f;
            #pragma unroll 16
            for (int d = 0; d < DD; d++) acc += xrow[h*DD + d] * rw[d*EE + e];

            float m1 = NEG_HUGE, m2 = NEG_HUGE;
            int   i1 = 0, i2 = 0;
            #pragma unroll
            for (int ee = 0; ee < EE; ee++) {
                float v = __shfl_sync(0xffffffffu, acc, hq*8 + ee);
                if (v > m1)      { m2 = m1; i2 = i1; m1 = v; i1 = ee; }
                else if (v > m2) { m2 = v;  i2 = ee; }
            }
            if (e == 0) {
                float dex = expf(m2 - m1);
                float wt1 = 1.0f / (1.0f + dex);
                float wt2 = dex * wt1;
                int base = (w * HH + h) * EE;
                unsigned int p1 = atomicAdd(&g_cnt[base + i1], 1u);
                g_ent_id[(size_t)(base + i1) * NTOK + p1] = (unsigned int)tk;
                g_ent_wt[(size_t)(base + i1) * NTOK + p1] = wt1;
                unsigned int p2 = atomicAdd(&g_cnt[base + i2], 1u);
                g_ent_id[(size_t)(base + i2) * NTOK + p2] = (unsigned int)tk | 0x80000000u;
                g_ent_wt[(size_t)(base + i2) * NTOK + p2] = wt2;
            }
        }
    }

    if (blockIdx.x < 24) {
        const int u    = blockIdx.x;
        const int proj = u >> 3;
        const int ee   = u & 7;
        const float* w1 = ((proj == 0) ? qw1 : (proj == 1) ? kw1 : vw1) + (size_t)ee * DD * HID;
        const float* w2 = ((proj == 0) ? qw2 : (proj == 1) ? kw2 : vw2) + (size_t)ee * HID * DD;
        uint* d1 = g_w1th + u * 4096;
        uint* d2 = g_w2th + u * 4096;
        for (int i = tid; i < 4096; i += 96) {
            int f = i >> 5, dd2 = i & 31;
            d1[i] = f2h2(w1[(2*dd2)*HID + f], w1[(2*dd2 + 1)*HID + f]);
        }
        for (int i = tid; i < 4096; i += 96) {
            int d = i >> 6, j2 = i & 63;
            d2[i] = f2h2(w2[(2*j2)*DD + d], w2[(2*j2 + 1)*DD + d]);
        }
    }
}

// ---------------------------------------------------------------------------
// Kernel 2: expert-grouped MoE GEMM, fp16 mma; register-dieted for 2 CTA/SM.
// Stage 1 computed in two 4-tile halves (peak live accs 16 vs 32).
// ---------------------------------------------------------------------------
#define MOE_SMEM (22272 * 4)

__global__ void __launch_bounds__(512, 2) moe_gemm_kernel()
{
    const int gid  = blockIdx.x;
    const int unit = gid / SPLITS;
    const int s    = gid % SPLITS;
    const int proj = unit >> 7;
    const int h    = (unit >> 3) & 15;
    const int e    = unit & 7;
    const int u24  = proj * 8 + e;

    extern __shared__ uint smu[];
    uint* w1t = smu;                    // [128 f][36]
    uint* w2t = smu + 128*36;           // [64 d][68]
    uint* hsm = w2t + 64*68;            // [128 tok][68]
    uint* xsm = hsm + 128*68;           // [128 tok][36]

    const int tid  = threadIdx.x;
    const int w    = tid >> 5;
    const int lane = tid & 31;
    const int g    = lane >> 2;
    const int tg   = lane & 3;
    const int wm   = w & 7;
    const int wn   = w >> 3;
    const int myTok = tid >> 2;
    const int part  = tid & 3;

    const int nt = (int)g_cnt[unit];
    const size_t ent_base = (size_t)unit * NTOK;

    int base = s * 128;
    if (base >= nt) return;

    const uint sbase = (uint)__cvta_generic_to_shared(smu);
    {
        const uint* w1g = g_w1th + u24 * 4096;
        const uint* w2g = g_w2th + u24 * 4096;
        #pragma unroll
        for (int it = 0; it < 2; it++) {
            int idx = tid + it * 512;
            int row = idx >> 3, c4 = (idx & 7) * 4;
            cpa16(sbase + (row*36 + c4)*4, &w1g[row*32 + c4]);
            int row2 = idx >> 4, c42 = (idx & 15) * 4;
            cpa16(sbase + (128*36 + row2*68 + c42)*4, &w2g[row2*64 + c42]);
        }
        asm volatile("cp.async.commit_group;");
    }

    uint xg[8];
    {
        uint idg = 0xFFFFFFFFu;
        int idx = base + myTok;
        if (idx < nt) idg = g_ent_id[ent_base + idx];
        #pragma unroll
        for (int q = 0; q < 8; q++) xg[q] = 0u;
        if (idg != 0xFFFFFFFFu) {
            const uint4* src = (const uint4*)(g_xh + (size_t)(idg & 0x7FFFFFFFu) * 512 + h * 32 + part * 8);
            uint4 v0 = src[0], v1 = src[1];
            xg[0]=v0.x; xg[1]=v0.y; xg[2]=v0.z; xg[3]=v0.w;
            xg[4]=v1.x; xg[5]=v1.y; xg[6]=v1.z; xg[7]=v1.w;
        }
    }
    asm volatile("cp.async.wait_group 0;");

    const int tokA = 16*wm + g, tokB = tokA + 8;

    for (int b2 = base; ; b2 += SPLITS * 128) {
        {
            uint* dst = xsm + myTok * 36 + part * 8;
            #pragma unroll
            for (int q = 0; q < 8; q++) dst[q] = xg[q];
        }

        uint idA = 0xFFFFFFFFu, idB = 0xFFFFFFFFu;
        float wtA = 0.0f, wtB = 0.0f;
        if (b2 + tokA < nt) {
            idA = g_ent_id[ent_base + b2 + tokA];
            wtA = g_ent_wt[ent_base + b2 + tokA];
        }
        if (b2 + tokB < nt) {
            idB = g_ent_id[ent_base + b2 + tokB];
            wtB = g_ent_wt[ent_base + b2 + tokB];
        }

        const int bn = b2 + SPLITS * 128;
        const bool has_next = bn < nt;
        uint idgn = 0xFFFFFFFFu;
        if (has_next && bn + myTok < nt) idgn = g_ent_id[ent_base + bn + myTok];

        __syncthreads();

        // ---- stage 1 in two halves (register diet) ----
        #pragma unroll
        for (int jh = 0; jh < 2; jh++) {
            float c1[4][4];
            #pragma unroll
            for (int j = 0; j < 4; j++)
                #pragma unroll
                for (int r = 0; r < 4; r++) c1[j][r] = 0.0f;

            #pragma unroll
            for (int c = 0; c < 4; c++) {
                uint a[4];
                a[0] = xsm[(16*wm + g)    *36 + 8*c + tg];
                a[1] = xsm[(16*wm + g + 8)*36 + 8*c + tg];
                a[2] = xsm[(16*wm + g)    *36 + 8*c + tg + 4];
                a[3] = xsm[(16*wm + g + 8)*36 + 8*c + tg + 4];
                #pragma unroll
                for (int j = 0; j < 4; j++) {
                    int jj = 4*jh + j;
                    uint b0 = w1t[(64*wn + 8*jj + g)*36 + 8*c + tg];
                    uint b1 = w1t[(64*wn + 8*jj + g)*36 + 8*c + tg + 4];
                    mma_f16(c1[j], a, b0, b1);
                }
            }
            #pragma unroll
            for (int j = 0; j < 4; j++) {
                int col2 = 32*wn + 4*(4*jh + j) + tg;
                hsm[(16*wm + g)    *68 + col2] = f2h2(gelu_tanh(c1[j][0]), gelu_tanh(c1[j][1]));
                hsm[(16*wm + g + 8)*68 + col2] = f2h2(gelu_tanh(c1[j][2]), gelu_tanh(c1[j][3]));
            }
        }

        #pragma unroll
        for (int q = 0; q < 8; q++) xg[q] = 0u;
        if (idgn != 0xFFFFFFFFu) {
            const uint4* src = (const uint4*)(g_xh + (size_t)(idgn & 0x7FFFFFFFu) * 512 + h * 32 + part * 8);
            uint4 v0 = src[0], v1 = src[1];
            xg[0]=v0.x; xg[1]=v0.y; xg[2]=v0.z; xg[3]=v0.w;
            xg[4]=v1.x; xg[5]=v1.y; xg[6]=v1.z; xg[7]=v1.w;
        }

        __syncthreads();

        // ---- stage 2: O = H @ W2 ----
        float c2[4][4];
        #pragma unroll
        for (int j = 0; j < 4; j++)
            #pragma unroll
            for (int r = 0; r < 4; r++) c2[j][r] = 0.0f;

        #pragma unroll
        for (int c = 0; c < 8; c++) {
            uint a[4];
            a[0] = hsm[(16*wm + g)    *68 + 8*c + tg];
            a[1] = hsm[(16*wm + g + 8)*68 + 8*c + tg];
            a[2] = hsm[(16*wm + g)    *68 + 8*c + tg + 4];
            a[3] = hsm[(16*wm + g + 8)*68 + 8*c + tg + 4];
            #pragma unroll
            for (int j = 0; j < 4; j++) {
                uint b0 = w2t[(32*wn + 8*j + g)*68 + 8*c + tg];
                uint b1 = w2t[(32*wn + 8*j + g)*68 + 8*c + tg + 4];
                mma_f16(c2[j], a, b0, b1);
            }
        }

        if (idA != 0xFFFFFFFFu) {
            unsigned int slot = idA >> 31, tkk = idA & 0x7FFFFFFFu;
            uint* dst = g_parth + ((((size_t)slot*3 + proj)*HH + h)*NTOK + tkk)*32;
            #pragma unroll
            for (int j = 0; j < 4; j++)
                dst[16*wn + 4*j + tg] = f2h2(wtA*c2[j][0], wtA*c2[j][1]);
        }
        if (idB != 0xFFFFFFFFu) {
            unsigned int slot = idB >> 31, tkk = idB & 0x7FFFFFFFu;
            uint* dst = g_parth + ((((size_t)slot*3 + proj)*HH + h)*NTOK + tkk)*32;
            #pragma unroll
            for (int j = 0; j < 4; j++)
                dst[16*wn + 4*j + tg] = f2h2(wtB*c2[j][2], wtB*c2[j][3]);
        }

        if (!has_next) break;
    }
}

// ---------------------------------------------------------------------------
// Kernel 3: combine slots + RoPE; 4 rows per warp, all loads issued up-front.
// ---------------------------------------------------------------------------
__global__ void __launch_bounds__(256) combine_rope_kernel(
    const int* __restrict__ pos_ids,
    const float* __restrict__ cosT, const float* __restrict__ sinT)
{
    if (blockIdx.x == 0) {
        for (int i = threadIdx.x; i < NUNIT; i += 256) g_cnt[i] = 0u;
    }

    const int warp = threadIdx.x >> 5;
    const int lane = threadIdx.x & 31;
    const int row0 = (blockIdx.x * 8 + warp) * 4;
    const size_t SLOT2 = (size_t)3 * HH * NTOK * 32;

    const int proj = row0 / (HH * NTOK);
    const int rest = row0 % (HH * NTOK);
    const int h   = rest / NTOK;
    const int tk0 = rest % NTOK;
    const int b   = tk0 >> 10, t0 = tk0 & 1023;
    const int bh  = b * HH + h;

    // issue ALL partial loads first (MLP=8)
    uint u1[4], u2[4];
    #pragma unroll
    for (int r = 0; r < 4; r++) {
        const size_t pbase = (size_t)(row0 + r) * 32;
        u1[r] = g_parth[pbase + lane];
        u2[r] = g_parth[pbase + SLOT2 + lane];
    }
    int pp[4];
    if (proj < 2) {
        #pragma unroll
        for (int r = 0; r < 4; r++) pp[r] = pos_ids[tk0 + r];
    }

    float va0[4], va1[4];
    #pragma unroll
    for (int r = 0; r < 4; r++) {
        float2 v1 = __half22float2(*(__half2*)&u1[r]);
        float2 v2 = __half22float2(*(__half2*)&u2[r]);
        float a0 = v1.x + v2.x;
        float a1 = v1.y + v2.y;

        if (proj < 2) {
            float2 c = *(const float2*)&cosT[pp[r]*DD + 2*lane];
            float2 s = *(const float2*)&sinT[pp[r]*DD + 2*lane];
            float o0 = __shfl_xor_sync(0xffffffffu, a0, 16);
            float o1 = __shfl_xor_sync(0xffffffffu, a1, 16);
            float rot0 = (lane < 16) ? -o0 : o0;
            float rot1 = (lane < 16) ? -o1 : o1;
            a0 = a0 * c.x + rot0 * s.x;
            a1 = a1 * c.y + rot1 * s.y;
        }
        if (proj == 0) { a0 *= 0.125f; a1 *= 0.125f; }
        va0[r] = a0; va1[r] = a1;
    }

    if (proj == 2) {
        #pragma unroll
        for (int p = 0; p < 2; p++) {
            size_t base = (size_t)bh * 512 * 64 + (size_t)((t0 >> 1) + p) * 64;
            g_vh[base + 2*lane]     = f2h2(va0[2*p], va0[2*p + 1]);
            g_vh[base + 2*lane + 1] = f2h2(va1[2*p], va1[2*p + 1]);
        }
    } else {
        uint* outg = (proj == 0) ? g_qh : g_kh;
        #pragma unroll
        for (int r = 0; r < 4; r++)
            outg[((size_t)bh * TT + t0 + r) * 32 + lane] = f2h2(va0[r], va1[r]);
    }
}

// ---------------------------------------------------------------------------
// Kernel 4: causal flash attention, fp16 mma (unchanged from R15).
// ---------------------------------------------------------------------------
#define ATTN_SMEM (18432 * 4)

__global__ void __launch_bounds__(256, 2) attn_kernel()
{
    extern __shared__ uint smu[];
    uint* psm = smu + 13824;

    const int wid = blockIdx.x;
    const int qtb = 7 - (wid >> 6);
    const int bh  = wid & 63;
    const int tid  = threadIdx.x;
    const int w    = tid >> 5;
    const int lane = tid & 31;
    const int g    = lane >> 2;
    const int tg   = lane & 3;

    const uint* qg = g_qh + (size_t)bh * TT * 32;
    const uint* kg = g_kh + (size_t)bh * TT * 32;
    const uint* vg = g_vh + (size_t)bh * 512 * 64;
    const int q0 = qtb * 128;
    const uint sbase = (uint)__cvta_generic_to_shared(smu);

    for (int i = tid; i < 768; i += 256) {
        int buf = i >> 8, rc = i & 255;
        int row = rc >> 3, c = rc & 7;
        smu[6912 + buf*2304 + row*72 + 64 + c] = (c == 0) ? 0x3C003C00u : 0u;
    }

    #pragma unroll
    for (int it = 0; it < 4; it++) {
        int idx = tid + it * 256;
        int row = idx >> 3, c4 = (idx & 7) * 4;
        *(uint4*)&psm[row*36 + c4] = *(const uint4*)&qg[(size_t)(q0 + row)*32 + c4];
    }
    __syncthreads();
    uint qa[4][4];
    {
        int rA = 16*w + g;
        #pragma unroll
        for (int c = 0; c < 4; c++) {
            qa[c][0] = psm[rA*36     + 8*c + tg];
            qa[c][1] = psm[(rA+8)*36 + 8*c + tg];
            qa[c][2] = psm[rA*36     + 8*c + tg + 4];
            qa[c][3] = psm[(rA+8)*36 + 8*c + tg + 4];
        }
    }

    float oa[9][4];
    #pragma unroll
    for (int j = 0; j < 9; j++)
        #pragma unroll
        for (int r = 0; r < 4; r++) oa[j][r] = 0.0f;
    float mA = -1e30f, mB = -1e30f;

    const int ktmax = 2*qtb + 1;

    #define ISSUE_TILE(kt_) do {                                              \
        int k0_ = (kt_) * 64;                                                 \
        int buf_ = (kt_) % 3;                                                 \
        uint kb_ = sbase + (buf_ * 2304) * 4;                                 \
        uint vb_ = sbase + ((6912 + buf_ * 2304)) * 4;                        \
        _Pragma("unroll")                                                     \
        for (int it_ = 0; it_ < 2; it_++) {                                   \
            int idx_ = tid + it_ * 256;                                       \
            int krow_ = idx_ >> 3, kc4_ = (idx_ & 7) * 4;                     \
            cpa16(kb_ + (krow_*36 + kc4_)*4,                                  \
                  &kg[(size_t)(k0_ + krow_)*32 + kc4_]);                      \
            int vrow_ = idx_ >> 4, vc4_ = (idx_ & 15) * 4;                    \
            cpa16(vb_ + (vrow_*72 + vc4_)*4,                                  \
                  &vg[(size_t)(k0_/2 + vrow_)*64 + vc4_]);                    \
        }                                                                     \
        asm volatile("cp.async.commit_group;");                               \
    } while (0)

    ISSUE_TILE(0);
    ISSUE_TILE(1);

    for (int kt = 0; kt <= ktmax; kt++) {
        if (kt < ktmax) {
            asm volatile("cp.async.wait_group 1;");
        } else {
            asm volatile("cp.async.wait_group 0;");
        }
        __syncthreads();
        if (kt + 2 <= ktmax) ISSUE_TILE(kt + 2);

        const uint* ksm = smu + (kt % 3) * 2304;
        const uint* vsm = smu + 6912 + (kt % 3) * 2304;
        const int k0 = kt * 64;

        float sc[8][4];
        #pragma unroll
        for (int j = 0; j < 8; j++)
            #pragma unroll
            for (int r = 0; r < 4; r++) sc[j][r] = 0.0f;

        #pragma unroll
        for (int c = 0; c < 4; c++) {
            #pragma unroll
            for (int j = 0; j < 8; j++) {
                uint b0 = ksm[(8*j + g)*36 + 8*c + tg];
                uint b1 = ksm[(8*j + g)*36 + 8*c + tg + 4];
                mma_f16(sc[j], qa[c], b0, b1);
            }
        }

        if (kt >= ktmax - 1) {
            const int rA = q0 + 16*w + g, rB = rA + 8;
            #pragma unroll
            for (int j = 0; j < 8; j++) {
                int col = k0 + 8*j + 2*tg;
                if (col     > rA) sc[j][0] = -1e30f;
                if (col + 1 > rA) sc[j][1] = -1e30f;
                if (col     > rB) sc[j][2] = -1e30f;
                if (col + 1 > rB) sc[j][3] = -1e30f;
            }
        }

        float mtA = -1e30f, mtB = -1e30f;
        #pragma unroll
        for (int j = 0; j < 8; j++) {
            mtA = fmaxf(mtA, fmaxf(sc[j][0], sc[j][1]));
            mtB = fmaxf(mtB, fmaxf(sc[j][2], sc[j][3]));
        }
        mtA = fmaxf(mtA, __shfl_xor_sync(0xffffffffu, mtA, 1));
        mtA = fmaxf(mtA, __shfl_xor_sync(0xffffffffu, mtA, 2));
        mtB = fmaxf(mtB, __shfl_xor_sync(0xffffffffu, mtB, 1));
        mtB = fmaxf(mtB, __shfl_xor_sync(0xffffffffu, mtB, 2));

        float mnA = fmaxf(mA, mtA), mnB = fmaxf(mB, mtB);
        float aA = __expf(mA - mnA), aB = __expf(mB - mnB);
        mA = mnA; mB = mnB;

        #pragma unroll
        for (int j = 0; j < 9; j++) {
            oa[j][0] *= aA; oa[j][1] *= aA;
            oa[j][2] *= aB; oa[j][3] *= aB;
        }

        float nAL = -mnA * L2E, nBL = -mnB * L2E;
        #pragma unroll
        for (int j = 0; j < 8; j++) {
            float t0 = fmaf(sc[j][0], L2E, nAL);
            float t1 = fmaf(sc[j][1], L2E, nAL);
            float t2 = fmaf(sc[j][2], L2E, nBL);
            float t3 = fmaf(sc[j][3], L2E, nBL);
            sc[j][0] = __uint_as_float(ex2h2(t0, t1));
            sc[j][1] = __uint_as_float(ex2h2(t2, t3));
        }

        #pragma unroll
        for (int c = 0; c < 4; c++) {
            uint a[4];
            a[0] = __float_as_uint(sc[2*c][0]);
            a[1] = __float_as_uint(sc[2*c][1]);
            a[2] = __float_as_uint(sc[2*c + 1][0]);
            a[3] = __float_as_uint(sc[2*c + 1][1]);
            #pragma unroll
            for (int jd = 0; jd < 9; jd++) {
                uint b0 = vsm[(8*c + tg)*72     + 8*jd + g];
                uint b1 = vsm[(8*c + tg + 4)*72 + 8*jd + g];
                mma_f16(oa[jd], a, b0, b1);
            }
        }
    }
    #undef ISSUE_TILE

    float lA = __shfl_sync(0xffffffffu, oa[8][0], lane & 28);
    float lB = __shfl_sync(0xffffffffu, oa[8][2], lane & 28);
    const int b = bh / HH, h = bh % HH;
    float invA = 1.0f / lA, invB = 1.0f / lB;
    const int rA = q0 + 16*w + g, rB = rA + 8;
    #pragma unroll
    for (int jd = 0; jd < 8; jd++) {
        g_aoh[((size_t)(b * TT) + rA) * 512 + h * 32 + 4*jd + tg] =
            f2h2(oa[jd][0] * invA, oa[jd][1] * invA);
        g_aoh[((size_t)(b * TT) + rB) * 512 + h * 32 + 4*jd + tg] =
            f2h2(oa[jd][2] * invB, oa[jd][3] * invB);
    }
}

// ---------------------------------------------------------------------------
// Kernel 5: y = ao @ ow^T, fp16 mma, 3-stage pipeline (unchanged from R15).
// ---------------------------------------------------------------------------
#define OUT_SMEM (3 * 9216 * 4)

__global__ void __launch_bounds__(256, 2) outproj_kernel(float* __restrict__ y)
{
    extern __shared__ uint osm[];

    const int tid  = threadIdx.x;
    const int w    = tid >> 5;
    const int lane = tid & 31;
    const int g    = lane >> 2;
    const int tg   = lane & 3;
    const int n0 = blockIdx.x * 128;
    const int m0 = blockIdx.y * 128;
    const uint sbase = (uint)__cvta_generic_to_shared(osm);

    float acc[16][4];
    #pragma unroll
    for (int j = 0; j < 16; j++)
        #pragma unroll
        for (int r = 0; r < 4; r++) acc[j][r] = 0.0f;

    #define OP_ISSUE(kc_) do {                                                \
        uint ab_ = sbase + ((kc_) % 3) * 9216 * 4;                            \
        uint bb_ = ab_ + 4608 * 4;                                            \
        _Pragma("unroll")                                                     \
        for (int it_ = 0; it_ < 4; it_++) {                                   \
            int idx_ = tid + it_ * 256;                                       \
            int row_ = idx_ >> 3, c4_ = (idx_ & 7) * 4;                       \
            cpa16(ab_ + (row_*36 + c4_)*4,                                    \
                  &g_aoh[(size_t)(m0 + row_) * 512 + (kc_)*32 + c4_]);        \
            cpa16(bb_ + (row_*36 + c4_)*4,                                    \
                  &g_owth[(size_t)(n0 + row_) * 512 + (kc_)*32 + c4_]);       \
        }                                                                     \
        asm volatile("cp.async.commit_group;");                               \
    } while (0)

    OP_ISSUE(0);
    OP_ISSUE(1);

    for (int kc = 0; kc < 16; kc++) {
        if (kc < 15) {
            asm volatile("cp.async.wait_group 1;");
        } else {
            asm volatile("cp.async.wait_group 0;");
        }
        __syncthreads();
        if (kc + 2 <= 15) OP_ISSUE(kc + 2);

        const uint* as = osm + (kc % 3) * 9216;
        const uint* bs = as + 4608;

        #pragma unroll
        for (int c = 0; c < 4; c++) {
            uint a[4];
            a[0] = as[(16*w + g)    *36 + 8*c + tg];
            a[1] = as[(16*w + g + 8)*36 + 8*c + tg];
            a[2] = as[(16*w + g)    *36 + 8*c + tg + 4];
            a[3] = as[(16*w + g + 8)*36 + 8*c + tg + 4];
            #pragma unroll
            for (int j = 0; j < 16; j++) {
                uint b0 = bs[(8*j + g)*36 + 8*c + tg];
                uint b1 = bs[(8*j + g)*36 + 8*c + tg + 4];
                mma_f16(acc[j], a, b0, b1);
            }
        }
    }
    #undef OP_ISSUE

    const int rA = m0 + 16*w + g, rB = rA + 8;
    #pragma unroll
    for (int j = 0; j < 16; j++) {
        *(float2*)&y[(size_t)rA * 1024 + n0 + 8*j + 2*tg] =
            make_float2(acc[j][0], acc[j][1]);
        *(float2*)&y[(size_t)rB * 1024 + n0 + 8*j + 2*tg] =
            make_float2(acc[j][2], acc[j][3]);
    }
}

// ---------------------------------------------------------------------------
extern "C" void kernel_launch(void* const* d_in, const int* in_sizes, int n_in,
                              void* d_out, int out_size)
{
    const float* x    = (const float*)d_in[0];
    const int*   pid  = (const int*)  d_in[1];
    const float* cosT = (const float*)d_in[2];
    const float* sinT = (const float*)d_in[3];
    const float* rq   = (const float*)d_in[4];
    const float* rk   = (const float*)d_in[5];
    const float* rv   = (const float*)d_in[6];
    const float* qw1  = (const float*)d_in[7];
    const float* qw2  = (const float*)d_in[8];
    const float* kw1  = (const float*)d_in[9];
    const float* kw2  = (const float*)d_in[10];
    const float* vw1  = (const float*)d_in[11];
    const float* vw2  = (const float*)d_in[12];
    const float* ow   = (const float*)d_in[13];
    float* y = (float*)d_out;

    cudaFuncSetAttribute(moe_gemm_kernel,
                         cudaFuncAttributeMaxDynamicSharedMemorySize, MOE_SMEM);
    cudaFuncSetAttribute(attn_kernel,
                         cudaFuncAttributeMaxDynamicSharedMemorySize, ATTN_SMEM);
    cudaFuncSetAttribute(outproj_kernel,
                         cudaFuncAttributeMaxDynamicSharedMemorySize, OUT_SMEM);

    route_kernel<<<NTOK / 4, 96>>>(x, rq, rk, rv, ow,
                                   qw1, qw2, kw1, kw2, vw1, vw2);
    moe_gemm_kernel<<<NUNIT * SPLITS, 512, MOE_SMEM>>>();
    combine_rope_kernel<<<(3 * HH * NTOK) / 32, 256>>>(pid, cosT, sinT);

    attn_kernel<<<512, 256, ATTN_SMEM>>>();

    dim3 g3(CC / 128, (BB * TT) / 128);
    outproj_kernel<<<g3, 256, OUT_SMEM>>>(y);
}